// round 3
// baseline (speedup 1.0000x reference)
#include <cuda_runtime.h>

// ---- problem constants ----
#define BATCH 8
#define HH    112
#define WWID  112
#define DIM   192
#define HEADS 6
#define HD    32
#define WS    7
#define WA    49
#define EXPAND 3
#define NWH   16
#define NWW   16
#define BNW   2048
#define NROLL 132
#define NK    230
#define NKP   240              // NK padded to multiple of 8
#define QKVC  (3*DIM)
#define ATT_SCALE 0.17677669529663689f

// padded smem strides (floats) — chosen for conflict-free MMA fragment loads
#define SKQ 36                 // q/k rows: bank = (4*gid + tig) % 32
#define SVP 40                 // v rows:   bank = (8*j + d) % 32
#define SLP 260                // logits:   260 % 32 == 4

// ---- scratch (device globals: allocation-free) ----
__device__ float g_qkv [BATCH*HH*WWID*QKVC];
__device__ float g_qkvp[BATCH*NWH*NWW*QKVC];
__device__ float g_attnout[BNW*WA*DIM];
__device__ int   g_rtab[NROLL];

__device__ __forceinline__ float to_tf32(float x) {
    unsigned u;
    asm("cvt.rna.tf32.f32 %0, %1;" : "=r"(u) : "f"(x));
    return __uint_as_float(u);
}

// fast exp on fma/alu pipes (no MUFU). |rel err| ~2e-6 for x <= 0.
__device__ __forceinline__ float fast_exp(float v) {
    v = fmaxf(v, -80.f);
    float t  = v * 1.4426950408889634f;       // log2(e)
    float tb = t + 12582912.0f;               // 1.5*2^23 magic
    int   i  = __float_as_int(tb) - 0x4B400000;
    float f  = t - (tb - 12582912.0f);        // f in [-0.5, 0.5]
    float p  = 0.0013333558f;                 // Taylor of 2^f = e^(f ln2)
    p = fmaf(p, f, 0.0096181291f);
    p = fmaf(p, f, 0.0555041087f);
    p = fmaf(p, f, 0.2402265070f);
    p = fmaf(p, f, 0.6931471806f);
    p = fmaf(p, f, 1.0f);
    return __int_as_float(__float_as_int(p) + (i << 23));
}

#define MMA_TF32(c0,c1,c2,c3,a0,a1,a2,a3,b0,b1)                              \
    asm volatile("mma.sync.aligned.m16n8k8.row.col.f32.tf32.tf32.f32 "       \
        "{%0,%1,%2,%3},{%4,%5,%6,%7},{%8,%9},{%0,%1,%2,%3};"                 \
        : "+f"(c0), "+f"(c1), "+f"(c2), "+f"(c3)                             \
        : "r"(a0), "r"(a1), "r"(a2), "r"(a3), "r"(b0), "r"(b1))

// ============================================================
__global__ void init_rtab_kernel() {
    if (threadIdx.x == 0 && blockIdx.x == 0) {
        int n = 0;
        for (int s = 0; s < 4; s++)
            for (int r = 0; r < 7; r++)
                for (int c = 0; c < 7; c++) {
                    bool inval;
                    if      (s == 0) inval = (r < 4 && c < 4);
                    else if (s == 1) inval = (r < 4 && c >= 3);
                    else if (s == 2) inval = (r >= 3 && c < 4);
                    else             inval = (r >= 3 && c >= 3);
                    if (!inval) g_rtab[n++] = (s << 6) | (r << 3) | c;
                }
    }
}

// ============================================================
// GEMM: C[M,N] = A[M,K] @ Bw[N,K]^T + bias[N]   (fp32, 128x64 tile)
// ============================================================
__global__ __launch_bounds__(256)
void gemm_bias_kernel(const float* __restrict__ A, const float* __restrict__ Bw,
                      const float* __restrict__ bias, float* __restrict__ C,
                      int M, int N, int K) {
    __shared__ float As[16][132];
    __shared__ float Bs[16][68];
    const int tid = threadIdx.x;
    const int m0 = blockIdx.x << 7;
    const int n0 = blockIdx.y << 6;
    const int ar = tid >> 1, ac = (tid & 1) << 3;
    const int br = tid >> 2, bc = (tid & 3) << 2;
    const int ty = tid >> 4, tx = tid & 15;

    float acc[8][4] = {};

    for (int k0 = 0; k0 < K; k0 += 16) {
        float4 a0 = *(const float4*)(A + (long)(m0 + ar) * K + k0 + ac);
        float4 a1 = *(const float4*)(A + (long)(m0 + ar) * K + k0 + ac + 4);
        float4 bv = *(const float4*)(Bw + (long)(n0 + br) * K + k0 + bc);
        As[ac + 0][ar] = a0.x; As[ac + 1][ar] = a0.y;
        As[ac + 2][ar] = a0.z; As[ac + 3][ar] = a0.w;
        As[ac + 4][ar] = a1.x; As[ac + 5][ar] = a1.y;
        As[ac + 6][ar] = a1.z; As[ac + 7][ar] = a1.w;
        Bs[bc + 0][br] = bv.x; Bs[bc + 1][br] = bv.y;
        Bs[bc + 2][br] = bv.z; Bs[bc + 3][br] = bv.w;
        __syncthreads();
#pragma unroll
        for (int kk = 0; kk < 16; kk++) {
            float4 a4 = *(const float4*)&As[kk][ty << 3];
            float4 a5 = *(const float4*)&As[kk][(ty << 3) + 4];
            float4 b4 = *(const float4*)&Bs[kk][tx << 2];
            float a[8] = {a4.x, a4.y, a4.z, a4.w, a5.x, a5.y, a5.z, a5.w};
            float b[4] = {b4.x, b4.y, b4.z, b4.w};
#pragma unroll
            for (int i = 0; i < 8; i++)
#pragma unroll
                for (int j = 0; j < 4; j++)
                    acc[i][j] += a[i] * b[j];
        }
        __syncthreads();
    }

    float4 bb = *(const float4*)(bias + n0 + (tx << 2));
#pragma unroll
    for (int i = 0; i < 8; i++) {
        float4 o;
        o.x = acc[i][0] + bb.x; o.y = acc[i][1] + bb.y;
        o.z = acc[i][2] + bb.z; o.w = acc[i][3] + bb.w;
        *(float4*)(C + (long)(m0 + (ty << 3) + i) * N + n0 + (tx << 2)) = o;
    }
}

// ============================================================
// attention: block = (window, head), 256 threads, tf32 mma.sync
// smem: q 64x36, k 240x36, v 240x40, logits 64x260  = 148736 B
// ============================================================
__global__ __launch_bounds__(256)
void attn_kernel(const float* __restrict__ rpb_table,
                 const float* __restrict__ rpb_nb,
                 const float* __restrict__ rpb_win) {
    extern __shared__ float sm[];
    float* sq = sm;                     // 64 * SKQ
    float* sk = sq + 64 * SKQ;          // NKP * SKQ
    float* sv = sk + NKP * SKQ;         // NKP * SVP
    float* sl = sv + NKP * SVP;         // 64 * SLP

    const int tid = threadIdx.x;
    const int w = blockIdx.x;
    const int h = blockIdx.y;
    const int b  = w >> 8;
    const int wl = w & 255;
    const int wi = wl >> 4, wj = wl & 15;
    const int y0 = wi * WS, x0 = wj * WS;

    // ---- zero q/k/v staging (padding rows/cols must be 0) ----
    {
        float4* z = (float4*)sm;
        const int nz = (64 * SKQ + NKP * SKQ + NKP * SVP) / 4;  // 5136
        float4 zz = make_float4(0.f, 0.f, 0.f, 0.f);
        for (int i = tid; i < nz; i += 256) z[i] = zz;
    }
    __syncthreads();

    // ---- gather q (scaled, tf32) ----
    for (int i = tid; i < WA * HD; i += 256) {
        int qi = i >> 5, d = i & 31;
        int r = qi / 7, c = qi - r * 7;
        float qv = g_qkv[(((b * HH) + (y0 + r)) * WWID + (x0 + c)) * QKVC + h * HD + d];
        sq[qi * SKQ + d] = to_tf32(qv * ATT_SCALE);
    }

    // ---- gather k / v (own window, rolled ring, pooled unfold) ----
    for (int i = tid; i < NK * HD; i += 256) {
        int j = i >> 5, d = i & 31;
        float kv = 0.f, vv = 0.f;
        if (j < WA) {
            int r = j / 7, c = j - r * 7;
            int base = (((b * HH) + (y0 + r)) * WWID + (x0 + c)) * QKVC;
            kv = g_qkv[base + DIM     + h * HD + d];
            vv = g_qkv[base + 2 * DIM + h * HD + d];
        } else if (j < WA + NROLL) {
            int pk = g_rtab[j - WA];
            int s = pk >> 6, r = (pk >> 3) & 7, c = pk & 7;
            int dy = (s < 2) ? EXPAND : -EXPAND;
            int dx = ((s & 1) == 0) ? EXPAND : -EXPAND;
            int y = (y0 + r + dy + HH) % HH;
            int x = (x0 + c + dx + WWID) % WWID;
            int base = ((b * HH + y) * WWID + x) * QKVC;
            kv = g_qkv[base + DIM     + h * HD + d];
            vv = g_qkv[base + 2 * DIM + h * HD + d];
        } else {
            int jp = j - WA - NROLL;
            int r = jp / 7, c = jp - r * 7;
            int py = wi + r - EXPAND, px = wj + c - EXPAND;
            if (py >= 0 && py < NWH && px >= 0 && px < NWW) {
                int base = ((b * NWH + py) * NWW + px) * QKVC;
                kv = g_qkvp[base + DIM     + h * HD + d];
                vv = g_qkvp[base + 2 * DIM + h * HD + d];
            }
        }
        sk[j * SKQ + d] = to_tf32(kv);
        sv[j * SVP + d] = to_tf32(vv);
    }
    __syncthreads();

    // ---- QK^T via tf32 mma: warp -> 16 q-rows x 120 j-cols ----
    {
        const int wp = tid >> 5, lane = tid & 31;
        const int gid = lane >> 2, tig = lane & 3;
        const int q0 = 16 * (wp & 3);
        const int jb = 120 * (wp >> 2);
        const int ra = (q0 + gid) * SKQ, rb = (q0 + gid + 8) * SKQ;
        unsigned A[4][4];
#pragma unroll
        for (int ks = 0; ks < 4; ks++) {
            int c0 = 8 * ks + tig;
            A[ks][0] = __float_as_uint(sq[ra + c0]);
            A[ks][1] = __float_as_uint(sq[rb + c0]);
            A[ks][2] = __float_as_uint(sq[ra + c0 + 4]);
            A[ks][3] = __float_as_uint(sq[rb + c0 + 4]);
        }
        for (int t = 0; t < 15; t++) {
            int j0 = jb + 8 * t;
            float c0 = 0.f, c1 = 0.f, c2 = 0.f, c3 = 0.f;
            const int kb = (j0 + gid) * SKQ;
#pragma unroll
            for (int ks = 0; ks < 4; ks++) {
                unsigned b0 = __float_as_uint(sk[kb + 8 * ks + tig]);
                unsigned b1 = __float_as_uint(sk[kb + 8 * ks + tig + 4]);
                MMA_TF32(c0, c1, c2, c3, A[ks][0], A[ks][1], A[ks][2], A[ks][3], b0, b1);
            }
            *(float2*)&sl[(q0 + gid) * SLP + j0 + 2 * tig]     = make_float2(c0, c1);
            *(float2*)&sl[(q0 + gid + 8) * SLP + j0 + 2 * tig] = make_float2(c2, c3);
        }
    }
    __syncthreads();

    // ---- bias + softmax (warp per row), fast_exp on fma pipe ----
    {
        const int warp = tid >> 5, lane = tid & 31;
        for (int row = warp; row < WA; row += 8) {
            const int rq = row / 7, cq = row - rq * 7;
            float* slr = &sl[row * SLP];
            float m = -1e30f;
            for (int j = lane; j < NK; j += 32) {
                float bias;
                if (j < WA) {
                    int rk = j / 7, ck = j - rk * 7;
                    bias = rpb_table[((rq - rk + 6) * 13 + (cq - ck + 6)) * HEADS + h];
                } else if (j < WA + NROLL) {
                    bias = rpb_nb[(h * WA + row) * NROLL + (j - WA)];
                } else {
                    int jp = j - WA - NROLL;
                    int rk = jp / 7, ck = jp - rk * 7;
                    bias = rpb_win[h * 169 + (rq - rk + 6) * 13 + (cq - ck + 6)];
                    int py = wi + rk - EXPAND, px = wj + ck - EXPAND;
                    if (py < 0 || py >= NWH || px < 0 || px >= NWW) bias -= 100.f;
                }
                float val = slr[j] + bias;
                slr[j] = val;
                m = fmaxf(m, val);
            }
#pragma unroll
            for (int o = 16; o > 0; o >>= 1) m = fmaxf(m, __shfl_xor_sync(0xffffffffu, m, o));
            float ssum = 0.f;
            for (int j = lane; j < NK; j += 32) {
                float e = fast_exp(slr[j] - m);
                slr[j] = e;
                ssum += e;
            }
#pragma unroll
            for (int o = 16; o > 0; o >>= 1) ssum += __shfl_xor_sync(0xffffffffu, ssum, o);
            float inv = 1.f / ssum;
            for (int j = lane; j < NK; j += 32) slr[j] = to_tf32(slr[j] * inv);
        }
    }
    __syncthreads();

    // ---- out = P @ V via tf32 mma: warp -> 16 q-rows x 16 d-cols ----
    {
        const int wp = tid >> 5, lane = tid & 31;
        const int gid = lane >> 2, tig = lane & 3;
        const int q0 = 16 * (wp & 3);
        const int d0 = 16 * (wp >> 2);
        const int ra = (q0 + gid) * SLP, rb = (q0 + gid + 8) * SLP;
        float acc[8] = {};
        for (int s = 0; s < 30; s++) {
            int j0 = 8 * s;
            unsigned a0 = __float_as_uint(sl[ra + j0 + tig]);
            unsigned a1 = __float_as_uint(sl[rb + j0 + tig]);
            unsigned a2 = __float_as_uint(sl[ra + j0 + tig + 4]);
            unsigned a3 = __float_as_uint(sl[rb + j0 + tig + 4]);
            int vb0 = (j0 + tig) * SVP + d0 + gid;
            int vb1 = (j0 + tig + 4) * SVP + d0 + gid;
            unsigned b00 = __float_as_uint(sv[vb0]);
            unsigned b01 = __float_as_uint(sv[vb1]);
            unsigned b10 = __float_as_uint(sv[vb0 + 8]);
            unsigned b11 = __float_as_uint(sv[vb1 + 8]);
            MMA_TF32(acc[0], acc[1], acc[2], acc[3], a0, a1, a2, a3, b00, b01);
            MMA_TF32(acc[4], acc[5], acc[6], acc[7], a0, a1, a2, a3, b10, b11);
        }
        const int q1 = q0 + gid, q2 = q0 + gid + 8;
        const int dcol = h * HD + d0 + 2 * tig;
        if (q1 < WA) {
            float* o = &g_attnout[(long)(w * WA + q1) * DIM + dcol];
            *(float2*)o       = make_float2(acc[0], acc[1]);
            *(float2*)(o + 8) = make_float2(acc[4], acc[5]);
        }
        if (q2 < WA) {
            float* o = &g_attnout[(long)(w * WA + q2) * DIM + dcol];
            *(float2*)o       = make_float2(acc[2], acc[3]);
            *(float2*)(o + 8) = make_float2(acc[6], acc[7]);
        }
    }
}

// ============================================================
// launch
// ============================================================
extern "C" void kernel_launch(void* const* d_in, const int* in_sizes, int n_in,
                              void* d_out, int out_size) {
    const float* x         = (const float*)d_in[0];
    const float* x_pooled  = (const float*)d_in[1];
    const float* qkv_w     = (const float*)d_in[2];
    const float* qkv_b     = (const float*)d_in[3];
    const float* proj_w    = (const float*)d_in[4];
    const float* proj_b    = (const float*)d_in[5];
    const float* rpb_table = (const float*)d_in[6];
    const float* rpb_nb    = (const float*)d_in[7];
    const float* rpb_win   = (const float*)d_in[8];
    float* out = (float*)d_out;

    float *p_qkv = nullptr, *p_qkvp = nullptr, *p_ao = nullptr;
    cudaGetSymbolAddress((void**)&p_qkv,  g_qkv);
    cudaGetSymbolAddress((void**)&p_qkvp, g_qkvp);
    cudaGetSymbolAddress((void**)&p_ao,   g_attnout);

    const int attn_smem = (64 * SKQ + NKP * SKQ + NKP * SVP + 64 * SLP) * (int)sizeof(float); // 148736
    cudaFuncSetAttribute(attn_kernel, cudaFuncAttributeMaxDynamicSharedMemorySize, attn_smem);

    init_rtab_kernel<<<1, 32>>>();

    gemm_bias_kernel<<<dim3(100352 / 128, QKVC / 64), 256>>>(
        x, qkv_w, qkv_b, p_qkv, BATCH * HH * WWID, QKVC, DIM);

    gemm_bias_kernel<<<dim3(2048 / 128, QKVC / 64), 256>>>(
        x_pooled, qkv_w, qkv_b, p_qkvp, BATCH * NWH * NWW, QKVC, DIM);

    attn_kernel<<<dim3(BNW, HEADS), 256, attn_smem>>>(rpb_table, rpb_nb, rpb_win);

    gemm_bias_kernel<<<dim3(100352 / 128, DIM / 64), 256>>>(
        p_ao, proj_w, proj_b, out, BNW * WA, DIM, DIM);
}

// round 4
// speedup vs baseline: 1.7206x; 1.7206x over previous
#include <cuda_runtime.h>

// ---- problem constants ----
#define BATCH 8
#define HH    112
#define WWID  112
#define DIM   192
#define HEADS 6
#define HD    32
#define SKP   36
#define WS    7
#define WA    49
#define EXPAND 3
#define NWH   16
#define NWW   16
#define BNW   2048
#define NROLL 132
#define NK    230
#define QKVC  (3*DIM)
#define ATT_SCALE 0.17677669529663689f

// ---- scratch ----
__device__ float g_qkv [BATCH*HH*WWID*QKVC];
__device__ float g_qkvp[BATCH*NWH*NWW*QKVC];
__device__ float g_attnout[BNW*WA*DIM];
__device__ int   g_rtab[NROLL];

__device__ __forceinline__ float to_tf32(float x) {
    unsigned u;
    asm("cvt.rna.tf32.f32 %0, %1;" : "=r"(u) : "f"(x));
    return __uint_as_float(u);
}

// fast exp on fma/alu pipes (no MUFU). valid for x <= 0.
__device__ __forceinline__ float fast_exp(float v) {
    v = fmaxf(v, -80.f);
    float t  = v * 1.4426950408889634f;
    float tb = t + 12582912.0f;
    int   i  = __float_as_int(tb) - 0x4B400000;
    float f  = t - (tb - 12582912.0f);
    float p  = 0.0013333558f;
    p = fmaf(p, f, 0.0096181291f);
    p = fmaf(p, f, 0.0555041087f);
    p = fmaf(p, f, 0.2402265070f);
    p = fmaf(p, f, 0.6931471806f);
    p = fmaf(p, f, 1.0f);
    return __int_as_float(__float_as_int(p) + (i << 23));
}

#define MMA_TF32(c0,c1,c2,c3,a0,a1,a2,a3,b0,b1)                              \
    asm volatile("mma.sync.aligned.m16n8k8.row.col.f32.tf32.tf32.f32 "       \
        "{%0,%1,%2,%3},{%4,%5,%6,%7},{%8,%9},{%0,%1,%2,%3};"                 \
        : "+f"(c0), "+f"(c1), "+f"(c2), "+f"(c3)                             \
        : "r"(a0), "r"(a1), "r"(a2), "r"(a3), "r"(b0), "r"(b1))

// ============================================================
__global__ void init_rtab_kernel() {
    if (threadIdx.x == 0 && blockIdx.x == 0) {
        int n = 0;
        for (int s = 0; s < 4; s++)
            for (int r = 0; r < 7; r++)
                for (int c = 0; c < 7; c++) {
                    bool inval;
                    if      (s == 0) inval = (r < 4 && c < 4);
                    else if (s == 1) inval = (r < 4 && c >= 3);
                    else if (s == 2) inval = (r >= 3 && c < 4);
                    else             inval = (r >= 3 && c >= 3);
                    if (!inval) g_rtab[n++] = (s << 6) | (r << 3) | c;
                }
    }
}

// ============================================================
// tf32 tensor-core GEMM: C[M,N] = A[M,K] @ Bw[N,K]^T + bias[N]
// block tile 128x64, 256 thr (8 warps, 4x2), warp tile 32x32.
// M%128==0, N%64==0, K%16==0 at all call sites.
// Fragment maps identical to the (validated) round-3 attention MMA.
// ============================================================
__global__ __launch_bounds__(256)
void gemm_tf32_kernel(const float* __restrict__ A, const float* __restrict__ Bw,
                      const float* __restrict__ bias, float* __restrict__ C,
                      int M, int N, int K) {
    __shared__ float As[16][136];   // stride 136: frag-load bank = 8*tig+gid (perm)
    __shared__ float Bs[16][72];    // stride 72:  same property
    const int tid = threadIdx.x;
    const int m0 = blockIdx.x << 7;
    const int n0 = blockIdx.y << 6;
    const int ar = tid >> 1, ac = (tid & 1) << 3;   // A stage: row, k-col 0/8
    const int br = tid >> 2, bc = (tid & 3) << 2;   // B stage: row, k-col 0..12
    const int wp = tid >> 5, lane = tid & 31;
    const int gid = lane >> 2, tig = lane & 3;
    const int wm = (wp >> 1) << 5;                  // 0,32,64,96
    const int wn = (wp & 1) << 5;                   // 0,32

    float acc[2][4][4] = {};

    for (int k0 = 0; k0 < K; k0 += 16) {
        float4 a0 = *(const float4*)(A + (long)(m0 + ar) * K + k0 + ac);
        float4 a1 = *(const float4*)(A + (long)(m0 + ar) * K + k0 + ac + 4);
        float4 bv = *(const float4*)(Bw + (long)(n0 + br) * K + k0 + bc);
        As[ac + 0][ar] = to_tf32(a0.x); As[ac + 1][ar] = to_tf32(a0.y);
        As[ac + 2][ar] = to_tf32(a0.z); As[ac + 3][ar] = to_tf32(a0.w);
        As[ac + 4][ar] = to_tf32(a1.x); As[ac + 5][ar] = to_tf32(a1.y);
        As[ac + 6][ar] = to_tf32(a1.z); As[ac + 7][ar] = to_tf32(a1.w);
        Bs[bc + 0][br] = to_tf32(bv.x); Bs[bc + 1][br] = to_tf32(bv.y);
        Bs[bc + 2][br] = to_tf32(bv.z); Bs[bc + 3][br] = to_tf32(bv.w);
        __syncthreads();
#pragma unroll
        for (int ks = 0; ks < 2; ks++) {
            const int kk = ks << 3;
            unsigned afr[2][4], bfr[4][2];
#pragma unroll
            for (int mt = 0; mt < 2; mt++) {
                const int mb = wm + (mt << 4);
                afr[mt][0] = __float_as_uint(As[kk + tig][mb + gid]);
                afr[mt][1] = __float_as_uint(As[kk + tig][mb + gid + 8]);
                afr[mt][2] = __float_as_uint(As[kk + tig + 4][mb + gid]);
                afr[mt][3] = __float_as_uint(As[kk + tig + 4][mb + gid + 8]);
            }
#pragma unroll
            for (int nt = 0; nt < 4; nt++) {
                const int nb = wn + (nt << 3);
                bfr[nt][0] = __float_as_uint(Bs[kk + tig][nb + gid]);
                bfr[nt][1] = __float_as_uint(Bs[kk + tig + 4][nb + gid]);
            }
#pragma unroll
            for (int mt = 0; mt < 2; mt++)
#pragma unroll
                for (int nt = 0; nt < 4; nt++)
                    MMA_TF32(acc[mt][nt][0], acc[mt][nt][1], acc[mt][nt][2], acc[mt][nt][3],
                             afr[mt][0], afr[mt][1], afr[mt][2], afr[mt][3],
                             bfr[nt][0], bfr[nt][1]);
        }
        __syncthreads();
    }

#pragma unroll
    for (int mt = 0; mt < 2; mt++) {
        const int r0 = m0 + wm + (mt << 4) + gid;
#pragma unroll
        for (int nt = 0; nt < 4; nt++) {
            const int ccol = n0 + wn + (nt << 3) + (tig << 1);
            const float b0 = bias[ccol], b1 = bias[ccol + 1];
            *(float2*)(C + (long)r0 * N + ccol) =
                make_float2(acc[mt][nt][0] + b0, acc[mt][nt][1] + b1);
            *(float2*)(C + (long)(r0 + 8) * N + ccol) =
                make_float2(acc[mt][nt][2] + b0, acc[mt][nt][3] + b1);
        }
    }
}

// ============================================================
// attention: one block = one (window, head). 256 threads.
// (round-2 structure, 2 CTA/SM; __expf replaced by fast_exp)
// smem: k(230x36) v(230x36) logits(49x230) = 111320 B
// ============================================================
__global__ __launch_bounds__(256)
void attn_kernel(const float* __restrict__ rpb_table,
                 const float* __restrict__ rpb_nb,
                 const float* __restrict__ rpb_win) {
    extern __shared__ float sm[];
    float* sk = sm;
    float* sv = sk + NK * SKP;
    float* sl = sv + NK * SKP;

    const int tid = threadIdx.x;
    const int w = blockIdx.x;
    const int h = blockIdx.y;
    const int b  = w >> 8;
    const int wl = w & 255;
    const int wi = wl >> 4, wj = wl & 15;
    const int y0 = wi * WS, x0 = wj * WS;

    // ---- gather k / v into padded smem ----
    for (int i = tid; i < NK * HD; i += 256) {
        int j = i >> 5, d = i & 31;
        float kv = 0.f, vv = 0.f;
        if (j < WA) {
            int r = j / 7, c = j - r * 7;
            int base = (((b * HH) + (y0 + r)) * WWID + (x0 + c)) * QKVC;
            kv = g_qkv[base + DIM     + h * HD + d];
            vv = g_qkv[base + 2 * DIM + h * HD + d];
        } else if (j < WA + NROLL) {
            int pk = g_rtab[j - WA];
            int s = pk >> 6, r = (pk >> 3) & 7, c = pk & 7;
            int dy = (s < 2) ? EXPAND : -EXPAND;
            int dx = ((s & 1) == 0) ? EXPAND : -EXPAND;
            int y = (y0 + r + dy + HH) % HH;
            int x = (x0 + c + dx + WWID) % WWID;
            int base = ((b * HH + y) * WWID + x) * QKVC;
            kv = g_qkv[base + DIM     + h * HD + d];
            vv = g_qkv[base + 2 * DIM + h * HD + d];
        } else {
            int jp = j - WA - NROLL;
            int r = jp / 7, c = jp - r * 7;
            int py = wi + r - EXPAND, px = wj + c - EXPAND;
            if (py >= 0 && py < NWH && px >= 0 && px < NWW) {
                int base = ((b * NWH + py) * NWW + px) * QKVC;
                kv = g_qkvp[base + DIM     + h * HD + d];
                vv = g_qkvp[base + 2 * DIM + h * HD + d];
            }
        }
        sk[j * SKP + d] = kv;
        sv[j * SKP + d] = vv;
    }
    __syncthreads();

    // ---- logits + bias: 2 q-rows per thread, q in registers ----
    {
        const int p  = tid >> 3;
        const int jg = tid & 7;
        if (p < 25) {
            const int r0 = 2 * p;
            const int r1 = r0 + 1;
            const bool has2 = (r1 < WA);
            float4 qa[8], qb[8];
            {
                int rr = r0 / 7, cc = r0 - rr * 7;
                const float* qp = &g_qkv[(((b * HH) + (y0 + rr)) * WWID + (x0 + cc)) * QKVC + h * HD];
#pragma unroll
                for (int d = 0; d < 8; d++) qa[d] = *(const float4*)(qp + 4 * d);
                int r2 = has2 ? r1 : r0;
                rr = r2 / 7; cc = r2 - rr * 7;
                qp = &g_qkv[(((b * HH) + (y0 + rr)) * WWID + (x0 + cc)) * QKVC + h * HD];
#pragma unroll
                for (int d = 0; d < 8; d++) qb[d] = *(const float4*)(qp + 4 * d);
            }
            const int rq0 = r0 / 7, cq0 = r0 - rq0 * 7;
            const int rq1 = r1 / 7, cq1 = r1 - rq1 * 7;

            for (int j = jg; j < NK; j += 8) {
                float acc0 = 0.f, acc1 = 0.f;
#pragma unroll
                for (int d = 0; d < 8; d++) {
                    float4 kt = *(const float4*)&sk[j * SKP + 4 * d];
                    acc0 += qa[d].x * kt.x + qa[d].y * kt.y + qa[d].z * kt.z + qa[d].w * kt.w;
                    acc1 += qb[d].x * kt.x + qb[d].y * kt.y + qb[d].z * kt.z + qb[d].w * kt.w;
                }
                float b0, b1;
                if (j < WA) {
                    int rk = j / 7, ck = j - rk * 7;
                    b0 = rpb_table[((rq0 - rk + 6) * 13 + (cq0 - ck + 6)) * HEADS + h];
                    b1 = rpb_table[((rq1 - rk + 6) * 13 + (cq1 - ck + 6)) * HEADS + h];
                } else if (j < WA + NROLL) {
                    b0 = rpb_nb[(h * WA + r0) * NROLL + (j - WA)];
                    b1 = has2 ? rpb_nb[(h * WA + r1) * NROLL + (j - WA)] : 0.f;
                } else {
                    int jp = j - WA - NROLL;
                    int rk = jp / 7, ck = jp - rk * 7;
                    b0 = rpb_win[h * 169 + (rq0 - rk + 6) * 13 + (cq0 - ck + 6)];
                    b1 = has2 ? rpb_win[h * 169 + (rq1 - rk + 6) * 13 + (cq1 - ck + 6)] : 0.f;
                    int py = wi + rk - EXPAND, px = wj + ck - EXPAND;
                    if (py < 0 || py >= NWH || px < 0 || px >= NWW) { b0 -= 100.f; b1 -= 100.f; }
                }
                sl[r0 * NK + j] = acc0 * ATT_SCALE + b0;
                if (has2) sl[r1 * NK + j] = acc1 * ATT_SCALE + b1;
            }
        }
    }
    __syncthreads();

    // ---- softmax (warp per row), fast_exp ----
    {
        const int warp = tid >> 5, lane = tid & 31;
        for (int row = warp; row < WA; row += 8) {
            float m = -1e30f;
            for (int j = lane; j < NK; j += 32) m = fmaxf(m, sl[row * NK + j]);
#pragma unroll
            for (int o = 16; o > 0; o >>= 1) m = fmaxf(m, __shfl_xor_sync(0xffffffffu, m, o));
            float ssum = 0.f;
            for (int j = lane; j < NK; j += 32) {
                float e = fast_exp(sl[row * NK + j] - m);
                sl[row * NK + j] = e;
                ssum += e;
            }
#pragma unroll
            for (int o = 16; o > 0; o >>= 1) ssum += __shfl_xor_sync(0xffffffffu, ssum, o);
            float inv = 1.f / ssum;
            for (int j = lane; j < NK; j += 32) sl[row * NK + j] *= inv;
        }
    }
    __syncthreads();

    // ---- out = attn @ v : 4 q-rows x 4 d per thread ----
    {
        const int g  = tid >> 3;
        const int dg = tid & 7;
        if (g < 13) {
            const int r0 = 4 * g;
            const int rmax = (WA - r0 < 4) ? (WA - r0) : 4;
            const int d0 = dg << 2;
            float acc[4][4] = {};
            for (int j = 0; j < NK; j++) {
                float4 v4 = *(const float4*)&sv[j * SKP + d0];
                float pr[4];
#pragma unroll
                for (int i = 0; i < 4; i++)
                    pr[i] = (i < rmax) ? sl[(r0 + i) * NK + j] : 0.f;
#pragma unroll
                for (int i = 0; i < 4; i++) {
                    acc[i][0] += pr[i] * v4.x; acc[i][1] += pr[i] * v4.y;
                    acc[i][2] += pr[i] * v4.z; acc[i][3] += pr[i] * v4.w;
                }
            }
#pragma unroll
            for (int i = 0; i < 4; i++) {
                if (i < rmax) {
                    float* o = &g_attnout[(long)(w * WA + r0 + i) * DIM + h * HD + d0];
                    *(float4*)o = make_float4(acc[i][0], acc[i][1], acc[i][2], acc[i][3]);
                }
            }
        }
    }
}

// ============================================================
// launch
// ============================================================
extern "C" void kernel_launch(void* const* d_in, const int* in_sizes, int n_in,
                              void* d_out, int out_size) {
    const float* x         = (const float*)d_in[0];
    const float* x_pooled  = (const float*)d_in[1];
    const float* qkv_w     = (const float*)d_in[2];
    const float* qkv_b     = (const float*)d_in[3];
    const float* proj_w    = (const float*)d_in[4];
    const float* proj_b    = (const float*)d_in[5];
    const float* rpb_table = (const float*)d_in[6];
    const float* rpb_nb    = (const float*)d_in[7];
    const float* rpb_win   = (const float*)d_in[8];
    float* out = (float*)d_out;

    float *p_qkv = nullptr, *p_qkvp = nullptr, *p_ao = nullptr;
    cudaGetSymbolAddress((void**)&p_qkv,  g_qkv);
    cudaGetSymbolAddress((void**)&p_qkvp, g_qkvp);
    cudaGetSymbolAddress((void**)&p_ao,   g_attnout);

    const int attn_smem = (2 * NK * SKP + WA * NK) * (int)sizeof(float); // 111320
    cudaFuncSetAttribute(attn_kernel, cudaFuncAttributeMaxDynamicSharedMemorySize, attn_smem);

    init_rtab_kernel<<<1, 32>>>();

    // qkv fine: (100352,576)
    gemm_tf32_kernel<<<dim3(100352 / 128, QKVC / 64), 256>>>(
        x, qkv_w, qkv_b, p_qkv, BATCH * HH * WWID, QKVC, DIM);

    // qkv pooled: (2048,576)
    gemm_tf32_kernel<<<dim3(2048 / 128, QKVC / 64), 256>>>(
        x_pooled, qkv_w, qkv_b, p_qkvp, BATCH * NWH * NWW, QKVC, DIM);

    // attention
    attn_kernel<<<dim3(BNW, HEADS), 256, attn_smem>>>(rpb_table, rpb_nb, rpb_win);

    // projection: (100352,192)
    gemm_tf32_kernel<<<dim3(100352 / 128, DIM / 64), 256>>>(
        p_ao, proj_w, proj_b, out, BNW * WA, DIM, DIM);
}

// round 6
// speedup vs baseline: 2.3533x; 1.3677x over previous
#include <cuda_runtime.h>
#include <cuda_fp16.h>

// ---- problem constants ----
#define BATCH 8
#define HH    112
#define WWID  112
#define DIM   192
#define HEADS 6
#define HD    32
#define WS    7
#define WA    49
#define EXPAND 3
#define NWH   16
#define NWW   16
#define BNW   2048
#define NROLL 132
#define NK    230
#define NKP   240
#define QKVC  (3*DIM)
#define ATT_SCALE 0.17677669529663689f

// smem strides in halves (conflict-free for frag loads AND scatter stores)
#define SKH 40
#define SVH 250
#define SQ_OFF  0
#define SK_OFF  (64*SKH)                 // 2560
#define SVT_OFF (SK_OFF + NKP*SKH)       // 12160
#define SMEM_HALVES (SVT_OFF + HD*SVH)   // 20160 -> 40320 B

// ---- scratch ----
__device__ float g_qkv [BATCH*HH*WWID*QKVC];
__device__ float g_qkvp[BATCH*NWH*NWW*QKVC];
__device__ float g_attnout[BNW*WA*DIM];
__device__ int   g_rtab[NROLL];
__device__ float g_bias[HEADS*64*NKP];             // precomputed bias (heads,64,240)
__device__ unsigned long long g_pmask[256];        // pooled-invalid bitmask per window pos

__device__ __forceinline__ float to_tf32(float x) {
    unsigned u;
    asm("cvt.rna.tf32.f32 %0, %1;" : "=r"(u) : "f"(x));
    return __uint_as_float(u);
}

// pack two floats to f16x2 in a 32-bit reg
__device__ __forceinline__ unsigned pack_half2(float lo, float hi) {
    __half2_raw hr = (__half2_raw)__floats2half2_rn(lo, hi);
    return ((unsigned)hr.y << 16) | (unsigned)hr.x;
}

// fast exp on fma/alu pipes. valid for x <= 0.
__device__ __forceinline__ float fast_exp(float v) {
    v = fmaxf(v, -80.f);
    float t  = v * 1.4426950408889634f;
    float tb = t + 12582912.0f;
    int   i  = __float_as_int(tb) - 0x4B400000;
    float f  = t - (tb - 12582912.0f);
    float p  = 0.0013333558f;
    p = fmaf(p, f, 0.0096181291f);
    p = fmaf(p, f, 0.0555041087f);
    p = fmaf(p, f, 0.2402265070f);
    p = fmaf(p, f, 0.6931471806f);
    p = fmaf(p, f, 1.0f);
    return __int_as_float(__float_as_int(p) + (i << 23));
}

#define MMA_TF32(c0,c1,c2,c3,a0,a1,a2,a3,b0,b1)                              \
    asm volatile("mma.sync.aligned.m16n8k8.row.col.f32.tf32.tf32.f32 "       \
        "{%0,%1,%2,%3},{%4,%5,%6,%7},{%8,%9},{%0,%1,%2,%3};"                 \
        : "+f"(c0), "+f"(c1), "+f"(c2), "+f"(c3)                             \
        : "r"(a0), "r"(a1), "r"(a2), "r"(a3), "r"(b0), "r"(b1))

#define MMA_F16(c0,c1,c2,c3,a0,a1,a2,a3,b0,b1)                               \
    asm volatile("mma.sync.aligned.m16n8k16.row.col.f32.f16.f16.f32 "        \
        "{%0,%1,%2,%3},{%4,%5,%6,%7},{%8,%9},{%0,%1,%2,%3};"                 \
        : "+f"(c0), "+f"(c1), "+f"(c2), "+f"(c3)                             \
        : "r"(a0), "r"(a1), "r"(a2), "r"(a3), "r"(b0), "r"(b1))

// ============================================================
__global__ void init_rtab_kernel() {
    if (threadIdx.x == 0 && blockIdx.x == 0) {
        int n = 0;
        for (int s = 0; s < 4; s++)
            for (int r = 0; r < 7; r++)
                for (int c = 0; c < 7; c++) {
                    bool inval;
                    if      (s == 0) inval = (r < 4 && c < 4);
                    else if (s == 1) inval = (r < 4 && c >= 3);
                    else if (s == 2) inval = (r >= 3 && c < 4);
                    else             inval = (r >= 3 && c >= 3);
                    if (!inval) g_rtab[n++] = (s << 6) | (r << 3) | c;
                }
    }
}

// bias table (heads, 64 q-rows, 240 keys) + pooled-invalid bitmasks
__global__ void init_bias_kernel(const float* __restrict__ rpb_table,
                                 const float* __restrict__ rpb_nb,
                                 const float* __restrict__ rpb_win) {
    for (int i = blockIdx.x * blockDim.x + threadIdx.x;
         i < HEADS * 64 * NKP; i += gridDim.x * blockDim.x) {
        int j   = i % NKP;
        int row = (i / NKP) & 63;
        int h   = i / (NKP * 64);
        float v;
        if (j >= NK)        v = -1e30f;     // padded keys -> softmax zero
        else if (row >= WA) v = 0.f;        // padded rows (outputs discarded)
        else {
            int rq = row / 7, cq = row - rq * 7;
            if (j < WA) {
                int rk = j / 7, ck = j - rk * 7;
                v = rpb_table[((rq - rk + 6) * 13 + (cq - ck + 6)) * HEADS + h];
            } else if (j < WA + NROLL) {
                v = rpb_nb[(h * WA + row) * NROLL + (j - WA)];
            } else {
                int jp = j - WA - NROLL;
                int rk = jp / 7, ck = jp - rk * 7;
                v = rpb_win[h * 169 + (rq - rk + 6) * 13 + (cq - ck + 6)];
            }
        }
        g_bias[i] = v;
    }
    if (blockIdx.x == 0 && threadIdx.x < 256) {
        int wi = threadIdx.x >> 4, wj = threadIdx.x & 15;
        unsigned long long m = 0ull;
        for (int s = 0; s < WA; s++) {
            int rk = s / 7, ck = s - rk * 7;
            int py = wi + rk - EXPAND, px = wj + ck - EXPAND;
            if (py < 0 || py >= NWH || px < 0 || px >= NWW) m |= (1ull << s);
        }
        g_pmask[threadIdx.x] = m;
    }
}

// ============================================================
// tf32 tensor-core GEMM (validated in R4)
// ============================================================
__global__ __launch_bounds__(256)
void gemm_tf32_kernel(const float* __restrict__ A, const float* __restrict__ Bw,
                      const float* __restrict__ bias, float* __restrict__ C,
                      int M, int N, int K) {
    __shared__ float As[16][136];
    __shared__ float Bs[16][72];
    const int tid = threadIdx.x;
    const int m0 = blockIdx.x << 7;
    const int n0 = blockIdx.y << 6;
    const int ar = tid >> 1, ac = (tid & 1) << 3;
    const int br = tid >> 2, bc = (tid & 3) << 2;
    const int wp = tid >> 5, lane = tid & 31;
    const int gid = lane >> 2, tig = lane & 3;
    const int wm = (wp >> 1) << 5;
    const int wn = (wp & 1) << 5;

    float acc[2][4][4] = {};

    for (int k0 = 0; k0 < K; k0 += 16) {
        float4 a0 = *(const float4*)(A + (long)(m0 + ar) * K + k0 + ac);
        float4 a1 = *(const float4*)(A + (long)(m0 + ar) * K + k0 + ac + 4);
        float4 bv = *(const float4*)(Bw + (long)(n0 + br) * K + k0 + bc);
        As[ac + 0][ar] = to_tf32(a0.x); As[ac + 1][ar] = to_tf32(a0.y);
        As[ac + 2][ar] = to_tf32(a0.z); As[ac + 3][ar] = to_tf32(a0.w);
        As[ac + 4][ar] = to_tf32(a1.x); As[ac + 5][ar] = to_tf32(a1.y);
        As[ac + 6][ar] = to_tf32(a1.z); As[ac + 7][ar] = to_tf32(a1.w);
        Bs[bc + 0][br] = to_tf32(bv.x); Bs[bc + 1][br] = to_tf32(bv.y);
        Bs[bc + 2][br] = to_tf32(bv.z); Bs[bc + 3][br] = to_tf32(bv.w);
        __syncthreads();
#pragma unroll
        for (int ks = 0; ks < 2; ks++) {
            const int kk = ks << 3;
            unsigned afr[2][4], bfr[4][2];
#pragma unroll
            for (int mt = 0; mt < 2; mt++) {
                const int mb = wm + (mt << 4);
                afr[mt][0] = __float_as_uint(As[kk + tig][mb + gid]);
                afr[mt][1] = __float_as_uint(As[kk + tig][mb + gid + 8]);
                afr[mt][2] = __float_as_uint(As[kk + tig + 4][mb + gid]);
                afr[mt][3] = __float_as_uint(As[kk + tig + 4][mb + gid + 8]);
            }
#pragma unroll
            for (int nt = 0; nt < 4; nt++) {
                const int nb = wn + (nt << 3);
                bfr[nt][0] = __float_as_uint(Bs[kk + tig][nb + gid]);
                bfr[nt][1] = __float_as_uint(Bs[kk + tig + 4][nb + gid]);
            }
#pragma unroll
            for (int mt = 0; mt < 2; mt++)
#pragma unroll
                for (int nt = 0; nt < 4; nt++)
                    MMA_TF32(acc[mt][nt][0], acc[mt][nt][1], acc[mt][nt][2], acc[mt][nt][3],
                             afr[mt][0], afr[mt][1], afr[mt][2], afr[mt][3],
                             bfr[nt][0], bfr[nt][1]);
        }
        __syncthreads();
    }

#pragma unroll
    for (int mt = 0; mt < 2; mt++) {
        const int r0 = m0 + wm + (mt << 4) + gid;
#pragma unroll
        for (int nt = 0; nt < 4; nt++) {
            const int ccol = n0 + wn + (nt << 3) + (tig << 1);
            const float b0 = bias[ccol], b1 = bias[ccol + 1];
            *(float2*)(C + (long)r0 * N + ccol) =
                make_float2(acc[mt][nt][0] + b0, acc[mt][nt][1] + b1);
            *(float2*)(C + (long)(r0 + 8) * N + ccol) =
                make_float2(acc[mt][nt][2] + b0, acc[mt][nt][3] + b1);
        }
    }
}

// ============================================================
// flash-style fp16 MMA attention: block = (window, head), 128 threads.
// logits live in registers; smem = q/k fp16 + v^T fp16 = 40320 B.
// ============================================================
__global__ __launch_bounds__(128, 3)
void attn_kernel() {
    extern __shared__ __half sh[];
    __half* sq  = sh + SQ_OFF;    // [64][SKH]
    __half* sk  = sh + SK_OFF;    // [NKP][SKH]
    __half* svt = sh + SVT_OFF;   // [HD][SVH]

    const int tid = threadIdx.x;
    const int wp = tid >> 5, lane = tid & 31;
    const int gid = lane >> 2, tig = lane & 3;
    const int w = blockIdx.x;
    const int h = blockIdx.y;
    const int b  = w >> 8;
    const int wl = w & 255;
    const int wi = wl >> 4, wj = wl & 15;
    const int y0 = wi * WS, x0 = wj * WS;

    // ---- zero smem (padding must be 0) ----
    {
        float4* z = (float4*)sh;
        float4 zz = make_float4(0.f, 0.f, 0.f, 0.f);
        for (int i = tid; i < SMEM_HALVES / 8; i += 128) z[i] = zz;
    }
    __syncthreads();

    // ---- gather q (scaled) ----
    for (int r = wp; r < WA; r += 4) {
        int rr = r / 7, cc = r - rr * 7;
        float qv = g_qkv[(((b * HH) + (y0 + rr)) * WWID + (x0 + cc)) * QKVC + h * HD + lane];
        sq[r * SKH + lane] = __float2half(qv * ATT_SCALE);
    }
    // ---- gather k / v ----
    for (int j = wp; j < NK; j += 4) {
        int base;
        if (j < WA) {
            int r = j / 7, c = j - r * 7;
            base = (((b * HH) + (y0 + r)) * WWID + (x0 + c)) * QKVC;
        } else if (j < WA + NROLL) {
            int pk = g_rtab[j - WA];
            int s = pk >> 6, r = (pk >> 3) & 7, c = pk & 7;
            int dy = (s < 2) ? EXPAND : -EXPAND;
            int dx = ((s & 1) == 0) ? EXPAND : -EXPAND;
            int y = (y0 + r + dy + HH) % HH;
            int x = (x0 + c + dx + WWID) % WWID;
            base = ((b * HH + y) * WWID + x) * QKVC;
        } else {
            int jp = j - WA - NROLL;
            int r = jp / 7, c = jp - r * 7;
            int py = wi + r - EXPAND, px = wj + c - EXPAND;
            base = (py >= 0 && py < NWH && px >= 0 && px < NWW)
                   ? ((b * NWH + py) * NWW + px) * QKVC : -1;
            if (base < 0) { sk[j * SKH + lane] = __float2half(0.f);
                            svt[lane * SVH + j] = __float2half(0.f); continue; }
            sk[j * SKH + lane]  = __float2half(g_qkvp[base + DIM     + h * HD + lane]);
            svt[lane * SVH + j] = __float2half(g_qkvp[base + 2 * DIM + h * HD + lane]);
            continue;
        }
        sk[j * SKH + lane]  = __float2half(g_qkv[base + DIM     + h * HD + lane]);
        svt[lane * SVH + j] = __float2half(g_qkv[base + 2 * DIM + h * HD + lane]);
    }
    __syncthreads();

    // ---- QK^T: warp owns 16 q-rows x 240 keys; S in registers ----
    const int q0 = wp << 4;
    unsigned qa[2][4];
#pragma unroll
    for (int ks = 0; ks < 2; ks++) {
        const int ra = (q0 + gid) * SKH + (ks << 4);
        const int rb = ra + (SKH << 3);                 // row + 8
        qa[ks][0] = *(const unsigned*)&sq[ra + 2 * tig];
        qa[ks][1] = *(const unsigned*)&sq[rb + 2 * tig];
        qa[ks][2] = *(const unsigned*)&sq[ra + 2 * tig + 8];
        qa[ks][3] = *(const unsigned*)&sq[rb + 2 * tig + 8];
    }

    float S[30][4];
    const unsigned long long pm = g_pmask[wl];
    const float* brow0 = &g_bias[((h << 6) + q0 + gid) * NKP];
    const float* brow1 = brow0 + (NKP << 3);

#pragma unroll
    for (int t = 0; t < 30; t++) {
        const int j0 = t << 3;
        float c0, c1, c2, c3;
        {   // bias preload as accumulator init
            float2 bL0 = *(const float2*)(brow0 + j0 + 2 * tig);
            float2 bL1 = *(const float2*)(brow1 + j0 + 2 * tig);
            c0 = bL0.x; c1 = bL0.y; c2 = bL1.x; c3 = bL1.y;
        }
        const int krow = (j0 + gid) * SKH;
        unsigned b00 = *(const unsigned*)&sk[krow + 2 * tig];
        unsigned b01 = *(const unsigned*)&sk[krow + 2 * tig + 8];
        unsigned b10 = *(const unsigned*)&sk[krow + 16 + 2 * tig];
        unsigned b11 = *(const unsigned*)&sk[krow + 16 + 2 * tig + 8];
        MMA_F16(c0, c1, c2, c3, qa[0][0], qa[0][1], qa[0][2], qa[0][3], b00, b01);
        MMA_F16(c0, c1, c2, c3, qa[1][0], qa[1][1], qa[1][2], qa[1][3], b10, b11);
        // pooled-boundary mask (-100 on invalid pooled slots)
        const int jj = j0 + 2 * tig;
        if (jj >= 181 && jj < 230 && ((pm >> (jj - 181)) & 1ull)) { c0 -= 100.f; c2 -= 100.f; }
        if (jj + 1 >= 181 && jj + 1 < 230 && ((pm >> (jj - 180)) & 1ull)) { c1 -= 100.f; c3 -= 100.f; }
        S[t][0] = c0; S[t][1] = c1; S[t][2] = c2; S[t][3] = c3;
    }

    // ---- softmax over registers (reduce across tig lanes) ----
    float m0 = -1e30f, m1 = -1e30f;
#pragma unroll
    for (int t = 0; t < 30; t++) {
        m0 = fmaxf(m0, fmaxf(S[t][0], S[t][1]));
        m1 = fmaxf(m1, fmaxf(S[t][2], S[t][3]));
    }
    m0 = fmaxf(m0, __shfl_xor_sync(0xffffffffu, m0, 1));
    m0 = fmaxf(m0, __shfl_xor_sync(0xffffffffu, m0, 2));
    m1 = fmaxf(m1, __shfl_xor_sync(0xffffffffu, m1, 1));
    m1 = fmaxf(m1, __shfl_xor_sync(0xffffffffu, m1, 2));
    float s0 = 0.f, s1 = 0.f;
#pragma unroll
    for (int t = 0; t < 30; t++) {
        S[t][0] = fast_exp(S[t][0] - m0); s0 += S[t][0];
        S[t][1] = fast_exp(S[t][1] - m0); s0 += S[t][1];
        S[t][2] = fast_exp(S[t][2] - m1); s1 += S[t][2];
        S[t][3] = fast_exp(S[t][3] - m1); s1 += S[t][3];
    }
    s0 += __shfl_xor_sync(0xffffffffu, s0, 1);
    s0 += __shfl_xor_sync(0xffffffffu, s0, 2);
    s1 += __shfl_xor_sync(0xffffffffu, s1, 1);
    s1 += __shfl_xor_sync(0xffffffffu, s1, 2);
    const float inv0 = 1.f / s0, inv1 = 1.f / s1;

    // ---- O = P @ V ----
    float O[4][4] = {};
#pragma unroll
    for (int kc = 0; kc < 15; kc++) {
        const int t0 = kc << 1;
        unsigned a0 = pack_half2(S[t0][0] * inv0, S[t0][1] * inv0);
        unsigned a1 = pack_half2(S[t0][2] * inv1, S[t0][3] * inv1);
        unsigned a2 = pack_half2(S[t0 + 1][0] * inv0, S[t0 + 1][1] * inv0);
        unsigned a3 = pack_half2(S[t0 + 1][2] * inv1, S[t0 + 1][3] * inv1);
        const int j0 = kc << 4;
#pragma unroll
        for (int nt = 0; nt < 4; nt++) {
            const int vrow = ((nt << 3) + gid) * SVH + j0 + 2 * tig;
            unsigned b0 = *(const unsigned*)&svt[vrow];
            unsigned b1 = *(const unsigned*)&svt[vrow + 8];
            MMA_F16(O[nt][0], O[nt][1], O[nt][2], O[nt][3], a0, a1, a2, a3, b0, b1);
        }
    }

    // ---- store ----
    const int r0 = q0 + gid, r1 = r0 + 8;
#pragma unroll
    for (int nt = 0; nt < 4; nt++) {
        const int dcol = h * HD + (nt << 3) + (tig << 1);
        if (r0 < WA)
            *(float2*)&g_attnout[(long)(w * WA + r0) * DIM + dcol] = make_float2(O[nt][0], O[nt][1]);
        if (r1 < WA)
            *(float2*)&g_attnout[(long)(w * WA + r1) * DIM + dcol] = make_float2(O[nt][2], O[nt][3]);
    }
}

// ============================================================
// launch
// ============================================================
extern "C" void kernel_launch(void* const* d_in, const int* in_sizes, int n_in,
                              void* d_out, int out_size) {
    const float* x         = (const float*)d_in[0];
    const float* x_pooled  = (const float*)d_in[1];
    const float* qkv_w     = (const float*)d_in[2];
    const float* qkv_b     = (const float*)d_in[3];
    const float* proj_w    = (const float*)d_in[4];
    const float* proj_b    = (const float*)d_in[5];
    const float* rpb_table = (const float*)d_in[6];
    const float* rpb_nb    = (const float*)d_in[7];
    const float* rpb_win   = (const float*)d_in[8];
    float* out = (float*)d_out;

    float *p_qkv = nullptr, *p_qkvp = nullptr, *p_ao = nullptr;
    cudaGetSymbolAddress((void**)&p_qkv,  g_qkv);
    cudaGetSymbolAddress((void**)&p_qkvp, g_qkvp);
    cudaGetSymbolAddress((void**)&p_ao,   g_attnout);

    const int attn_smem = SMEM_HALVES * 2;  // 40320 B
    cudaFuncSetAttribute(attn_kernel, cudaFuncAttributeMaxDynamicSharedMemorySize, attn_smem);

    init_rtab_kernel<<<1, 32>>>();
    init_bias_kernel<<<96, 256>>>(rpb_table, rpb_nb, rpb_win);

    gemm_tf32_kernel<<<dim3(100352 / 128, QKVC / 64), 256>>>(
        x, qkv_w, qkv_b, p_qkv, BATCH * HH * WWID, QKVC, DIM);

    gemm_tf32_kernel<<<dim3(2048 / 128, QKVC / 64), 256>>>(
        x_pooled, qkv_w, qkv_b, p_qkvp, BATCH * NWH * NWW, QKVC, DIM);

    attn_kernel<<<dim3(BNW, HEADS), 128, attn_smem>>>();

    gemm_tf32_kernel<<<dim3(100352 / 128, DIM / 64), 256>>>(
        p_ao, proj_w, proj_b, out, BNW * WA, DIM, DIM);
}

// round 8
// speedup vs baseline: 2.5055x; 1.0647x over previous
#include <cuda_runtime.h>
#include <cuda_fp16.h>
#include <limits.h>

// ---- problem constants ----
#define BATCH 8
#define HH    112
#define WWID  112
#define DIM   192
#define HEADS 6
#define HD    32
#define WS    7
#define WA    49
#define EXPAND 3
#define NWH   16
#define NWW   16
#define BNW   2048
#define NROLL 132
#define NK    230
#define NKP   256
#define QKVC  (3*DIM)
#define ATT_SCALE 0.17677669529663689f
#define FINE_STRIDE (HH*WWID*QKVC)
#define POOL_STRIDE (NWH*NWW*QKVC)

// smem layout (in halves)
#define SKH 40
#define SVH 264
#define SQ_OFF   0
#define SK_OFF   (64*SKH)                  // 2560
#define SVT_OFF  (SK_OFF + NKP*SKH)        // 12800
#define SRED_OFF (SVT_OFF + HD*SVH)        // 21248
#define SMEM_HALVES (SRED_OFF + 512)       // 21760 halves = 43520 B
#define SOP_STRIDE 34                      // EVEN: float2 stores stay 8B-aligned

// ---- scratch ----
__device__ float g_qkv [BATCH*HH*WWID*QKVC];
__device__ float g_qkvp[BATCH*NWH*NWW*QKVC];
__device__ float g_attnout[BNW*WA*DIM];
__device__ float g_bias[HEADS*64*NKP];
__device__ unsigned long long g_pmask[256];
__device__ int   g_gtab[256*NKP];          // per-window k/v source offsets
__device__ int   g_qtab[256*64];           // per-window q source offsets

__device__ __forceinline__ float to_tf32(float x) {
    unsigned u;
    asm("cvt.rna.tf32.f32 %0, %1;" : "=r"(u) : "f"(x));
    return __uint_as_float(u);
}

__device__ __forceinline__ unsigned pack_half2(float lo, float hi) {
    __half2_raw hr = (__half2_raw)__floats2half2_rn(lo, hi);
    return ((unsigned)hr.y << 16) | (unsigned)hr.x;
}

// fast exp on fma/alu pipes. valid for x <= 0.
__device__ __forceinline__ float fast_exp(float v) {
    v = fmaxf(v, -80.f);
    float t  = v * 1.4426950408889634f;
    float tb = t + 12582912.0f;
    int   i  = __float_as_int(tb) - 0x4B400000;
    float f  = t - (tb - 12582912.0f);
    float p  = 0.0013333558f;
    p = fmaf(p, f, 0.0096181291f);
    p = fmaf(p, f, 0.0555041087f);
    p = fmaf(p, f, 0.2402265070f);
    p = fmaf(p, f, 0.6931471806f);
    p = fmaf(p, f, 1.0f);
    return __int_as_float(__float_as_int(p) + (i << 23));
}

#define MMA_TF32(c0,c1,c2,c3,a0,a1,a2,a3,b0,b1)                              \
    asm volatile("mma.sync.aligned.m16n8k8.row.col.f32.tf32.tf32.f32 "       \
        "{%0,%1,%2,%3},{%4,%5,%6,%7},{%8,%9},{%0,%1,%2,%3};"                 \
        : "+f"(c0), "+f"(c1), "+f"(c2), "+f"(c3)                             \
        : "r"(a0), "r"(a1), "r"(a2), "r"(a3), "r"(b0), "r"(b1))

#define MMA_F16(c0,c1,c2,c3,a0,a1,a2,a3,b0,b1)                               \
    asm volatile("mma.sync.aligned.m16n8k16.row.col.f32.f16.f16.f32 "        \
        "{%0,%1,%2,%3},{%4,%5,%6,%7},{%8,%9},{%0,%1,%2,%3};"                 \
        : "+f"(c0), "+f"(c1), "+f"(c2), "+f"(c3)                             \
        : "r"(a0), "r"(a1), "r"(a2), "r"(a3), "r"(b0), "r"(b1))

// ============================================================
// per-window gather tables (one thread per window position)
// ============================================================
__global__ void init_gtab_kernel() {
    int wl = threadIdx.x;
    if (blockIdx.x != 0 || wl >= 256) return;
    int wi = wl >> 4, wj = wl & 15;
    int y0 = wi * WS, x0 = wj * WS;
    for (int j = 0; j < WA; j++) {
        int r = j / 7, c = j - r * 7;
        g_gtab[wl * NKP + j] = ((y0 + r) * WWID + (x0 + c)) * QKVC;
    }
    int n = WA;
    for (int s = 0; s < 4; s++)
        for (int r = 0; r < 7; r++)
            for (int c = 0; c < 7; c++) {
                bool inval;
                if      (s == 0) inval = (r < 4 && c < 4);
                else if (s == 1) inval = (r < 4 && c >= 3);
                else if (s == 2) inval = (r >= 3 && c < 4);
                else             inval = (r >= 3 && c >= 3);
                if (inval) continue;
                int dy = (s < 2) ? EXPAND : -EXPAND;
                int dx = ((s & 1) == 0) ? EXPAND : -EXPAND;
                int y = (y0 + r + dy + HH) % HH;
                int x = (x0 + c + dx + WWID) % WWID;
                g_gtab[wl * NKP + n++] = (y * WWID + x) * QKVC;
            }
    for (int jp = 0; jp < WA; jp++) {
        int r = jp / 7, c = jp - r * 7;
        int py = wi + r - EXPAND, px = wj + c - EXPAND;
        g_gtab[wl * NKP + 181 + jp] =
            (py >= 0 && py < NWH && px >= 0 && px < NWW)
            ? ~((py * NWW + px) * QKVC) : INT_MIN;
    }
    for (int j = NK; j < NKP; j++) g_gtab[wl * NKP + j] = INT_MIN;
    for (int r = 0; r < WA; r++) {
        int rr = r / 7, cc = r - rr * 7;
        g_qtab[wl * 64 + r] = ((y0 + rr) * WWID + (x0 + cc)) * QKVC;
    }
    unsigned long long m = 0ull;
    for (int s = 0; s < WA; s++) {
        int rk = s / 7, ck = s - rk * 7;
        int py = wi + rk - EXPAND, px = wj + ck - EXPAND;
        if (py < 0 || py >= NWH || px < 0 || px >= NWW) m |= (1ull << s);
    }
    g_pmask[wl] = m;
}

// bias table (heads, 64 q-rows, 256 keys)
__global__ void init_bias_kernel(const float* __restrict__ rpb_table,
                                 const float* __restrict__ rpb_nb,
                                 const float* __restrict__ rpb_win) {
    for (int i = blockIdx.x * blockDim.x + threadIdx.x;
         i < HEADS * 64 * NKP; i += gridDim.x * blockDim.x) {
        int j   = i % NKP;
        int row = (i / NKP) & 63;
        int h   = i / (NKP * 64);
        float v;
        if (j >= NK)        v = -1e30f;
        else if (row >= WA) v = 0.f;
        else {
            int rq = row / 7, cq = row - rq * 7;
            if (j < WA) {
                int rk = j / 7, ck = j - rk * 7;
                v = rpb_table[((rq - rk + 6) * 13 + (cq - ck + 6)) * HEADS + h];
            } else if (j < WA + NROLL) {
                v = rpb_nb[(h * WA + row) * NROLL + (j - WA)];
            } else {
                int jp = j - WA - NROLL;
                int rk = jp / 7, ck = jp - rk * 7;
                v = rpb_win[h * 169 + (rq - rk + 6) * 13 + (cq - ck + 6)];
            }
        }
        g_bias[i] = v;
    }
}

// ============================================================
// tf32 tensor-core GEMM (validated in R4)
// ============================================================
__global__ __launch_bounds__(256)
void gemm_tf32_kernel(const float* __restrict__ A, const float* __restrict__ Bw,
                      const float* __restrict__ bias, float* __restrict__ C,
                      int M, int N, int K) {
    __shared__ float As[16][136];
    __shared__ float Bs[16][72];
    const int tid = threadIdx.x;
    const int m0 = blockIdx.x << 7;
    const int n0 = blockIdx.y << 6;
    const int ar = tid >> 1, ac = (tid & 1) << 3;
    const int br = tid >> 2, bc = (tid & 3) << 2;
    const int wp = tid >> 5, lane = tid & 31;
    const int gid = lane >> 2, tig = lane & 3;
    const int wm = (wp >> 1) << 5;
    const int wn = (wp & 1) << 5;

    float acc[2][4][4] = {};

    for (int k0 = 0; k0 < K; k0 += 16) {
        float4 a0 = *(const float4*)(A + (long)(m0 + ar) * K + k0 + ac);
        float4 a1 = *(const float4*)(A + (long)(m0 + ar) * K + k0 + ac + 4);
        float4 bv = *(const float4*)(Bw + (long)(n0 + br) * K + k0 + bc);
        As[ac + 0][ar] = to_tf32(a0.x); As[ac + 1][ar] = to_tf32(a0.y);
        As[ac + 2][ar] = to_tf32(a0.z); As[ac + 3][ar] = to_tf32(a0.w);
        As[ac + 4][ar] = to_tf32(a1.x); As[ac + 5][ar] = to_tf32(a1.y);
        As[ac + 6][ar] = to_tf32(a1.z); As[ac + 7][ar] = to_tf32(a1.w);
        Bs[bc + 0][br] = to_tf32(bv.x); Bs[bc + 1][br] = to_tf32(bv.y);
        Bs[bc + 2][br] = to_tf32(bv.z); Bs[bc + 3][br] = to_tf32(bv.w);
        __syncthreads();
#pragma unroll
        for (int ks = 0; ks < 2; ks++) {
            const int kk = ks << 3;
            unsigned afr[2][4], bfr[4][2];
#pragma unroll
            for (int mt = 0; mt < 2; mt++) {
                const int mb = wm + (mt << 4);
                afr[mt][0] = __float_as_uint(As[kk + tig][mb + gid]);
                afr[mt][1] = __float_as_uint(As[kk + tig][mb + gid + 8]);
                afr[mt][2] = __float_as_uint(As[kk + tig + 4][mb + gid]);
                afr[mt][3] = __float_as_uint(As[kk + tig + 4][mb + gid + 8]);
            }
#pragma unroll
            for (int nt = 0; nt < 4; nt++) {
                const int nb = wn + (nt << 3);
                bfr[nt][0] = __float_as_uint(Bs[kk + tig][nb + gid]);
                bfr[nt][1] = __float_as_uint(Bs[kk + tig + 4][nb + gid]);
            }
#pragma unroll
            for (int mt = 0; mt < 2; mt++)
#pragma unroll
                for (int nt = 0; nt < 4; nt++)
                    MMA_TF32(acc[mt][nt][0], acc[mt][nt][1], acc[mt][nt][2], acc[mt][nt][3],
                             afr[mt][0], afr[mt][1], afr[mt][2], afr[mt][3],
                             bfr[nt][0], bfr[nt][1]);
        }
        __syncthreads();
    }

#pragma unroll
    for (int mt = 0; mt < 2; mt++) {
        const int r0 = m0 + wm + (mt << 4) + gid;
#pragma unroll
        for (int nt = 0; nt < 4; nt++) {
            const int ccol = n0 + wn + (nt << 3) + (tig << 1);
            const float b0 = bias[ccol], b1 = bias[ccol + 1];
            *(float2*)(C + (long)r0 * N + ccol) =
                make_float2(acc[mt][nt][0] + b0, acc[mt][nt][1] + b1);
            *(float2*)(C + (long)(r0 + 8) * N + ccol) =
                make_float2(acc[mt][nt][2] + b0, acc[mt][nt][3] + b1);
        }
    }
}

// ============================================================
// fp16 MMA attention, key-split: block=(window,head), 256 threads.
// warp wp: q-rows 16*(wp&3).., keys 128*(wp>>2)..  S=64 f32 regs.
// ============================================================
__global__ __launch_bounds__(256, 2)
void attn_kernel() {
    extern __shared__ __half sh[];
    __half* sq   = sh + SQ_OFF;    // [64][SKH]
    __half* sk   = sh + SK_OFF;    // [NKP][SKH]
    __half* svt  = sh + SVT_OFF;   // [HD][SVH]
    float*  sred = (float*)(sh + SRED_OFF);   // [2 kinds][2 halves][64]
    float*  sOp  = (float*)(sh + SK_OFF);     // [64][SOP_STRIDE] partial O (aliases sk)

    const int tid = threadIdx.x;
    const int wp = tid >> 5, lane = tid & 31;
    const int gid = lane >> 2, tig = lane & 3;
    const int w = blockIdx.x;
    const int h = blockIdx.y;
    const int b  = w >> 8;
    const int wl = w & 255;
    const int bFine = b * FINE_STRIDE;
    const int bPool = b * POOL_STRIDE;
    const int hcol = h * HD;

    // ---- zero smem ----
    {
        float4* z = (float4*)sh;
        float4 zz = make_float4(0.f, 0.f, 0.f, 0.f);
        for (int i = tid; i < (SRED_OFF) / 8; i += 256) z[i] = zz;
    }
    __syncthreads();

    // ---- gather q ----
    for (int r = wp; r < WA; r += 8) {
        int off = g_qtab[(wl << 6) + r];
        sq[r * SKH + lane] = __float2half(g_qkv[bFine + off + hcol + lane] * ATT_SCALE);
    }
    // ---- gather k / v (table-driven, no divmod) ----
    for (int j = wp; j < NK; j += 8) {
        int off = g_gtab[(wl << 8) + j];
        if (off == INT_MIN) continue;
        const float* base = (off >= 0) ? (g_qkv + bFine + off) : (g_qkvp + bPool + ~off);
        sk[j * SKH + lane]  = __float2half(base[DIM     + hcol + lane]);
        svt[lane * SVH + j] = __float2half(base[2 * DIM + hcol + lane]);
    }
    __syncthreads();

    // ---- QK^T: warp -> 16 q-rows x 128 keys ----
    const int q0 = (wp & 3) << 4;
    const int kh = wp >> 2;           // key half 0/1
    const int kb = kh << 7;           // key base 0/128
    unsigned qa[2][4];
#pragma unroll
    for (int ks = 0; ks < 2; ks++) {
        const int ra = (q0 + gid) * SKH + (ks << 4);
        const int rb = ra + (SKH << 3);
        qa[ks][0] = *(const unsigned*)&sq[ra + 2 * tig];
        qa[ks][1] = *(const unsigned*)&sq[rb + 2 * tig];
        qa[ks][2] = *(const unsigned*)&sq[ra + 2 * tig + 8];
        qa[ks][3] = *(const unsigned*)&sq[rb + 2 * tig + 8];
    }

    float S[16][4];
    const unsigned long long pm = g_pmask[wl];
    const float* brow0 = &g_bias[(((h << 6) + q0 + gid) << 8) + kb];
    const float* brow1 = brow0 + (NKP << 3);

#pragma unroll
    for (int t = 0; t < 16; t++) {
        const int j0 = kb + (t << 3);
        float c0, c1, c2, c3;
        {
            float2 bL0 = *(const float2*)(brow0 + (t << 3) + 2 * tig);
            float2 bL1 = *(const float2*)(brow1 + (t << 3) + 2 * tig);
            c0 = bL0.x; c1 = bL0.y; c2 = bL1.x; c3 = bL1.y;
        }
        const int krow = (j0 + gid) * SKH;
        unsigned b00 = *(const unsigned*)&sk[krow + 2 * tig];
        unsigned b01 = *(const unsigned*)&sk[krow + 2 * tig + 8];
        unsigned b10 = *(const unsigned*)&sk[krow + 16 + 2 * tig];
        unsigned b11 = *(const unsigned*)&sk[krow + 16 + 2 * tig + 8];
        MMA_F16(c0, c1, c2, c3, qa[0][0], qa[0][1], qa[0][2], qa[0][3], b00, b01);
        MMA_F16(c0, c1, c2, c3, qa[1][0], qa[1][1], qa[1][2], qa[1][3], b10, b11);
        if (kh) {   // pooled-boundary mask lives entirely in keys 181..229
            const int jj = j0 + 2 * tig;
            if (jj >= 181 && jj < 230 && ((pm >> (jj - 181)) & 1ull)) { c0 -= 100.f; c2 -= 100.f; }
            if (jj + 1 >= 181 && jj + 1 < 230 && ((pm >> (jj - 180)) & 1ull)) { c1 -= 100.f; c3 -= 100.f; }
        }
        S[t][0] = c0; S[t][1] = c1; S[t][2] = c2; S[t][3] = c3;
    }

    // ---- softmax: warp-local then cross-half via smem ----
    float m0 = -1e30f, m1 = -1e30f;
#pragma unroll
    for (int t = 0; t < 16; t++) {
        m0 = fmaxf(m0, fmaxf(S[t][0], S[t][1]));
        m1 = fmaxf(m1, fmaxf(S[t][2], S[t][3]));
    }
    m0 = fmaxf(m0, __shfl_xor_sync(0xffffffffu, m0, 1));
    m0 = fmaxf(m0, __shfl_xor_sync(0xffffffffu, m0, 2));
    m1 = fmaxf(m1, __shfl_xor_sync(0xffffffffu, m1, 1));
    m1 = fmaxf(m1, __shfl_xor_sync(0xffffffffu, m1, 2));
    if (tig == 0) {
        sred[(kh << 6) + q0 + gid]     = m0;
        sred[(kh << 6) + q0 + gid + 8] = m1;
    }
    __syncthreads();
    m0 = fmaxf(m0, sred[((kh ^ 1) << 6) + q0 + gid]);
    m1 = fmaxf(m1, sred[((kh ^ 1) << 6) + q0 + gid + 8]);

    float s0 = 0.f, s1 = 0.f;
#pragma unroll
    for (int t = 0; t < 16; t++) {
        S[t][0] = fast_exp(S[t][0] - m0); s0 += S[t][0];
        S[t][1] = fast_exp(S[t][1] - m0); s0 += S[t][1];
        S[t][2] = fast_exp(S[t][2] - m1); s1 += S[t][2];
        S[t][3] = fast_exp(S[t][3] - m1); s1 += S[t][3];
    }
    s0 += __shfl_xor_sync(0xffffffffu, s0, 1);
    s0 += __shfl_xor_sync(0xffffffffu, s0, 2);
    s1 += __shfl_xor_sync(0xffffffffu, s1, 1);
    s1 += __shfl_xor_sync(0xffffffffu, s1, 2);
    if (tig == 0) {
        sred[128 + (kh << 6) + q0 + gid]     = s0;
        sred[128 + (kh << 6) + q0 + gid + 8] = s1;
    }
    __syncthreads();
    s0 += sred[128 + ((kh ^ 1) << 6) + q0 + gid];
    s1 += sred[128 + ((kh ^ 1) << 6) + q0 + gid + 8];
    const float inv0 = 1.f / s0, inv1 = 1.f / s1;

    // ---- O = P @ V over this warp's 128 keys ----
    float O[4][4] = {};
#pragma unroll
    for (int kc = 0; kc < 8; kc++) {
        const int t0 = kc << 1;
        unsigned a0 = pack_half2(S[t0][0] * inv0, S[t0][1] * inv0);
        unsigned a1 = pack_half2(S[t0][2] * inv1, S[t0][3] * inv1);
        unsigned a2 = pack_half2(S[t0 + 1][0] * inv0, S[t0 + 1][1] * inv0);
        unsigned a3 = pack_half2(S[t0 + 1][2] * inv1, S[t0 + 1][3] * inv1);
        const int j0 = kb + (kc << 4);
#pragma unroll
        for (int nt = 0; nt < 4; nt++) {
            const int vrow = ((nt << 3) + gid) * SVH + j0 + 2 * tig;
            unsigned b0 = *(const unsigned*)&svt[vrow];
            unsigned b1 = *(const unsigned*)&svt[vrow + 8];
            MMA_F16(O[nt][0], O[nt][1], O[nt][2], O[nt][3], a0, a1, a2, a3, b0, b1);
        }
    }

    // ---- combine key-halves (sOp aliases sk: dead after QK) ----
    __syncthreads();
    if (kh == 1) {
#pragma unroll
        for (int nt = 0; nt < 4; nt++) {
            const int col = (nt << 3) + (tig << 1);
            *(float2*)&sOp[(q0 + gid) * SOP_STRIDE + col]     = make_float2(O[nt][0], O[nt][1]);
            *(float2*)&sOp[(q0 + gid + 8) * SOP_STRIDE + col] = make_float2(O[nt][2], O[nt][3]);
        }
    }
    __syncthreads();
    if (kh == 0) {
        const int r0 = q0 + gid, r1 = r0 + 8;
#pragma unroll
        for (int nt = 0; nt < 4; nt++) {
            const int col = (nt << 3) + (tig << 1);
            float2 p0 = *(const float2*)&sOp[r0 * SOP_STRIDE + col];
            float2 p1 = *(const float2*)&sOp[r1 * SOP_STRIDE + col];
            const int dcol = hcol + col;
            if (r0 < WA)
                *(float2*)&g_attnout[(long)(w * WA + r0) * DIM + dcol] =
                    make_float2(O[nt][0] + p0.x, O[nt][1] + p0.y);
            if (r1 < WA)
                *(float2*)&g_attnout[(long)(w * WA + r1) * DIM + dcol] =
                    make_float2(O[nt][2] + p1.x, O[nt][3] + p1.y);
        }
    }
}

// ============================================================
// launch
// ============================================================
extern "C" void kernel_launch(void* const* d_in, const int* in_sizes, int n_in,
                              void* d_out, int out_size) {
    const float* x         = (const float*)d_in[0];
    const float* x_pooled  = (const float*)d_in[1];
    const float* qkv_w     = (const float*)d_in[2];
    const float* qkv_b     = (const float*)d_in[3];
    const float* proj_w    = (const float*)d_in[4];
    const float* proj_b    = (const float*)d_in[5];
    const float* rpb_table = (const float*)d_in[6];
    const float* rpb_nb    = (const float*)d_in[7];
    const float* rpb_win   = (const float*)d_in[8];
    float* out = (float*)d_out;

    float *p_qkv = nullptr, *p_qkvp = nullptr, *p_ao = nullptr;
    cudaGetSymbolAddress((void**)&p_qkv,  g_qkv);
    cudaGetSymbolAddress((void**)&p_qkvp, g_qkvp);
    cudaGetSymbolAddress((void**)&p_ao,   g_attnout);

    const int attn_smem = SMEM_HALVES * 2;  // 43520 B
    cudaFuncSetAttribute(attn_kernel, cudaFuncAttributeMaxDynamicSharedMemorySize, attn_smem);

    init_gtab_kernel<<<1, 256>>>();
    init_bias_kernel<<<96, 256>>>(rpb_table, rpb_nb, rpb_win);

    gemm_tf32_kernel<<<dim3(100352 / 128, QKVC / 64), 256>>>(
        x, qkv_w, qkv_b, p_qkv, BATCH * HH * WWID, QKVC, DIM);

    gemm_tf32_kernel<<<dim3(2048 / 128, QKVC / 64), 256>>>(
        x_pooled, qkv_w, qkv_b, p_qkvp, BATCH * NWH * NWW, QKVC, DIM);

    attn_kernel<<<dim3(BNW, HEADS), 256, attn_smem>>>();

    gemm_tf32_kernel<<<dim3(100352 / 128, DIM / 64), 256>>>(
        p_ao, proj_w, proj_b, out, BNW * WA, DIM, DIM);
}

// round 9
// speedup vs baseline: 2.5154x; 1.0040x over previous
#include <cuda_runtime.h>
#include <cuda_fp16.h>
#include <limits.h>

// ---- problem constants ----
#define BATCH 8
#define HH    112
#define WWID  112
#define DIM   192
#define HEADS 6
#define HD    32
#define WS    7
#define WA    49
#define EXPAND 3
#define NWH   16
#define NWW   16
#define BNW   2048
#define NROLL 132
#define NK    230
#define NKP   256
#define QKVC  (3*DIM)
#define ATT_SCALE 0.17677669529663689f
#define FINE_STRIDE (HH*WWID*QKVC)
#define POOL_STRIDE (NWH*NWW*QKVC)

// smem layout (in halves)
#define SKH 40
#define SVH 264
#define SQ_OFF   0
#define SK_OFF   (64*SKH)                  // 2560
#define SVT_OFF  (SK_OFF + NKP*SKH)        // 12800
#define SRED_OFF (SVT_OFF + HD*SVH)        // 21248
#define SMEM_HALVES (SRED_OFF + 512)       // 21760 halves = 43520 B
#define SOP_STRIDE 34                      // EVEN: float2 stores stay 8B-aligned

// ---- scratch ----
__device__ float g_qkv [BATCH*HH*WWID*QKVC];
__device__ float g_qkvp[BATCH*NWH*NWW*QKVC];
__device__ float g_attnout[BNW*WA*DIM];
__device__ float g_bias[HEADS*64*NKP];
__device__ unsigned long long g_pmask[256];
__device__ int   g_gtab[256*NKP];
__device__ int   g_qtab[256*64];

__device__ __forceinline__ float to_tf32(float x) {
    unsigned u;
    asm("cvt.rna.tf32.f32 %0, %1;" : "=r"(u) : "f"(x));
    return __uint_as_float(u);
}

__device__ __forceinline__ unsigned pack_half2(float lo, float hi) {
    __half2_raw hr = (__half2_raw)__floats2half2_rn(lo, hi);
    return ((unsigned)hr.y << 16) | (unsigned)hr.x;
}

// fast exp on fma/alu pipes. valid for x <= 0.
__device__ __forceinline__ float fast_exp(float v) {
    v = fmaxf(v, -80.f);
    float t  = v * 1.4426950408889634f;
    float tb = t + 12582912.0f;
    int   i  = __float_as_int(tb) - 0x4B400000;
    float f  = t - (tb - 12582912.0f);
    float p  = 0.0013333558f;
    p = fmaf(p, f, 0.0096181291f);
    p = fmaf(p, f, 0.0555041087f);
    p = fmaf(p, f, 0.2402265070f);
    p = fmaf(p, f, 0.6931471806f);
    p = fmaf(p, f, 1.0f);
    return __int_as_float(__float_as_int(p) + (i << 23));
}

#define MMA_TF32(c0,c1,c2,c3,a0,a1,a2,a3,b0,b1)                              \
    asm volatile("mma.sync.aligned.m16n8k8.row.col.f32.tf32.tf32.f32 "       \
        "{%0,%1,%2,%3},{%4,%5,%6,%7},{%8,%9},{%0,%1,%2,%3};"                 \
        : "+f"(c0), "+f"(c1), "+f"(c2), "+f"(c3)                             \
        : "r"(a0), "r"(a1), "r"(a2), "r"(a3), "r"(b0), "r"(b1))

#define MMA_F16(c0,c1,c2,c3,a0,a1,a2,a3,b0,b1)                               \
    asm volatile("mma.sync.aligned.m16n8k16.row.col.f32.f16.f16.f32 "        \
        "{%0,%1,%2,%3},{%4,%5,%6,%7},{%8,%9},{%0,%1,%2,%3};"                 \
        : "+f"(c0), "+f"(c1), "+f"(c2), "+f"(c3)                             \
        : "r"(a0), "r"(a1), "r"(a2), "r"(a3), "r"(b0), "r"(b1))

// ============================================================
// merged init: bias table + per-window gather tables (5 launches total
// so ncu -s 5 profiles attn_kernel)
// ============================================================
__global__ void init_kernel(const float* __restrict__ rpb_table,
                            const float* __restrict__ rpb_nb,
                            const float* __restrict__ rpb_win) {
    for (int i = blockIdx.x * blockDim.x + threadIdx.x;
         i < HEADS * 64 * NKP; i += gridDim.x * blockDim.x) {
        int j   = i % NKP;
        int row = (i / NKP) & 63;
        int h   = i / (NKP * 64);
        float v;
        if (j >= NK)        v = -1e30f;
        else if (row >= WA) v = 0.f;
        else {
            int rq = row / 7, cq = row - rq * 7;
            if (j < WA) {
                int rk = j / 7, ck = j - rk * 7;
                v = rpb_table[((rq - rk + 6) * 13 + (cq - ck + 6)) * HEADS + h];
            } else if (j < WA + NROLL) {
                v = rpb_nb[(h * WA + row) * NROLL + (j - WA)];
            } else {
                int jp = j - WA - NROLL;
                int rk = jp / 7, ck = jp - rk * 7;
                v = rpb_win[h * 169 + (rq - rk + 6) * 13 + (cq - ck + 6)];
            }
        }
        g_bias[i] = v;
    }
    if (blockIdx.x == 0 && threadIdx.x < 256) {
        int wl = threadIdx.x;
        int wi = wl >> 4, wj = wl & 15;
        int y0 = wi * WS, x0 = wj * WS;
        for (int j = 0; j < WA; j++) {
            int r = j / 7, c = j - r * 7;
            g_gtab[wl * NKP + j] = ((y0 + r) * WWID + (x0 + c)) * QKVC;
        }
        int n = WA;
        for (int s = 0; s < 4; s++)
            for (int r = 0; r < 7; r++)
                for (int c = 0; c < 7; c++) {
                    bool inval;
                    if      (s == 0) inval = (r < 4 && c < 4);
                    else if (s == 1) inval = (r < 4 && c >= 3);
                    else if (s == 2) inval = (r >= 3 && c < 4);
                    else             inval = (r >= 3 && c >= 3);
                    if (inval) continue;
                    int dy = (s < 2) ? EXPAND : -EXPAND;
                    int dx = ((s & 1) == 0) ? EXPAND : -EXPAND;
                    int y = (y0 + r + dy + HH) % HH;
                    int x = (x0 + c + dx + WWID) % WWID;
                    g_gtab[wl * NKP + n++] = (y * WWID + x) * QKVC;
                }
        for (int jp = 0; jp < WA; jp++) {
            int r = jp / 7, c = jp - r * 7;
            int py = wi + r - EXPAND, px = wj + c - EXPAND;
            g_gtab[wl * NKP + 181 + jp] =
                (py >= 0 && py < NWH && px >= 0 && px < NWW)
                ? ~((py * NWW + px) * QKVC) : INT_MIN;
        }
        for (int j = NK; j < NKP; j++) g_gtab[wl * NKP + j] = INT_MIN;
        for (int r = 0; r < WA; r++) {
            int rr = r / 7, cc = r - rr * 7;
            g_qtab[wl * 64 + r] = ((y0 + rr) * WWID + (x0 + cc)) * QKVC;
        }
        unsigned long long m = 0ull;
        for (int s = 0; s < WA; s++) {
            int rk = s / 7, ck = s - rk * 7;
            int py = wi + rk - EXPAND, px = wj + ck - EXPAND;
            if (py < 0 || py >= NWH || px < 0 || px >= NWW) m |= (1ull << s);
        }
        g_pmask[wl] = m;
    }
}

// ============================================================
// tf32 tensor-core GEMM, DOUBLE-BUFFERED k-loop (1 barrier/iter)
// block tile 128x64, 256 thr, warp tile 32x32.
// ============================================================
__global__ __launch_bounds__(256)
void gemm_tf32_kernel(const float* __restrict__ A, const float* __restrict__ Bw,
                      const float* __restrict__ bias, float* __restrict__ C,
                      int M, int N, int K) {
    __shared__ float As[2][16][136];
    __shared__ float Bs[2][16][72];
    const int tid = threadIdx.x;
    const int m0 = blockIdx.x << 7;
    const int n0 = blockIdx.y << 6;
    const int ar = tid >> 1, ac = (tid & 1) << 3;
    const int br = tid >> 2, bc = (tid & 3) << 2;
    const int wp = tid >> 5, lane = tid & 31;
    const int gid = lane >> 2, tig = lane & 3;
    const int wm = (wp >> 1) << 5;
    const int wn = (wp & 1) << 5;

    const float* Aptr = A + (long)(m0 + ar) * K + ac;
    const float* Bptr = Bw + (long)(n0 + br) * K + bc;

    float acc[2][4][4] = {};

    // prologue: stage k-tile 0 into buffer 0
    {
        float4 a0 = *(const float4*)(Aptr);
        float4 a1 = *(const float4*)(Aptr + 4);
        float4 bv = *(const float4*)(Bptr);
        As[0][ac + 0][ar] = to_tf32(a0.x); As[0][ac + 1][ar] = to_tf32(a0.y);
        As[0][ac + 2][ar] = to_tf32(a0.z); As[0][ac + 3][ar] = to_tf32(a0.w);
        As[0][ac + 4][ar] = to_tf32(a1.x); As[0][ac + 5][ar] = to_tf32(a1.y);
        As[0][ac + 6][ar] = to_tf32(a1.z); As[0][ac + 7][ar] = to_tf32(a1.w);
        Bs[0][bc + 0][br] = to_tf32(bv.x); Bs[0][bc + 1][br] = to_tf32(bv.y);
        Bs[0][bc + 2][br] = to_tf32(bv.z); Bs[0][bc + 3][br] = to_tf32(bv.w);
    }
    __syncthreads();

    int cur = 0;
    for (int k0 = 0; k0 < K; k0 += 16) {
        const bool has_next = (k0 + 16) < K;
        float4 na0, na1, nbv;
        if (has_next) {   // prefetch next tile (overlaps with MMAs below)
            na0 = *(const float4*)(Aptr + k0 + 16);
            na1 = *(const float4*)(Aptr + k0 + 20);
            nbv = *(const float4*)(Bptr + k0 + 16);
        }
#pragma unroll
        for (int ks = 0; ks < 2; ks++) {
            const int kk = ks << 3;
            unsigned afr[2][4], bfr[4][2];
#pragma unroll
            for (int mt = 0; mt < 2; mt++) {
                const int mb = wm + (mt << 4);
                afr[mt][0] = __float_as_uint(As[cur][kk + tig][mb + gid]);
                afr[mt][1] = __float_as_uint(As[cur][kk + tig][mb + gid + 8]);
                afr[mt][2] = __float_as_uint(As[cur][kk + tig + 4][mb + gid]);
                afr[mt][3] = __float_as_uint(As[cur][kk + tig + 4][mb + gid + 8]);
            }
#pragma unroll
            for (int nt = 0; nt < 4; nt++) {
                const int nb = wn + (nt << 3);
                bfr[nt][0] = __float_as_uint(Bs[cur][kk + tig][nb + gid]);
                bfr[nt][1] = __float_as_uint(Bs[cur][kk + tig + 4][nb + gid]);
            }
#pragma unroll
            for (int mt = 0; mt < 2; mt++)
#pragma unroll
                for (int nt = 0; nt < 4; nt++)
                    MMA_TF32(acc[mt][nt][0], acc[mt][nt][1], acc[mt][nt][2], acc[mt][nt][3],
                             afr[mt][0], afr[mt][1], afr[mt][2], afr[mt][3],
                             bfr[nt][0], bfr[nt][1]);
        }
        if (has_next) {
            const int nxt = cur ^ 1;
            As[nxt][ac + 0][ar] = to_tf32(na0.x); As[nxt][ac + 1][ar] = to_tf32(na0.y);
            As[nxt][ac + 2][ar] = to_tf32(na0.z); As[nxt][ac + 3][ar] = to_tf32(na0.w);
            As[nxt][ac + 4][ar] = to_tf32(na1.x); As[nxt][ac + 5][ar] = to_tf32(na1.y);
            As[nxt][ac + 6][ar] = to_tf32(na1.z); As[nxt][ac + 7][ar] = to_tf32(na1.w);
            Bs[nxt][bc + 0][br] = to_tf32(nbv.x); Bs[nxt][bc + 1][br] = to_tf32(nbv.y);
            Bs[nxt][bc + 2][br] = to_tf32(nbv.z); Bs[nxt][bc + 3][br] = to_tf32(nbv.w);
            __syncthreads();
            cur = nxt;
        }
    }

#pragma unroll
    for (int mt = 0; mt < 2; mt++) {
        const int r0 = m0 + wm + (mt << 4) + gid;
#pragma unroll
        for (int nt = 0; nt < 4; nt++) {
            const int ccol = n0 + wn + (nt << 3) + (tig << 1);
            const float b0 = bias[ccol], b1 = bias[ccol + 1];
            *(float2*)(C + (long)r0 * N + ccol) =
                make_float2(acc[mt][nt][0] + b0, acc[mt][nt][1] + b1);
            *(float2*)(C + (long)(r0 + 8) * N + ccol) =
                make_float2(acc[mt][nt][2] + b0, acc[mt][nt][3] + b1);
        }
    }
}

// ============================================================
// fp16 MMA attention, key-split (identical to R8, passed)
// ============================================================
__global__ __launch_bounds__(256, 2)
void attn_kernel() {
    extern __shared__ __half sh[];
    __half* sq   = sh + SQ_OFF;
    __half* sk   = sh + SK_OFF;
    __half* svt  = sh + SVT_OFF;
    float*  sred = (float*)(sh + SRED_OFF);
    float*  sOp  = (float*)(sh + SK_OFF);

    const int tid = threadIdx.x;
    const int wp = tid >> 5, lane = tid & 31;
    const int gid = lane >> 2, tig = lane & 3;
    const int w = blockIdx.x;
    const int h = blockIdx.y;
    const int b  = w >> 8;
    const int wl = w & 255;
    const int bFine = b * FINE_STRIDE;
    const int bPool = b * POOL_STRIDE;
    const int hcol = h * HD;

    {
        float4* z = (float4*)sh;
        float4 zz = make_float4(0.f, 0.f, 0.f, 0.f);
        for (int i = tid; i < (SRED_OFF) / 8; i += 256) z[i] = zz;
    }
    __syncthreads();

    for (int r = wp; r < WA; r += 8) {
        int off = g_qtab[(wl << 6) + r];
        sq[r * SKH + lane] = __float2half(g_qkv[bFine + off + hcol + lane] * ATT_SCALE);
    }
    for (int j = wp; j < NK; j += 8) {
        int off = g_gtab[(wl << 8) + j];
        if (off == INT_MIN) continue;
        const float* base = (off >= 0) ? (g_qkv + bFine + off) : (g_qkvp + bPool + ~off);
        sk[j * SKH + lane]  = __float2half(base[DIM     + hcol + lane]);
        svt[lane * SVH + j] = __float2half(base[2 * DIM + hcol + lane]);
    }
    __syncthreads();

    const int q0 = (wp & 3) << 4;
    const int kh = wp >> 2;
    const int kb = kh << 7;
    unsigned qa[2][4];
#pragma unroll
    for (int ks = 0; ks < 2; ks++) {
        const int ra = (q0 + gid) * SKH + (ks << 4);
        const int rb = ra + (SKH << 3);
        qa[ks][0] = *(const unsigned*)&sq[ra + 2 * tig];
        qa[ks][1] = *(const unsigned*)&sq[rb + 2 * tig];
        qa[ks][2] = *(const unsigned*)&sq[ra + 2 * tig + 8];
        qa[ks][3] = *(const unsigned*)&sq[rb + 2 * tig + 8];
    }

    float S[16][4];
    const unsigned long long pm = g_pmask[wl];
    const float* brow0 = &g_bias[(((h << 6) + q0 + gid) << 8) + kb];
    const float* brow1 = brow0 + (NKP << 3);

#pragma unroll
    for (int t = 0; t < 16; t++) {
        const int j0 = kb + (t << 3);
        float c0, c1, c2, c3;
        {
            float2 bL0 = *(const float2*)(brow0 + (t << 3) + 2 * tig);
            float2 bL1 = *(const float2*)(brow1 + (t << 3) + 2 * tig);
            c0 = bL0.x; c1 = bL0.y; c2 = bL1.x; c3 = bL1.y;
        }
        const int krow = (j0 + gid) * SKH;
        unsigned b00 = *(const unsigned*)&sk[krow + 2 * tig];
        unsigned b01 = *(const unsigned*)&sk[krow + 2 * tig + 8];
        unsigned b10 = *(const unsigned*)&sk[krow + 16 + 2 * tig];
        unsigned b11 = *(const unsigned*)&sk[krow + 16 + 2 * tig + 8];
        MMA_F16(c0, c1, c2, c3, qa[0][0], qa[0][1], qa[0][2], qa[0][3], b00, b01);
        MMA_F16(c0, c1, c2, c3, qa[1][0], qa[1][1], qa[1][2], qa[1][3], b10, b11);
        if (kh) {
            const int jj = j0 + 2 * tig;
            if (jj >= 181 && jj < 230 && ((pm >> (jj - 181)) & 1ull)) { c0 -= 100.f; c2 -= 100.f; }
            if (jj + 1 >= 181 && jj + 1 < 230 && ((pm >> (jj - 180)) & 1ull)) { c1 -= 100.f; c3 -= 100.f; }
        }
        S[t][0] = c0; S[t][1] = c1; S[t][2] = c2; S[t][3] = c3;
    }

    float m0 = -1e30f, m1 = -1e30f;
#pragma unroll
    for (int t = 0; t < 16; t++) {
        m0 = fmaxf(m0, fmaxf(S[t][0], S[t][1]));
        m1 = fmaxf(m1, fmaxf(S[t][2], S[t][3]));
    }
    m0 = fmaxf(m0, __shfl_xor_sync(0xffffffffu, m0, 1));
    m0 = fmaxf(m0, __shfl_xor_sync(0xffffffffu, m0, 2));
    m1 = fmaxf(m1, __shfl_xor_sync(0xffffffffu, m1, 1));
    m1 = fmaxf(m1, __shfl_xor_sync(0xffffffffu, m1, 2));
    if (tig == 0) {
        sred[(kh << 6) + q0 + gid]     = m0;
        sred[(kh << 6) + q0 + gid + 8] = m1;
    }
    __syncthreads();
    m0 = fmaxf(m0, sred[((kh ^ 1) << 6) + q0 + gid]);
    m1 = fmaxf(m1, sred[((kh ^ 1) << 6) + q0 + gid + 8]);

    float s0 = 0.f, s1 = 0.f;
#pragma unroll
    for (int t = 0; t < 16; t++) {
        S[t][0] = fast_exp(S[t][0] - m0); s0 += S[t][0];
        S[t][1] = fast_exp(S[t][1] - m0); s0 += S[t][1];
        S[t][2] = fast_exp(S[t][2] - m1); s1 += S[t][2];
        S[t][3] = fast_exp(S[t][3] - m1); s1 += S[t][3];
    }
    s0 += __shfl_xor_sync(0xffffffffu, s0, 1);
    s0 += __shfl_xor_sync(0xffffffffu, s0, 2);
    s1 += __shfl_xor_sync(0xffffffffu, s1, 1);
    s1 += __shfl_xor_sync(0xffffffffu, s1, 2);
    if (tig == 0) {
        sred[128 + (kh << 6) + q0 + gid]     = s0;
        sred[128 + (kh << 6) + q0 + gid + 8] = s1;
    }
    __syncthreads();
    s0 += sred[128 + ((kh ^ 1) << 6) + q0 + gid];
    s1 += sred[128 + ((kh ^ 1) << 6) + q0 + gid + 8];
    const float inv0 = 1.f / s0, inv1 = 1.f / s1;

    float O[4][4] = {};
#pragma unroll
    for (int kc = 0; kc < 8; kc++) {
        const int t0 = kc << 1;
        unsigned a0 = pack_half2(S[t0][0] * inv0, S[t0][1] * inv0);
        unsigned a1 = pack_half2(S[t0][2] * inv1, S[t0][3] * inv1);
        unsigned a2 = pack_half2(S[t0 + 1][0] * inv0, S[t0 + 1][1] * inv0);
        unsigned a3 = pack_half2(S[t0 + 1][2] * inv1, S[t0 + 1][3] * inv1);
        const int j0 = kb + (kc << 4);
#pragma unroll
        for (int nt = 0; nt < 4; nt++) {
            const int vrow = ((nt << 3) + gid) * SVH + j0 + 2 * tig;
            unsigned b0 = *(const unsigned*)&svt[vrow];
            unsigned b1 = *(const unsigned*)&svt[vrow + 8];
            MMA_F16(O[nt][0], O[nt][1], O[nt][2], O[nt][3], a0, a1, a2, a3, b0, b1);
        }
    }

    __syncthreads();
    if (kh == 1) {
#pragma unroll
        for (int nt = 0; nt < 4; nt++) {
            const int col = (nt << 3) + (tig << 1);
            *(float2*)&sOp[(q0 + gid) * SOP_STRIDE + col]     = make_float2(O[nt][0], O[nt][1]);
            *(float2*)&sOp[(q0 + gid + 8) * SOP_STRIDE + col] = make_float2(O[nt][2], O[nt][3]);
        }
    }
    __syncthreads();
    if (kh == 0) {
        const int r0 = q0 + gid, r1 = r0 + 8;
#pragma unroll
        for (int nt = 0; nt < 4; nt++) {
            const int col = (nt << 3) + (tig << 1);
            float2 p0 = *(const float2*)&sOp[r0 * SOP_STRIDE + col];
            float2 p1 = *(const float2*)&sOp[r1 * SOP_STRIDE + col];
            const int dcol = hcol + col;
            if (r0 < WA)
                *(float2*)&g_attnout[(long)(w * WA + r0) * DIM + dcol] =
                    make_float2(O[nt][0] + p0.x, O[nt][1] + p0.y);
            if (r1 < WA)
                *(float2*)&g_attnout[(long)(w * WA + r1) * DIM + dcol] =
                    make_float2(O[nt][2] + p1.x, O[nt][3] + p1.y);
        }
    }
}

// ============================================================
// launch
// ============================================================
extern "C" void kernel_launch(void* const* d_in, const int* in_sizes, int n_in,
                              void* d_out, int out_size) {
    const float* x         = (const float*)d_in[0];
    const float* x_pooled  = (const float*)d_in[1];
    const float* qkv_w     = (const float*)d_in[2];
    const float* qkv_b     = (const float*)d_in[3];
    const float* proj_w    = (const float*)d_in[4];
    const float* proj_b    = (const float*)d_in[5];
    const float* rpb_table = (const float*)d_in[6];
    const float* rpb_nb    = (const float*)d_in[7];
    const float* rpb_win   = (const float*)d_in[8];
    float* out = (float*)d_out;

    float *p_qkv = nullptr, *p_qkvp = nullptr, *p_ao = nullptr;
    cudaGetSymbolAddress((void**)&p_qkv,  g_qkv);
    cudaGetSymbolAddress((void**)&p_qkvp, g_qkvp);
    cudaGetSymbolAddress((void**)&p_ao,   g_attnout);

    const int attn_smem = SMEM_HALVES * 2;  // 43520 B
    cudaFuncSetAttribute(attn_kernel, cudaFuncAttributeMaxDynamicSharedMemorySize, attn_smem);

    init_kernel<<<96, 256>>>(rpb_table, rpb_nb, rpb_win);

    gemm_tf32_kernel<<<dim3(100352 / 128, QKVC / 64), 256>>>(
        x, qkv_w, qkv_b, p_qkv, BATCH * HH * WWID, QKVC, DIM);

    gemm_tf32_kernel<<<dim3(2048 / 128, QKVC / 64), 256>>>(
        x_pooled, qkv_w, qkv_b, p_qkvp, BATCH * NWH * NWW, QKVC, DIM);

    attn_kernel<<<dim3(BNW, HEADS), 256, attn_smem>>>();

    gemm_tf32_kernel<<<dim3(100352 / 128, DIM / 64), 256>>>(
        p_ao, proj_w, proj_b, out, BNW * WA, DIM, DIM);
}

// round 11
// speedup vs baseline: 3.4352x; 1.3656x over previous
#include <cuda_runtime.h>
#include <cuda_fp16.h>
#include <limits.h>

// ---- problem constants ----
#define BATCH 8
#define HH    112
#define WWID  112
#define DIM   192
#define HEADS 6
#define HD    32
#define WS    7
#define WA    49
#define EXPAND 3
#define NWH   16
#define NWW   16
#define BNW   2048
#define NROLL 132
#define NK    230
#define NKP   256
#define QKVC  (3*DIM)
#define ATT_SCALE 0.17677669529663689f
#define FINE_STRIDE (HH*WWID*QKVC)
#define POOL_STRIDE (NWH*NWW*QKVC)

// smem layout (in halves)
#define SKH 40
#define SVH 264
#define SBS 264
#define SQ_OFF    0
#define SK_OFF    2560               // 64*SKH
#define SVT_OFF   12800              // SK_OFF + 256*SKH
#define SBIAS_OFF 21248              // SVT_OFF + 32*SVH
#define SRED_OFF  38144              // SBIAS_OFF + 64*SBS
#define SMEM_HALVES 38656            // SRED_OFF + 512 -> 77312 B
#define SOP_STRIDE 34

// ---- scratch ----
__device__ float  g_qkv [BATCH*HH*WWID*QKVC];
__device__ float  g_qkvp[BATCH*NWH*NWW*QKVC];
__device__ float  g_attnout[BNW*WA*DIM];
__device__ __half g_bias_h[HEADS*64*NKP];
__device__ unsigned long long g_pmask[256];
__device__ int    g_gtab[256*NKP];
__device__ int    g_qtab[256*64];

__device__ __forceinline__ float to_tf32(float x) {
    unsigned u;
    asm("cvt.rna.tf32.f32 %0, %1;" : "=r"(u) : "f"(x));
    return __uint_as_float(u);
}

__device__ __forceinline__ unsigned pack_half2(float lo, float hi) {
    __half2_raw hr = (__half2_raw)__floats2half2_rn(lo, hi);
    return ((unsigned)hr.y << 16) | (unsigned)hr.x;
}

// fast exp on fma/alu pipes. valid for x <= 0.
__device__ __forceinline__ float fast_exp(float v) {
    v = fmaxf(v, -80.f);
    float t  = v * 1.4426950408889634f;
    float tb = t + 12582912.0f;
    int   i  = __float_as_int(tb) - 0x4B400000;
    float f  = t - (tb - 12582912.0f);
    float p  = 0.0013333558f;
    p = fmaf(p, f, 0.0096181291f);
    p = fmaf(p, f, 0.0555041087f);
    p = fmaf(p, f, 0.2402265070f);
    p = fmaf(p, f, 0.6931471806f);
    p = fmaf(p, f, 1.0f);
    return __int_as_float(__float_as_int(p) + (i << 23));
}

#define MMA_TF32(c0,c1,c2,c3,a0,a1,a2,a3,b0,b1)                              \
    asm volatile("mma.sync.aligned.m16n8k8.row.col.f32.tf32.tf32.f32 "       \
        "{%0,%1,%2,%3},{%4,%5,%6,%7},{%8,%9},{%0,%1,%2,%3};"                 \
        : "+f"(c0), "+f"(c1), "+f"(c2), "+f"(c3)                             \
        : "r"(a0), "r"(a1), "r"(a2), "r"(a3), "r"(b0), "r"(b1))

#define MMA_F16(c0,c1,c2,c3,a0,a1,a2,a3,b0,b1)                               \
    asm volatile("mma.sync.aligned.m16n8k16.row.col.f32.f16.f16.f32 "        \
        "{%0,%1,%2,%3},{%4,%5,%6,%7},{%8,%9},{%0,%1,%2,%3};"                 \
        : "+f"(c0), "+f"(c1), "+f"(c2), "+f"(c3)                             \
        : "r"(a0), "r"(a1), "r"(a2), "r"(a3), "r"(b0), "r"(b1))

// ============================================================
// init: fp16 bias table + gather tables + pooled masks
// ============================================================
__global__ void init_kernel(const float* __restrict__ rpb_table,
                            const float* __restrict__ rpb_nb,
                            const float* __restrict__ rpb_win) {
    for (int i = blockIdx.x * blockDim.x + threadIdx.x;
         i < HEADS * 64 * NKP; i += gridDim.x * blockDim.x) {
        int j   = i % NKP;
        int row = (i / NKP) & 63;
        int h   = i / (NKP * 64);
        float v;
        if (j >= NK)        v = -60000.f;
        else if (row >= WA) v = 0.f;
        else {
            int rq = row / 7, cq = row - rq * 7;
            if (j < WA) {
                int rk = j / 7, ck = j - rk * 7;
                v = rpb_table[((rq - rk + 6) * 13 + (cq - ck + 6)) * HEADS + h];
            } else if (j < WA + NROLL) {
                v = rpb_nb[(h * WA + row) * NROLL + (j - WA)];
            } else {
                int jp = j - WA - NROLL;
                int rk = jp / 7, ck = jp - rk * 7;
                v = rpb_win[h * 169 + (rq - rk + 6) * 13 + (cq - ck + 6)];
            }
        }
        g_bias_h[i] = __float2half(v);
    }
    if (blockIdx.x == 0 && threadIdx.x < 256) {
        int wl = threadIdx.x;
        int wi = wl >> 4, wj = wl & 15;
        int y0 = wi * WS, x0 = wj * WS;
        for (int j = 0; j < WA; j++) {
            int r = j / 7, c = j - r * 7;
            g_gtab[wl * NKP + j] = ((y0 + r) * WWID + (x0 + c)) * QKVC;
        }
        int n = WA;
        for (int s = 0; s < 4; s++)
            for (int r = 0; r < 7; r++)
                for (int c = 0; c < 7; c++) {
                    bool inval;
                    if      (s == 0) inval = (r < 4 && c < 4);
                    else if (s == 1) inval = (r < 4 && c >= 3);
                    else if (s == 2) inval = (r >= 3 && c < 4);
                    else             inval = (r >= 3 && c >= 3);
                    if (inval) continue;
                    int dy = (s < 2) ? EXPAND : -EXPAND;
                    int dx = ((s & 1) == 0) ? EXPAND : -EXPAND;
                    int y = (y0 + r + dy + HH) % HH;
                    int x = (x0 + c + dx + WWID) % WWID;
                    g_gtab[wl * NKP + n++] = (y * WWID + x) * QKVC;
                }
        for (int jp = 0; jp < WA; jp++) {
            int r = jp / 7, c = jp - r * 7;
            int py = wi + r - EXPAND, px = wj + c - EXPAND;
            g_gtab[wl * NKP + 181 + jp] =
                (py >= 0 && py < NWH && px >= 0 && px < NWW)
                ? ~((py * NWW + px) * QKVC) : INT_MIN;
        }
        for (int j = NK; j < NKP; j++) g_gtab[wl * NKP + j] = INT_MIN;
        for (int r = 0; r < 64; r++) {
            if (r < WA) {
                int rr = r / 7, cc = r - rr * 7;
                g_qtab[wl * 64 + r] = ((y0 + rr) * WWID + (x0 + cc)) * QKVC;
            } else {
                g_qtab[wl * 64 + r] = INT_MIN;
            }
        }
        unsigned long long m = 0ull;
        for (int s = 0; s < WA; s++) {
            int rk = s / 7, ck = s - rk * 7;
            int py = wi + rk - EXPAND, px = wj + ck - EXPAND;
            if (py < 0 || py >= NWH || px < 0 || px >= NWW) m |= (1ull << s);
        }
        g_pmask[wl] = m;
    }
}

// ============================================================
// tf32 tensor-core GEMM, double-buffered (validated in R9)
// ============================================================
__global__ __launch_bounds__(256)
void gemm_tf32_kernel(const float* __restrict__ A, const float* __restrict__ Bw,
                      const float* __restrict__ bias, float* __restrict__ C,
                      int M, int N, int K) {
    __shared__ float As[2][16][136];
    __shared__ float Bs[2][16][72];
    const int tid = threadIdx.x;
    const int m0 = blockIdx.x << 7;
    const int n0 = blockIdx.y << 6;
    const int ar = tid >> 1, ac = (tid & 1) << 3;
    const int br = tid >> 2, bc = (tid & 3) << 2;
    const int wp = tid >> 5, lane = tid & 31;
    const int gid = lane >> 2, tig = lane & 3;
    const int wm = (wp >> 1) << 5;
    const int wn = (wp & 1) << 5;

    const float* Aptr = A + (long)(m0 + ar) * K + ac;
    const float* Bptr = Bw + (long)(n0 + br) * K + bc;

    float acc[2][4][4] = {};

    {
        float4 a0 = *(const float4*)(Aptr);
        float4 a1 = *(const float4*)(Aptr + 4);
        float4 bv = *(const float4*)(Bptr);
        As[0][ac + 0][ar] = to_tf32(a0.x); As[0][ac + 1][ar] = to_tf32(a0.y);
        As[0][ac + 2][ar] = to_tf32(a0.z); As[0][ac + 3][ar] = to_tf32(a0.w);
        As[0][ac + 4][ar] = to_tf32(a1.x); As[0][ac + 5][ar] = to_tf32(a1.y);
        As[0][ac + 6][ar] = to_tf32(a1.z); As[0][ac + 7][ar] = to_tf32(a1.w);
        Bs[0][bc + 0][br] = to_tf32(bv.x); Bs[0][bc + 1][br] = to_tf32(bv.y);
        Bs[0][bc + 2][br] = to_tf32(bv.z); Bs[0][bc + 3][br] = to_tf32(bv.w);
    }
    __syncthreads();

    int cur = 0;
    for (int k0 = 0; k0 < K; k0 += 16) {
        const bool has_next = (k0 + 16) < K;
        float4 na0, na1, nbv;
        if (has_next) {
            na0 = *(const float4*)(Aptr + k0 + 16);
            na1 = *(const float4*)(Aptr + k0 + 20);
            nbv = *(const float4*)(Bptr + k0 + 16);
        }
#pragma unroll
        for (int ks = 0; ks < 2; ks++) {
            const int kk = ks << 3;
            unsigned afr[2][4], bfr[4][2];
#pragma unroll
            for (int mt = 0; mt < 2; mt++) {
                const int mb = wm + (mt << 4);
                afr[mt][0] = __float_as_uint(As[cur][kk + tig][mb + gid]);
                afr[mt][1] = __float_as_uint(As[cur][kk + tig][mb + gid + 8]);
                afr[mt][2] = __float_as_uint(As[cur][kk + tig + 4][mb + gid]);
                afr[mt][3] = __float_as_uint(As[cur][kk + tig + 4][mb + gid + 8]);
            }
#pragma unroll
            for (int nt = 0; nt < 4; nt++) {
                const int nb = wn + (nt << 3);
                bfr[nt][0] = __float_as_uint(Bs[cur][kk + tig][nb + gid]);
                bfr[nt][1] = __float_as_uint(Bs[cur][kk + tig + 4][nb + gid]);
            }
#pragma unroll
            for (int mt = 0; mt < 2; mt++)
#pragma unroll
                for (int nt = 0; nt < 4; nt++)
                    MMA_TF32(acc[mt][nt][0], acc[mt][nt][1], acc[mt][nt][2], acc[mt][nt][3],
                             afr[mt][0], afr[mt][1], afr[mt][2], afr[mt][3],
                             bfr[nt][0], bfr[nt][1]);
        }
        if (has_next) {
            const int nxt = cur ^ 1;
            As[nxt][ac + 0][ar] = to_tf32(na0.x); As[nxt][ac + 1][ar] = to_tf32(na0.y);
            As[nxt][ac + 2][ar] = to_tf32(na0.z); As[nxt][ac + 3][ar] = to_tf32(na0.w);
            As[nxt][ac + 4][ar] = to_tf32(na1.x); As[nxt][ac + 5][ar] = to_tf32(na1.y);
            As[nxt][ac + 6][ar] = to_tf32(na1.z); As[nxt][ac + 7][ar] = to_tf32(na1.w);
            Bs[nxt][bc + 0][br] = to_tf32(nbv.x); Bs[nxt][bc + 1][br] = to_tf32(nbv.y);
            Bs[nxt][bc + 2][br] = to_tf32(nbv.z); Bs[nxt][bc + 3][br] = to_tf32(nbv.w);
            __syncthreads();
            cur = nxt;
        }
    }

#pragma unroll
    for (int mt = 0; mt < 2; mt++) {
        const int r0 = m0 + wm + (mt << 4) + gid;
#pragma unroll
        for (int nt = 0; nt < 4; nt++) {
            const int ccol = n0 + wn + (nt << 3) + (tig << 1);
            const float b0 = bias[ccol], b1 = bias[ccol + 1];
            *(float2*)(C + (long)r0 * N + ccol) =
                make_float2(acc[mt][nt][0] + b0, acc[mt][nt][1] + b1);
            *(float2*)(C + (long)(r0 + 8) * N + ccol) =
                make_float2(acc[mt][nt][2] + b0, acc[mt][nt][3] + b1);
        }
    }
}

// ============================================================
// fp16 MMA attention: 3 barriers, predicated gather, smem bias,
// single-exchange online softmax + pooled -100 mask (kh==1).
// ============================================================
__global__ __launch_bounds__(256, 2)
void attn_kernel() {
    extern __shared__ __half sh[];
    __half* sq    = sh + SQ_OFF;
    __half* sk    = sh + SK_OFF;
    __half* svt   = sh + SVT_OFF;
    __half* sbias = sh + SBIAS_OFF;
    float*  sred  = (float*)(sh + SRED_OFF);
    float*  sOp   = (float*)(sh + SK_OFF);    // aliases sk (dead after QK)

    const int tid = threadIdx.x;
    const int wp = tid >> 5, lane = tid & 31;
    const int gid = lane >> 2, tig = lane & 3;
    const int sub = lane >> 4, d2 = lane & 15;
    const int w = blockIdx.x;
    const int h = blockIdx.y;
    const int b  = w >> 8;
    const int wl = w & 255;
    const int bFine = b * FINE_STRIDE;
    const int bPool = b * POOL_STRIDE;
    const int hcol = h * HD;

    // ---- gather q (64 rows, zero-padded via table) ----
#pragma unroll
    for (int it = 0; it < 4; it++) {
        int r = (wp << 3) + (it << 1) + sub;
        int off = g_qtab[(wl << 6) + r];
        float2 qv = make_float2(0.f, 0.f);
        if (off != INT_MIN)
            qv = *(const float2*)(g_qkv + bFine + off + hcol + 2 * d2);
        *(unsigned*)&sq[r * SKH + 2 * d2] = pack_half2(qv.x * ATT_SCALE, qv.y * ATT_SCALE);
    }
    // ---- gather k / v (256 keys, predicated, 2 keys/warp/iter) ----
#pragma unroll 4
    for (int it = 0; it < 16; it++) {
        int j = (it << 4) + (wp << 1) + sub;
        int off = g_gtab[(wl << 8) + j];
        float2 kk = make_float2(0.f, 0.f), vv = make_float2(0.f, 0.f);
        if (off != INT_MIN) {
            const float* base = (off >= 0) ? (g_qkv + bFine + off)
                                           : (g_qkvp + bPool + ~off);
            kk = *(const float2*)(base + DIM + hcol + 2 * d2);
            vv = *(const float2*)(base + 2 * DIM + hcol + 2 * d2);
        }
        *(unsigned*)&sk[j * SKH + 2 * d2] = pack_half2(kk.x, kk.y);
        svt[(2 * d2) * SVH + j]     = __float2half(vv.x);
        svt[(2 * d2 + 1) * SVH + j] = __float2half(vv.y);
    }
    // ---- stage this head's bias slab into smem (fp16) ----
    {
        const __half* src = &g_bias_h[(h << 6) * NKP];
#pragma unroll
        for (int i = tid; i < 64 * 32; i += 256) {
            int row = i >> 5, ch = (i & 31) << 3;
            *(uint4*)&sbias[row * SBS + ch] = *(const uint4*)&src[(row << 8) + ch];
        }
    }
    __syncthreads();   // barrier 1

    // ---- QK^T: warp -> 16 q-rows x 128 keys, bias from smem ----
    const int q0 = (wp & 3) << 4;
    const int kh = wp >> 2;
    const int kb = kh << 7;
    unsigned qa[2][4];
#pragma unroll
    for (int ks = 0; ks < 2; ks++) {
        const int ra = (q0 + gid) * SKH + (ks << 4);
        const int rb = ra + (SKH << 3);
        qa[ks][0] = *(const unsigned*)&sq[ra + 2 * tig];
        qa[ks][1] = *(const unsigned*)&sq[rb + 2 * tig];
        qa[ks][2] = *(const unsigned*)&sq[ra + 2 * tig + 8];
        qa[ks][3] = *(const unsigned*)&sq[rb + 2 * tig + 8];
    }

    float S[16][4];
    const unsigned long long pm = g_pmask[wl];
    const __half* bq0 = &sbias[(q0 + gid) * SBS + kb + 2 * tig];
    const __half* bq1 = bq0 + (SBS << 3);

#pragma unroll
    for (int t = 0; t < 16; t++) {
        const int j0 = kb + (t << 3);
        float2 bL0 = __half22float2(*(const __half2*)(bq0 + (t << 3)));
        float2 bL1 = __half22float2(*(const __half2*)(bq1 + (t << 3)));
        float c0 = bL0.x, c1 = bL0.y, c2 = bL1.x, c3 = bL1.y;
        const int krow = (j0 + gid) * SKH;
        unsigned b00 = *(const unsigned*)&sk[krow + 2 * tig];
        unsigned b01 = *(const unsigned*)&sk[krow + 2 * tig + 8];
        unsigned b10 = *(const unsigned*)&sk[krow + 16 + 2 * tig];
        unsigned b11 = *(const unsigned*)&sk[krow + 16 + 2 * tig + 8];
        MMA_F16(c0, c1, c2, c3, qa[0][0], qa[0][1], qa[0][2], qa[0][3], b00, b01);
        MMA_F16(c0, c1, c2, c3, qa[1][0], qa[1][1], qa[1][2], qa[1][3], b10, b11);
        if (kh) {   // pooled-boundary -100 mask (keys 181..229)
            const int jj = j0 + 2 * tig;
            if (jj >= 181 && jj < 230 && ((pm >> (jj - 181)) & 1ull)) { c0 -= 100.f; c2 -= 100.f; }
            if (jj + 1 >= 181 && jj + 1 < 230 && ((pm >> (jj - 180)) & 1ull)) { c1 -= 100.f; c3 -= 100.f; }
        }
        S[t][0] = c0; S[t][1] = c1; S[t][2] = c2; S[t][3] = c3;
    }

    // ---- online softmax: local max/exp/sum, ONE exchange barrier ----
    float m0 = -1e30f, m1 = -1e30f;
#pragma unroll
    for (int t = 0; t < 16; t++) {
        m0 = fmaxf(m0, fmaxf(S[t][0], S[t][1]));
        m1 = fmaxf(m1, fmaxf(S[t][2], S[t][3]));
    }
    m0 = fmaxf(m0, __shfl_xor_sync(0xffffffffu, m0, 1));
    m0 = fmaxf(m0, __shfl_xor_sync(0xffffffffu, m0, 2));
    m1 = fmaxf(m1, __shfl_xor_sync(0xffffffffu, m1, 1));
    m1 = fmaxf(m1, __shfl_xor_sync(0xffffffffu, m1, 2));

    float s0 = 0.f, s1 = 0.f;
#pragma unroll
    for (int t = 0; t < 16; t++) {
        S[t][0] = fast_exp(S[t][0] - m0); s0 += S[t][0];
        S[t][1] = fast_exp(S[t][1] - m0); s0 += S[t][1];
        S[t][2] = fast_exp(S[t][2] - m1); s1 += S[t][2];
        S[t][3] = fast_exp(S[t][3] - m1); s1 += S[t][3];
    }
    s0 += __shfl_xor_sync(0xffffffffu, s0, 1);
    s0 += __shfl_xor_sync(0xffffffffu, s0, 2);
    s1 += __shfl_xor_sync(0xffffffffu, s1, 1);
    s1 += __shfl_xor_sync(0xffffffffu, s1, 2);

    if (tig == 0) {
        sred[(kh << 6) + q0 + gid]           = m0;
        sred[(kh << 6) + q0 + gid + 8]       = m1;
        sred[128 + (kh << 6) + q0 + gid]     = s0;
        sred[128 + (kh << 6) + q0 + gid + 8] = s1;
    }
    __syncthreads();   // barrier 2
    {
        float mo0 = sred[((kh ^ 1) << 6) + q0 + gid];
        float mo1 = sred[((kh ^ 1) << 6) + q0 + gid + 8];
        float so0 = sred[128 + ((kh ^ 1) << 6) + q0 + gid];
        float so1 = sred[128 + ((kh ^ 1) << 6) + q0 + gid + 8];
        float M0 = fmaxf(m0, mo0), M1 = fmaxf(m1, mo1);
        float sc0 = fast_exp(m0 - M0), sc1 = fast_exp(m1 - M1);
        float den0 = s0 * sc0 + so0 * fast_exp(mo0 - M0);
        float den1 = s1 * sc1 + so1 * fast_exp(mo1 - M1);
        m0 = sc0 / den0;
        m1 = sc1 / den1;
    }

    // ---- O = P @ V over this warp's 128 keys ----
    float O[4][4] = {};
#pragma unroll
    for (int kc = 0; kc < 8; kc++) {
        const int t0 = kc << 1;
        unsigned a0 = pack_half2(S[t0][0] * m0, S[t0][1] * m0);
        unsigned a1 = pack_half2(S[t0][2] * m1, S[t0][3] * m1);
        unsigned a2 = pack_half2(S[t0 + 1][0] * m0, S[t0 + 1][1] * m0);
        unsigned a3 = pack_half2(S[t0 + 1][2] * m1, S[t0 + 1][3] * m1);
        const int j0 = kb + (kc << 4);
#pragma unroll
        for (int nt = 0; nt < 4; nt++) {
            const int vrow = ((nt << 3) + gid) * SVH + j0 + 2 * tig;
            unsigned b0 = *(const unsigned*)&svt[vrow];
            unsigned b1 = *(const unsigned*)&svt[vrow + 8];
            MMA_F16(O[nt][0], O[nt][1], O[nt][2], O[nt][3], a0, a1, a2, a3, b0, b1);
        }
    }

    // ---- combine key-halves (sOp aliases sk) ----
    if (kh == 1) {
#pragma unroll
        for (int nt = 0; nt < 4; nt++) {
            const int col = (nt << 3) + (tig << 1);
            *(float2*)&sOp[(q0 + gid) * SOP_STRIDE + col]     = make_float2(O[nt][0], O[nt][1]);
            *(float2*)&sOp[(q0 + gid + 8) * SOP_STRIDE + col] = make_float2(O[nt][2], O[nt][3]);
        }
    }
    __syncthreads();   // barrier 3
    if (kh == 0) {
        const int r0 = q0 + gid, r1 = r0 + 8;
#pragma unroll
        for (int nt = 0; nt < 4; nt++) {
            const int col = (nt << 3) + (tig << 1);
            float2 p0 = *(const float2*)&sOp[r0 * SOP_STRIDE + col];
            float2 p1 = *(const float2*)&sOp[r1 * SOP_STRIDE + col];
            const int dcol = hcol + col;
            if (r0 < WA)
                *(float2*)&g_attnout[(long)(w * WA + r0) * DIM + dcol] =
                    make_float2(O[nt][0] + p0.x, O[nt][1] + p0.y);
            if (r1 < WA)
                *(float2*)&g_attnout[(long)(w * WA + r1) * DIM + dcol] =
                    make_float2(O[nt][2] + p1.x, O[nt][3] + p1.y);
        }
    }
}

// ============================================================
// launch
// ============================================================
extern "C" void kernel_launch(void* const* d_in, const int* in_sizes, int n_in,
                              void* d_out, int out_size) {
    const float* x         = (const float*)d_in[0];
    const float* x_pooled  = (const float*)d_in[1];
    const float* qkv_w     = (const float*)d_in[2];
    const float* qkv_b     = (const float*)d_in[3];
    const float* proj_w    = (const float*)d_in[4];
    const float* proj_b    = (const float*)d_in[5];
    const float* rpb_table = (const float*)d_in[6];
    const float* rpb_nb    = (const float*)d_in[7];
    const float* rpb_win   = (const float*)d_in[8];
    float* out = (float*)d_out;

    float *p_qkv = nullptr, *p_qkvp = nullptr, *p_ao = nullptr;
    cudaGetSymbolAddress((void**)&p_qkv,  g_qkv);
    cudaGetSymbolAddress((void**)&p_qkvp, g_qkvp);
    cudaGetSymbolAddress((void**)&p_ao,   g_attnout);

    const int attn_smem = SMEM_HALVES * 2;  // 77312 B
    cudaFuncSetAttribute(attn_kernel, cudaFuncAttributeMaxDynamicSharedMemorySize, attn_smem);

    init_kernel<<<96, 256>>>(rpb_table, rpb_nb, rpb_win);

    gemm_tf32_kernel<<<dim3(100352 / 128, QKVC / 64), 256>>>(
        x, qkv_w, qkv_b, p_qkv, BATCH * HH * WWID, QKVC, DIM);

    gemm_tf32_kernel<<<dim3(2048 / 128, QKVC / 64), 256>>>(
        x_pooled, qkv_w, qkv_b, p_qkvp, BATCH * NWH * NWW, QKVC, DIM);

    attn_kernel<<<dim3(BNW, HEADS), 256, attn_smem>>>();

    gemm_tf32_kernel<<<dim3(100352 / 128, DIM / 64), 256>>>(
        p_ao, proj_w, proj_b, out, BNW * WA, DIM, DIM);
}

// round 12
// speedup vs baseline: 3.7961x; 1.1051x over previous
#include <cuda_runtime.h>
#include <cuda_fp16.h>
#include <limits.h>

// ---- problem constants ----
#define BATCH 8
#define HH    112
#define WWID  112
#define DIM   192
#define HEADS 6
#define HD    32
#define WS    7
#define WA    49
#define EXPAND 3
#define NWH   16
#define NWW   16
#define BNW   2048
#define NROLL 132
#define NK    230
#define NKP   256
#define QKVC  (3*DIM)
#define ATT_SCALE 0.17677669529663689f
#define FINE_STRIDE (HH*WWID*QKVC)
#define POOL_STRIDE (NWH*NWW*QKVC)

// attention smem layout (in halves)
#define SKH 40
#define SVH 264
#define SBS 264
#define SQ_OFF    0
#define SK_OFF    2560               // 64*SKH
#define SVT_OFF   12800              // SK_OFF + 256*SKH
#define SBIAS_OFF 21248              // SVT_OFF + 32*SVH
#define SRED_OFF  38144              // SBIAS_OFF + 64*SBS
#define SMEM_HALVES 38656            // SRED_OFF + 512 -> 77312 B
#define SOP_STRIDE 34

// GEMM fp16 tile strides (halves)
#define GAS 24                       // A row stride: bank = (12*gid+tig)%32, perfect perm
#define GBS 24

// ---- scratch ----
__device__ float  g_qkv [BATCH*HH*WWID*QKVC];
__device__ float  g_qkvp[BATCH*NWH*NWW*QKVC];
__device__ float  g_attnout[BNW*WA*DIM];
__device__ __half g_bias_h[HEADS*64*NKP];
__device__ unsigned long long g_pmask[256];
__device__ int    g_gtab[256*NKP];
__device__ int    g_qtab[256*64];

__device__ __forceinline__ unsigned pack_half2(float lo, float hi) {
    __half2_raw hr = (__half2_raw)__floats2half2_rn(lo, hi);
    return ((unsigned)hr.y << 16) | (unsigned)hr.x;
}

// fast exp on fma/alu pipes. valid for x <= 0.
__device__ __forceinline__ float fast_exp(float v) {
    v = fmaxf(v, -80.f);
    float t  = v * 1.4426950408889634f;
    float tb = t + 12582912.0f;
    int   i  = __float_as_int(tb) - 0x4B400000;
    float f  = t - (tb - 12582912.0f);
    float p  = 0.0013333558f;
    p = fmaf(p, f, 0.0096181291f);
    p = fmaf(p, f, 0.0555041087f);
    p = fmaf(p, f, 0.2402265070f);
    p = fmaf(p, f, 0.6931471806f);
    p = fmaf(p, f, 1.0f);
    return __int_as_float(__float_as_int(p) + (i << 23));
}

#define MMA_F16(c0,c1,c2,c3,a0,a1,a2,a3,b0,b1)                               \
    asm volatile("mma.sync.aligned.m16n8k16.row.col.f32.f16.f16.f32 "        \
        "{%0,%1,%2,%3},{%4,%5,%6,%7},{%8,%9},{%0,%1,%2,%3};"                 \
        : "+f"(c0), "+f"(c1), "+f"(c2), "+f"(c3)                             \
        : "r"(a0), "r"(a1), "r"(a2), "r"(a3), "r"(b0), "r"(b1))

// ============================================================
// init: fp16 bias table + gather tables + pooled masks
// ============================================================
__global__ void init_kernel(const float* __restrict__ rpb_table,
                            const float* __restrict__ rpb_nb,
                            const float* __restrict__ rpb_win) {
    for (int i = blockIdx.x * blockDim.x + threadIdx.x;
         i < HEADS * 64 * NKP; i += gridDim.x * blockDim.x) {
        int j   = i % NKP;
        int row = (i / NKP) & 63;
        int h   = i / (NKP * 64);
        float v;
        if (j >= NK)        v = -60000.f;
        else if (row >= WA) v = 0.f;
        else {
            int rq = row / 7, cq = row - rq * 7;
            if (j < WA) {
                int rk = j / 7, ck = j - rk * 7;
                v = rpb_table[((rq - rk + 6) * 13 + (cq - ck + 6)) * HEADS + h];
            } else if (j < WA + NROLL) {
                v = rpb_nb[(h * WA + row) * NROLL + (j - WA)];
            } else {
                int jp = j - WA - NROLL;
                int rk = jp / 7, ck = jp - rk * 7;
                v = rpb_win[h * 169 + (rq - rk + 6) * 13 + (cq - ck + 6)];
            }
        }
        g_bias_h[i] = __float2half(v);
    }
    if (blockIdx.x == 0 && threadIdx.x < 256) {
        int wl = threadIdx.x;
        int wi = wl >> 4, wj = wl & 15;
        int y0 = wi * WS, x0 = wj * WS;
        for (int j = 0; j < WA; j++) {
            int r = j / 7, c = j - r * 7;
            g_gtab[wl * NKP + j] = ((y0 + r) * WWID + (x0 + c)) * QKVC;
        }
        int n = WA;
        for (int s = 0; s < 4; s++)
            for (int r = 0; r < 7; r++)
                for (int c = 0; c < 7; c++) {
                    bool inval;
                    if      (s == 0) inval = (r < 4 && c < 4);
                    else if (s == 1) inval = (r < 4 && c >= 3);
                    else if (s == 2) inval = (r >= 3 && c < 4);
                    else             inval = (r >= 3 && c >= 3);
                    if (inval) continue;
                    int dy = (s < 2) ? EXPAND : -EXPAND;
                    int dx = ((s & 1) == 0) ? EXPAND : -EXPAND;
                    int y = (y0 + r + dy + HH) % HH;
                    int x = (x0 + c + dx + WWID) % WWID;
                    g_gtab[wl * NKP + n++] = (y * WWID + x) * QKVC;
                }
        for (int jp = 0; jp < WA; jp++) {
            int r = jp / 7, c = jp - r * 7;
            int py = wi + r - EXPAND, px = wj + c - EXPAND;
            g_gtab[wl * NKP + 181 + jp] =
                (py >= 0 && py < NWH && px >= 0 && px < NWW)
                ? ~((py * NWW + px) * QKVC) : INT_MIN;
        }
        for (int j = NK; j < NKP; j++) g_gtab[wl * NKP + j] = INT_MIN;
        for (int r = 0; r < 64; r++) {
            if (r < WA) {
                int rr = r / 7, cc = r - rr * 7;
                g_qtab[wl * 64 + r] = ((y0 + rr) * WWID + (x0 + cc)) * QKVC;
            } else {
                g_qtab[wl * 64 + r] = INT_MIN;
            }
        }
        unsigned long long m = 0ull;
        for (int s = 0; s < WA; s++) {
            int rk = s / 7, ck = s - rk * 7;
            int py = wi + rk - EXPAND, px = wj + ck - EXPAND;
            if (py < 0 || py >= NWH || px < 0 || px >= NWW) m |= (1ull << s);
        }
        g_pmask[wl] = m;
    }
}

// ============================================================
// fp16 tensor-core GEMM: C[M,N] = A[M,K]@Bw[N,K]^T + bias[N]
// block 128x64, 256 thr, warp 32x32, m16n8k16, double-buffered.
// ============================================================
__global__ __launch_bounds__(256)
void gemm_fp16_kernel(const float* __restrict__ A, const float* __restrict__ Bw,
                      const float* __restrict__ bias, float* __restrict__ C,
                      int M, int N, int K) {
    __shared__ __half As[2][128 * GAS];
    __shared__ __half Bs[2][64 * GBS];
    const int tid = threadIdx.x;
    const int m0 = blockIdx.x << 7;
    const int n0 = blockIdx.y << 6;
    const int ar = tid >> 1, ac = (tid & 1) << 3;   // A: row 0..127, k 0/8
    const int br = tid >> 2, bc = (tid & 3) << 2;   // B: row 0..63,  k 0/4/8/12
    const int wp = tid >> 5, lane = tid & 31;
    const int gid = lane >> 2, tig = lane & 3;
    const int wm = (wp >> 1) << 5;
    const int wn = (wp & 1) << 5;

    const float* Aptr = A + (long)(m0 + ar) * K + ac;
    const float* Bptr = Bw + (long)(n0 + br) * K + bc;

    float acc[2][4][4] = {};

    // stage k-tile 0
    {
        float4 a0 = *(const float4*)(Aptr);
        float4 a1 = *(const float4*)(Aptr + 4);
        float4 bv = *(const float4*)(Bptr);
        uint4 ap; ap.x = pack_half2(a0.x, a0.y); ap.y = pack_half2(a0.z, a0.w);
        ap.z = pack_half2(a1.x, a1.y); ap.w = pack_half2(a1.z, a1.w);
        *(uint4*)&As[0][ar * GAS + ac] = ap;
        uint2 bp; bp.x = pack_half2(bv.x, bv.y); bp.y = pack_half2(bv.z, bv.w);
        *(uint2*)&Bs[0][br * GBS + bc] = bp;
    }
    __syncthreads();

    int cur = 0;
    for (int k0 = 0; k0 < K; k0 += 16) {
        const bool has_next = (k0 + 16) < K;
        float4 na0, na1, nbv;
        if (has_next) {
            na0 = *(const float4*)(Aptr + k0 + 16);
            na1 = *(const float4*)(Aptr + k0 + 20);
            nbv = *(const float4*)(Bptr + k0 + 16);
        }
        // fragments
        unsigned afr[2][4], bfr[4][2];
#pragma unroll
        for (int mt = 0; mt < 2; mt++) {
            const int r = (wm + (mt << 4) + gid) * GAS + 2 * tig;
            afr[mt][0] = *(const unsigned*)&As[cur][r];
            afr[mt][1] = *(const unsigned*)&As[cur][r + (GAS << 3)];
            afr[mt][2] = *(const unsigned*)&As[cur][r + 8];
            afr[mt][3] = *(const unsigned*)&As[cur][r + (GAS << 3) + 8];
        }
#pragma unroll
        for (int nt = 0; nt < 4; nt++) {
            const int r = (wn + (nt << 3) + gid) * GBS + 2 * tig;
            bfr[nt][0] = *(const unsigned*)&Bs[cur][r];
            bfr[nt][1] = *(const unsigned*)&Bs[cur][r + 8];
        }
#pragma unroll
        for (int mt = 0; mt < 2; mt++)
#pragma unroll
            for (int nt = 0; nt < 4; nt++)
                MMA_F16(acc[mt][nt][0], acc[mt][nt][1], acc[mt][nt][2], acc[mt][nt][3],
                        afr[mt][0], afr[mt][1], afr[mt][2], afr[mt][3],
                        bfr[nt][0], bfr[nt][1]);

        if (has_next) {
            const int nxt = cur ^ 1;
            uint4 ap; ap.x = pack_half2(na0.x, na0.y); ap.y = pack_half2(na0.z, na0.w);
            ap.z = pack_half2(na1.x, na1.y); ap.w = pack_half2(na1.z, na1.w);
            *(uint4*)&As[nxt][ar * GAS + ac] = ap;
            uint2 bp; bp.x = pack_half2(nbv.x, nbv.y); bp.y = pack_half2(nbv.z, nbv.w);
            *(uint2*)&Bs[nxt][br * GBS + bc] = bp;
            __syncthreads();
            cur = nxt;
        }
    }

#pragma unroll
    for (int mt = 0; mt < 2; mt++) {
        const int r0 = m0 + wm + (mt << 4) + gid;
#pragma unroll
        for (int nt = 0; nt < 4; nt++) {
            const int ccol = n0 + wn + (nt << 3) + (tig << 1);
            const float b0 = bias[ccol], b1 = bias[ccol + 1];
            *(float2*)(C + (long)r0 * N + ccol) =
                make_float2(acc[mt][nt][0] + b0, acc[mt][nt][1] + b1);
            *(float2*)(C + (long)(r0 + 8) * N + ccol) =
                make_float2(acc[mt][nt][2] + b0, acc[mt][nt][3] + b1);
        }
    }
}

// ============================================================
// fp16 MMA attention (identical to R11, passed)
// ============================================================
__global__ __launch_bounds__(256, 2)
void attn_kernel() {
    extern __shared__ __half sh[];
    __half* sq    = sh + SQ_OFF;
    __half* sk    = sh + SK_OFF;
    __half* svt   = sh + SVT_OFF;
    __half* sbias = sh + SBIAS_OFF;
    float*  sred  = (float*)(sh + SRED_OFF);
    float*  sOp   = (float*)(sh + SK_OFF);

    const int tid = threadIdx.x;
    const int wp = tid >> 5, lane = tid & 31;
    const int gid = lane >> 2, tig = lane & 3;
    const int sub = lane >> 4, d2 = lane & 15;
    const int w = blockIdx.x;
    const int h = blockIdx.y;
    const int b  = w >> 8;
    const int wl = w & 255;
    const int bFine = b * FINE_STRIDE;
    const int bPool = b * POOL_STRIDE;
    const int hcol = h * HD;

#pragma unroll
    for (int it = 0; it < 4; it++) {
        int r = (wp << 3) + (it << 1) + sub;
        int off = g_qtab[(wl << 6) + r];
        float2 qv = make_float2(0.f, 0.f);
        if (off != INT_MIN)
            qv = *(const float2*)(g_qkv + bFine + off + hcol + 2 * d2);
        *(unsigned*)&sq[r * SKH + 2 * d2] = pack_half2(qv.x * ATT_SCALE, qv.y * ATT_SCALE);
    }
#pragma unroll 4
    for (int it = 0; it < 16; it++) {
        int j = (it << 4) + (wp << 1) + sub;
        int off = g_gtab[(wl << 8) + j];
        float2 kk = make_float2(0.f, 0.f), vv = make_float2(0.f, 0.f);
        if (off != INT_MIN) {
            const float* base = (off >= 0) ? (g_qkv + bFine + off)
                                           : (g_qkvp + bPool + ~off);
            kk = *(const float2*)(base + DIM + hcol + 2 * d2);
            vv = *(const float2*)(base + 2 * DIM + hcol + 2 * d2);
        }
        *(unsigned*)&sk[j * SKH + 2 * d2] = pack_half2(kk.x, kk.y);
        svt[(2 * d2) * SVH + j]     = __float2half(vv.x);
        svt[(2 * d2 + 1) * SVH + j] = __float2half(vv.y);
    }
    {
        const __half* src = &g_bias_h[(h << 6) * NKP];
#pragma unroll
        for (int i = tid; i < 64 * 32; i += 256) {
            int row = i >> 5, ch = (i & 31) << 3;
            *(uint4*)&sbias[row * SBS + ch] = *(const uint4*)&src[(row << 8) + ch];
        }
    }
    __syncthreads();

    const int q0 = (wp & 3) << 4;
    const int kh = wp >> 2;
    const int kb = kh << 7;
    unsigned qa[2][4];
#pragma unroll
    for (int ks = 0; ks < 2; ks++) {
        const int ra = (q0 + gid) * SKH + (ks << 4);
        const int rb = ra + (SKH << 3);
        qa[ks][0] = *(const unsigned*)&sq[ra + 2 * tig];
        qa[ks][1] = *(const unsigned*)&sq[rb + 2 * tig];
        qa[ks][2] = *(const unsigned*)&sq[ra + 2 * tig + 8];
        qa[ks][3] = *(const unsigned*)&sq[rb + 2 * tig + 8];
    }

    float S[16][4];
    const unsigned long long pm = g_pmask[wl];
    const __half* bq0 = &sbias[(q0 + gid) * SBS + kb + 2 * tig];
    const __half* bq1 = bq0 + (SBS << 3);

#pragma unroll
    for (int t = 0; t < 16; t++) {
        const int j0 = kb + (t << 3);
        float2 bL0 = __half22float2(*(const __half2*)(bq0 + (t << 3)));
        float2 bL1 = __half22float2(*(const __half2*)(bq1 + (t << 3)));
        float c0 = bL0.x, c1 = bL0.y, c2 = bL1.x, c3 = bL1.y;
        const int krow = (j0 + gid) * SKH;
        unsigned b00 = *(const unsigned*)&sk[krow + 2 * tig];
        unsigned b01 = *(const unsigned*)&sk[krow + 2 * tig + 8];
        unsigned b10 = *(const unsigned*)&sk[krow + 16 + 2 * tig];
        unsigned b11 = *(const unsigned*)&sk[krow + 16 + 2 * tig + 8];
        MMA_F16(c0, c1, c2, c3, qa[0][0], qa[0][1], qa[0][2], qa[0][3], b00, b01);
        MMA_F16(c0, c1, c2, c3, qa[1][0], qa[1][1], qa[1][2], qa[1][3], b10, b11);
        if (kh) {
            const int jj = j0 + 2 * tig;
            if (jj >= 181 && jj < 230 && ((pm >> (jj - 181)) & 1ull)) { c0 -= 100.f; c2 -= 100.f; }
            if (jj + 1 >= 181 && jj + 1 < 230 && ((pm >> (jj - 180)) & 1ull)) { c1 -= 100.f; c3 -= 100.f; }
        }
        S[t][0] = c0; S[t][1] = c1; S[t][2] = c2; S[t][3] = c3;
    }

    float m0 = -1e30f, m1 = -1e30f;
#pragma unroll
    for (int t = 0; t < 16; t++) {
        m0 = fmaxf(m0, fmaxf(S[t][0], S[t][1]));
        m1 = fmaxf(m1, fmaxf(S[t][2], S[t][3]));
    }
    m0 = fmaxf(m0, __shfl_xor_sync(0xffffffffu, m0, 1));
    m0 = fmaxf(m0, __shfl_xor_sync(0xffffffffu, m0, 2));
    m1 = fmaxf(m1, __shfl_xor_sync(0xffffffffu, m1, 1));
    m1 = fmaxf(m1, __shfl_xor_sync(0xffffffffu, m1, 2));

    float s0 = 0.f, s1 = 0.f;
#pragma unroll
    for (int t = 0; t < 16; t++) {
        S[t][0] = fast_exp(S[t][0] - m0); s0 += S[t][0];
        S[t][1] = fast_exp(S[t][1] - m0); s0 += S[t][1];
        S[t][2] = fast_exp(S[t][2] - m1); s1 += S[t][2];
        S[t][3] = fast_exp(S[t][3] - m1); s1 += S[t][3];
    }
    s0 += __shfl_xor_sync(0xffffffffu, s0, 1);
    s0 += __shfl_xor_sync(0xffffffffu, s0, 2);
    s1 += __shfl_xor_sync(0xffffffffu, s1, 1);
    s1 += __shfl_xor_sync(0xffffffffu, s1, 2);

    if (tig == 0) {
        sred[(kh << 6) + q0 + gid]           = m0;
        sred[(kh << 6) + q0 + gid + 8]       = m1;
        sred[128 + (kh << 6) + q0 + gid]     = s0;
        sred[128 + (kh << 6) + q0 + gid + 8] = s1;
    }
    __syncthreads();
    {
        float mo0 = sred[((kh ^ 1) << 6) + q0 + gid];
        float mo1 = sred[((kh ^ 1) << 6) + q0 + gid + 8];
        float so0 = sred[128 + ((kh ^ 1) << 6) + q0 + gid];
        float so1 = sred[128 + ((kh ^ 1) << 6) + q0 + gid + 8];
        float M0 = fmaxf(m0, mo0), M1 = fmaxf(m1, mo1);
        float sc0 = fast_exp(m0 - M0), sc1 = fast_exp(m1 - M1);
        float den0 = s0 * sc0 + so0 * fast_exp(mo0 - M0);
        float den1 = s1 * sc1 + so1 * fast_exp(mo1 - M1);
        m0 = sc0 / den0;
        m1 = sc1 / den1;
    }

    float O[4][4] = {};
#pragma unroll
    for (int kc = 0; kc < 8; kc++) {
        const int t0 = kc << 1;
        unsigned a0 = pack_half2(S[t0][0] * m0, S[t0][1] * m0);
        unsigned a1 = pack_half2(S[t0][2] * m1, S[t0][3] * m1);
        unsigned a2 = pack_half2(S[t0 + 1][0] * m0, S[t0 + 1][1] * m0);
        unsigned a3 = pack_half2(S[t0 + 1][2] * m1, S[t0 + 1][3] * m1);
        const int j0 = kb + (kc << 4);
#pragma unroll
        for (int nt = 0; nt < 4; nt++) {
            const int vrow = ((nt << 3) + gid) * SVH + j0 + 2 * tig;
            unsigned b0 = *(const unsigned*)&svt[vrow];
            unsigned b1 = *(const unsigned*)&svt[vrow + 8];
            MMA_F16(O[nt][0], O[nt][1], O[nt][2], O[nt][3], a0, a1, a2, a3, b0, b1);
        }
    }

    if (kh == 1) {
#pragma unroll
        for (int nt = 0; nt < 4; nt++) {
            const int col = (nt << 3) + (tig << 1);
            *(float2*)&sOp[(q0 + gid) * SOP_STRIDE + col]     = make_float2(O[nt][0], O[nt][1]);
            *(float2*)&sOp[(q0 + gid + 8) * SOP_STRIDE + col] = make_float2(O[nt][2], O[nt][3]);
        }
    }
    __syncthreads();
    if (kh == 0) {
        const int r0 = q0 + gid, r1 = r0 + 8;
#pragma unroll
        for (int nt = 0; nt < 4; nt++) {
            const int col = (nt << 3) + (tig << 1);
            float2 p0 = *(const float2*)&sOp[r0 * SOP_STRIDE + col];
            float2 p1 = *(const float2*)&sOp[r1 * SOP_STRIDE + col];
            const int dcol = hcol + col;
            if (r0 < WA)
                *(float2*)&g_attnout[(long)(w * WA + r0) * DIM + dcol] =
                    make_float2(O[nt][0] + p0.x, O[nt][1] + p0.y);
            if (r1 < WA)
                *(float2*)&g_attnout[(long)(w * WA + r1) * DIM + dcol] =
                    make_float2(O[nt][2] + p1.x, O[nt][3] + p1.y);
        }
    }
}

// ============================================================
// launch
// ============================================================
extern "C" void kernel_launch(void* const* d_in, const int* in_sizes, int n_in,
                              void* d_out, int out_size) {
    const float* x         = (const float*)d_in[0];
    const float* x_pooled  = (const float*)d_in[1];
    const float* qkv_w     = (const float*)d_in[2];
    const float* qkv_b     = (const float*)d_in[3];
    const float* proj_w    = (const float*)d_in[4];
    const float* proj_b    = (const float*)d_in[5];
    const float* rpb_table = (const float*)d_in[6];
    const float* rpb_nb    = (const float*)d_in[7];
    const float* rpb_win   = (const float*)d_in[8];
    float* out = (float*)d_out;

    float *p_qkv = nullptr, *p_qkvp = nullptr, *p_ao = nullptr;
    cudaGetSymbolAddress((void**)&p_qkv,  g_qkv);
    cudaGetSymbolAddress((void**)&p_qkvp, g_qkvp);
    cudaGetSymbolAddress((void**)&p_ao,   g_attnout);

    const int attn_smem = SMEM_HALVES * 2;  // 77312 B
    cudaFuncSetAttribute(attn_kernel, cudaFuncAttributeMaxDynamicSharedMemorySize, attn_smem);

    init_kernel<<<96, 256>>>(rpb_table, rpb_nb, rpb_win);

    gemm_fp16_kernel<<<dim3(100352 / 128, QKVC / 64), 256>>>(
        x, qkv_w, qkv_b, p_qkv, BATCH * HH * WWID, QKVC, DIM);

    gemm_fp16_kernel<<<dim3(2048 / 128, QKVC / 64), 256>>>(
        x_pooled, qkv_w, qkv_b, p_qkvp, BATCH * NWH * NWW, QKVC, DIM);

    attn_kernel<<<dim3(BNW, HEADS), 256, attn_smem>>>();

    gemm_fp16_kernel<<<dim3(100352 / 128, DIM / 64), 256>>>(
        p_ao, proj_w, proj_b, out, BNW * WA, DIM, DIM);
}

// round 13
// speedup vs baseline: 3.9311x; 1.0356x over previous
#include <cuda_runtime.h>
#include <cuda_fp16.h>
#include <limits.h>

// ---- problem constants ----
#define BATCH 8
#define HH    112
#define WWID  112
#define DIM   192
#define HEADS 6
#define HD    32
#define WS    7
#define WA    49
#define EXPAND 3
#define NWH   16
#define NWW   16
#define BNW   2048
#define NROLL 132
#define NK    230
#define NKP   256
#define QKVC  (3*DIM)
#define ATT_SCALE 0.17677669529663689f
#define FINE_STRIDE (HH*WWID*QKVC)
#define POOL_STRIDE (NWH*NWW*QKVC)

// attention smem layout (in halves)
#define SKH 40
#define SVH 264
#define SBS 264
#define SQ_OFF    0
#define SK_OFF    2560               // 64*SKH
#define SVT_OFF   12800              // SK_OFF + 256*SKH
#define SBIAS_OFF 21248              // SVT_OFF + 32*SVH
#define SRED_OFF  38144              // SBIAS_OFF + 64*SBS
#define SMEM_HALVES 38656            // SRED_OFF + 512 -> 77312 B
#define SOP_STRIDE 34

// GEMM fp16 tile strides (halves)
#define GAS 24
#define GBS 24

// ---- scratch ----
__device__ float  g_qkv [BATCH*HH*WWID*QKVC];
__device__ float  g_qkvp[BATCH*NWH*NWW*QKVC];
__device__ float  g_attnout[BNW*WA*DIM];
__device__ __half g_bias_h[HEADS*64*NKP];
__device__ unsigned long long g_pmask[256];
__device__ int    g_gtab[256*NKP];
__device__ int    g_qtab[256*64];

__device__ __forceinline__ unsigned pack_half2(float lo, float hi) {
    __half2_raw hr = (__half2_raw)__floats2half2_rn(lo, hi);
    return ((unsigned)hr.y << 16) | (unsigned)hr.x;
}

__device__ __forceinline__ unsigned smem_u32(const void* p) {
    return (unsigned)__cvta_generic_to_shared(p);
}

// fast exp on fma/alu pipes. valid for x <= 0.
__device__ __forceinline__ float fast_exp(float v) {
    v = fmaxf(v, -80.f);
    float t  = v * 1.4426950408889634f;
    float tb = t + 12582912.0f;
    int   i  = __float_as_int(tb) - 0x4B400000;
    float f  = t - (tb - 12582912.0f);
    float p  = 0.0013333558f;
    p = fmaf(p, f, 0.0096181291f);
    p = fmaf(p, f, 0.0555041087f);
    p = fmaf(p, f, 0.2402265070f);
    p = fmaf(p, f, 0.6931471806f);
    p = fmaf(p, f, 1.0f);
    return __int_as_float(__float_as_int(p) + (i << 23));
}

#define MMA_F16(c0,c1,c2,c3,a0,a1,a2,a3,b0,b1)                               \
    asm volatile("mma.sync.aligned.m16n8k16.row.col.f32.f16.f16.f32 "        \
        "{%0,%1,%2,%3},{%4,%5,%6,%7},{%8,%9},{%0,%1,%2,%3};"                 \
        : "+f"(c0), "+f"(c1), "+f"(c2), "+f"(c3)                             \
        : "r"(a0), "r"(a1), "r"(a2), "r"(a3), "r"(b0), "r"(b1))

#define LDMATRIX_X4(r0,r1,r2,r3,addr)                                        \
    asm volatile("ldmatrix.sync.aligned.m8n8.x4.shared.b16 {%0,%1,%2,%3}, [%4];" \
        : "=r"(r0), "=r"(r1), "=r"(r2), "=r"(r3) : "r"(addr))

// ============================================================
// init: fp16 bias table + gather tables + pooled masks
// ============================================================
__global__ void init_kernel(const float* __restrict__ rpb_table,
                            const float* __restrict__ rpb_nb,
                            const float* __restrict__ rpb_win) {
    for (int i = blockIdx.x * blockDim.x + threadIdx.x;
         i < HEADS * 64 * NKP; i += gridDim.x * blockDim.x) {
        int j   = i % NKP;
        int row = (i / NKP) & 63;
        int h   = i / (NKP * 64);
        float v;
        if (j >= NK)        v = -60000.f;
        else if (row >= WA) v = 0.f;
        else {
            int rq = row / 7, cq = row - rq * 7;
            if (j < WA) {
                int rk = j / 7, ck = j - rk * 7;
                v = rpb_table[((rq - rk + 6) * 13 + (cq - ck + 6)) * HEADS + h];
            } else if (j < WA + NROLL) {
                v = rpb_nb[(h * WA + row) * NROLL + (j - WA)];
            } else {
                int jp = j - WA - NROLL;
                int rk = jp / 7, ck = jp - rk * 7;
                v = rpb_win[h * 169 + (rq - rk + 6) * 13 + (cq - ck + 6)];
            }
        }
        g_bias_h[i] = __float2half(v);
    }
    if (blockIdx.x == 0 && threadIdx.x < 256) {
        int wl = threadIdx.x;
        int wi = wl >> 4, wj = wl & 15;
        int y0 = wi * WS, x0 = wj * WS;
        for (int j = 0; j < WA; j++) {
            int r = j / 7, c = j - r * 7;
            g_gtab[wl * NKP + j] = ((y0 + r) * WWID + (x0 + c)) * QKVC;
        }
        int n = WA;
        for (int s = 0; s < 4; s++)
            for (int r = 0; r < 7; r++)
                for (int c = 0; c < 7; c++) {
                    bool inval;
                    if      (s == 0) inval = (r < 4 && c < 4);
                    else if (s == 1) inval = (r < 4 && c >= 3);
                    else if (s == 2) inval = (r >= 3 && c < 4);
                    else             inval = (r >= 3 && c >= 3);
                    if (inval) continue;
                    int dy = (s < 2) ? EXPAND : -EXPAND;
                    int dx = ((s & 1) == 0) ? EXPAND : -EXPAND;
                    int y = (y0 + r + dy + HH) % HH;
                    int x = (x0 + c + dx + WWID) % WWID;
                    g_gtab[wl * NKP + n++] = (y * WWID + x) * QKVC;
                }
        for (int jp = 0; jp < WA; jp++) {
            int r = jp / 7, c = jp - r * 7;
            int py = wi + r - EXPAND, px = wj + c - EXPAND;
            g_gtab[wl * NKP + 181 + jp] =
                (py >= 0 && py < NWH && px >= 0 && px < NWW)
                ? ~((py * NWW + px) * QKVC) : INT_MIN;
        }
        for (int j = NK; j < NKP; j++) g_gtab[wl * NKP + j] = INT_MIN;
        for (int r = 0; r < 64; r++) {
            if (r < WA) {
                int rr = r / 7, cc = r - rr * 7;
                g_qtab[wl * 64 + r] = ((y0 + rr) * WWID + (x0 + cc)) * QKVC;
            } else {
                g_qtab[wl * 64 + r] = INT_MIN;
            }
        }
        unsigned long long m = 0ull;
        for (int s = 0; s < WA; s++) {
            int rk = s / 7, ck = s - rk * 7;
            int py = wi + rk - EXPAND, px = wj + ck - EXPAND;
            if (py < 0 || py >= NWH || px < 0 || px >= NWW) m |= (1ull << s);
        }
        g_pmask[wl] = m;
    }
}

// ============================================================
// fp16 tensor-core GEMM with ldmatrix.x4 fragment loads
// block 128x64, 256 thr, warp 32x32, m16n8k16, double-buffered.
// ============================================================
__global__ __launch_bounds__(256)
void gemm_fp16_kernel(const float* __restrict__ A, const float* __restrict__ Bw,
                      const float* __restrict__ bias, float* __restrict__ C,
                      int M, int N, int K) {
    __shared__ __half As[2][128 * GAS];
    __shared__ __half Bs[2][64 * GBS];
    const int tid = threadIdx.x;
    const int m0 = blockIdx.x << 7;
    const int n0 = blockIdx.y << 6;
    const int ar = tid >> 1, ac = (tid & 1) << 3;
    const int br = tid >> 2, bc = (tid & 3) << 2;
    const int wp = tid >> 5, lane = tid & 31;
    const int gid = lane >> 2, tig = lane & 3;
    const int wm = (wp >> 1) << 5;
    const int wn = (wp & 1) << 5;

    const float* Aptr = A + (long)(m0 + ar) * K + ac;
    const float* Bptr = Bw + (long)(n0 + br) * K + bc;

    // ldmatrix lane addresses (fixed per buffer)
    const int lrow = (lane & 7) + ((lane >> 3) & 1) * 8;
    const int lcol = (lane >> 4) << 3;
    unsigned aaddr[2], baddr[2];
#pragma unroll
    for (int mt = 0; mt < 2; mt++)
        aaddr[mt] = smem_u32(&As[0][(wm + (mt << 4) + lrow) * GAS + lcol]);
#pragma unroll
    for (int ntp = 0; ntp < 2; ntp++)
        baddr[ntp] = smem_u32(&Bs[0][(wn + (ntp << 4) + lrow) * GBS + lcol]);
    const unsigned ABUF = 128 * GAS * 2;
    const unsigned BBUF = 64 * GBS * 2;

    float acc[2][4][4] = {};

    {
        float4 a0 = *(const float4*)(Aptr);
        float4 a1 = *(const float4*)(Aptr + 4);
        float4 bv = *(const float4*)(Bptr);
        uint4 ap; ap.x = pack_half2(a0.x, a0.y); ap.y = pack_half2(a0.z, a0.w);
        ap.z = pack_half2(a1.x, a1.y); ap.w = pack_half2(a1.z, a1.w);
        *(uint4*)&As[0][ar * GAS + ac] = ap;
        uint2 bp; bp.x = pack_half2(bv.x, bv.y); bp.y = pack_half2(bv.z, bv.w);
        *(uint2*)&Bs[0][br * GBS + bc] = bp;
    }
    __syncthreads();

    int cur = 0;
    for (int k0 = 0; k0 < K; k0 += 16) {
        const bool has_next = (k0 + 16) < K;
        float4 na0, na1, nbv;
        if (has_next) {
            na0 = *(const float4*)(Aptr + k0 + 16);
            na1 = *(const float4*)(Aptr + k0 + 20);
            nbv = *(const float4*)(Bptr + k0 + 16);
        }
        unsigned afr[2][4];
#pragma unroll
        for (int mt = 0; mt < 2; mt++)
            LDMATRIX_X4(afr[mt][0], afr[mt][1], afr[mt][2], afr[mt][3],
                        aaddr[mt] + cur * ABUF);
#pragma unroll
        for (int ntp = 0; ntp < 2; ntp++) {
            unsigned b0a, b0b, b1a, b1b;
            LDMATRIX_X4(b0a, b0b, b1a, b1b, baddr[ntp] + cur * BBUF);
            // b0a/b1a -> n-octet (2*ntp), b0b/b1b -> n-octet (2*ntp+1)
#pragma unroll
            for (int mt = 0; mt < 2; mt++) {
                MMA_F16(acc[mt][2*ntp][0], acc[mt][2*ntp][1], acc[mt][2*ntp][2], acc[mt][2*ntp][3],
                        afr[mt][0], afr[mt][1], afr[mt][2], afr[mt][3], b0a, b1a);
                MMA_F16(acc[mt][2*ntp+1][0], acc[mt][2*ntp+1][1], acc[mt][2*ntp+1][2], acc[mt][2*ntp+1][3],
                        afr[mt][0], afr[mt][1], afr[mt][2], afr[mt][3], b0b, b1b);
            }
        }
        if (has_next) {
            const int nxt = cur ^ 1;
            uint4 ap; ap.x = pack_half2(na0.x, na0.y); ap.y = pack_half2(na0.z, na0.w);
            ap.z = pack_half2(na1.x, na1.y); ap.w = pack_half2(na1.z, na1.w);
            *(uint4*)&As[nxt][ar * GAS + ac] = ap;
            uint2 bp; bp.x = pack_half2(nbv.x, nbv.y); bp.y = pack_half2(nbv.z, nbv.w);
            *(uint2*)&Bs[nxt][br * GBS + bc] = bp;
            __syncthreads();
            cur = nxt;
        }
    }

#pragma unroll
    for (int mt = 0; mt < 2; mt++) {
        const int r0 = m0 + wm + (mt << 4) + gid;
#pragma unroll
        for (int nt = 0; nt < 4; nt++) {
            const int ccol = n0 + wn + (nt << 3) + (tig << 1);
            const float b0 = bias[ccol], b1 = bias[ccol + 1];
            *(float2*)(C + (long)r0 * N + ccol) =
                make_float2(acc[mt][nt][0] + b0, acc[mt][nt][1] + b1);
            *(float2*)(C + (long)(r0 + 8) * N + ccol) =
                make_float2(acc[mt][nt][2] + b0, acc[mt][nt][3] + b1);
        }
    }
}

// ============================================================
// fp16 MMA attention with ldmatrix.x4 for K and V fragments
// ============================================================
__global__ __launch_bounds__(256, 2)
void attn_kernel() {
    extern __shared__ __half sh[];
    __half* sq    = sh + SQ_OFF;
    __half* sk    = sh + SK_OFF;
    __half* svt   = sh + SVT_OFF;
    __half* sbias = sh + SBIAS_OFF;
    float*  sred  = (float*)(sh + SRED_OFF);
    float*  sOp   = (float*)(sh + SK_OFF);

    const int tid = threadIdx.x;
    const int wp = tid >> 5, lane = tid & 31;
    const int gid = lane >> 2, tig = lane & 3;
    const int sub = lane >> 4, d2 = lane & 15;
    const int w = blockIdx.x;
    const int h = blockIdx.y;
    const int b  = w >> 8;
    const int wl = w & 255;
    const int bFine = b * FINE_STRIDE;
    const int bPool = b * POOL_STRIDE;
    const int hcol = h * HD;

#pragma unroll
    for (int it = 0; it < 4; it++) {
        int r = (wp << 3) + (it << 1) + sub;
        int off = g_qtab[(wl << 6) + r];
        float2 qv = make_float2(0.f, 0.f);
        if (off != INT_MIN)
            qv = *(const float2*)(g_qkv + bFine + off + hcol + 2 * d2);
        *(unsigned*)&sq[r * SKH + 2 * d2] = pack_half2(qv.x * ATT_SCALE, qv.y * ATT_SCALE);
    }
#pragma unroll 4
    for (int it = 0; it < 16; it++) {
        int j = (it << 4) + (wp << 1) + sub;
        int off = g_gtab[(wl << 8) + j];
        float2 kk = make_float2(0.f, 0.f), vv = make_float2(0.f, 0.f);
        if (off != INT_MIN) {
            const float* base = (off >= 0) ? (g_qkv + bFine + off)
                                           : (g_qkvp + bPool + ~off);
            kk = *(const float2*)(base + DIM + hcol + 2 * d2);
            vv = *(const float2*)(base + 2 * DIM + hcol + 2 * d2);
        }
        *(unsigned*)&sk[j * SKH + 2 * d2] = pack_half2(kk.x, kk.y);
        svt[(2 * d2) * SVH + j]     = __float2half(vv.x);
        svt[(2 * d2 + 1) * SVH + j] = __float2half(vv.y);
    }
    {
        const __half* src = &g_bias_h[(h << 6) * NKP];
#pragma unroll
        for (int i = tid; i < 64 * 32; i += 256) {
            int row = i >> 5, ch = (i & 31) << 3;
            *(uint4*)&sbias[row * SBS + ch] = *(const uint4*)&src[(row << 8) + ch];
        }
    }
    __syncthreads();

    const int q0 = (wp & 3) << 4;
    const int kh = wp >> 2;
    const int kb = kh << 7;
    unsigned qa[2][4];
#pragma unroll
    for (int ks = 0; ks < 2; ks++) {
        const int ra = (q0 + gid) * SKH + (ks << 4);
        const int rb = ra + (SKH << 3);
        qa[ks][0] = *(const unsigned*)&sq[ra + 2 * tig];
        qa[ks][1] = *(const unsigned*)&sq[rb + 2 * tig];
        qa[ks][2] = *(const unsigned*)&sq[ra + 2 * tig + 8];
        qa[ks][3] = *(const unsigned*)&sq[rb + 2 * tig + 8];
    }

    float S[16][4];
    const unsigned long long pm = g_pmask[wl];
    const __half* bq0 = &sbias[(q0 + gid) * SBS + kb + 2 * tig];
    const __half* bq1 = bq0 + (SBS << 3);

    // ldmatrix base for K: lane -> row j0+(lane&7), k-col (lane>>3)*8
    const unsigned kaddr0 = smem_u32(&sk[(kb + (lane & 7)) * SKH + ((lane >> 3) << 3)]);

#pragma unroll
    for (int t = 0; t < 16; t++) {
        const int j0 = kb + (t << 3);
        float2 bL0 = __half22float2(*(const __half2*)(bq0 + (t << 3)));
        float2 bL1 = __half22float2(*(const __half2*)(bq1 + (t << 3)));
        float c0 = bL0.x, c1 = bL0.y, c2 = bL1.x, c3 = bL1.y;
        unsigned b00, b01, b10, b11;
        LDMATRIX_X4(b00, b01, b10, b11, kaddr0 + t * (8 * SKH * 2));
        MMA_F16(c0, c1, c2, c3, qa[0][0], qa[0][1], qa[0][2], qa[0][3], b00, b01);
        MMA_F16(c0, c1, c2, c3, qa[1][0], qa[1][1], qa[1][2], qa[1][3], b10, b11);
        if (kh) {
            const int jj = j0 + 2 * tig;
            if (jj >= 181 && jj < 230 && ((pm >> (jj - 181)) & 1ull)) { c0 -= 100.f; c2 -= 100.f; }
            if (jj + 1 >= 181 && jj + 1 < 230 && ((pm >> (jj - 180)) & 1ull)) { c1 -= 100.f; c3 -= 100.f; }
        }
        S[t][0] = c0; S[t][1] = c1; S[t][2] = c2; S[t][3] = c3;
    }

    float m0 = -1e30f, m1 = -1e30f;
#pragma unroll
    for (int t = 0; t < 16; t++) {
        m0 = fmaxf(m0, fmaxf(S[t][0], S[t][1]));
        m1 = fmaxf(m1, fmaxf(S[t][2], S[t][3]));
    }
    m0 = fmaxf(m0, __shfl_xor_sync(0xffffffffu, m0, 1));
    m0 = fmaxf(m0, __shfl_xor_sync(0xffffffffu, m0, 2));
    m1 = fmaxf(m1, __shfl_xor_sync(0xffffffffu, m1, 1));
    m1 = fmaxf(m1, __shfl_xor_sync(0xffffffffu, m1, 2));

    float s0 = 0.f, s1 = 0.f;
#pragma unroll
    for (int t = 0; t < 16; t++) {
        S[t][0] = fast_exp(S[t][0] - m0); s0 += S[t][0];
        S[t][1] = fast_exp(S[t][1] - m0); s0 += S[t][1];
        S[t][2] = fast_exp(S[t][2] - m1); s1 += S[t][2];
        S[t][3] = fast_exp(S[t][3] - m1); s1 += S[t][3];
    }
    s0 += __shfl_xor_sync(0xffffffffu, s0, 1);
    s0 += __shfl_xor_sync(0xffffffffu, s0, 2);
    s1 += __shfl_xor_sync(0xffffffffu, s1, 1);
    s1 += __shfl_xor_sync(0xffffffffu, s1, 2);

    if (tig == 0) {
        sred[(kh << 6) + q0 + gid]           = m0;
        sred[(kh << 6) + q0 + gid + 8]       = m1;
        sred[128 + (kh << 6) + q0 + gid]     = s0;
        sred[128 + (kh << 6) + q0 + gid + 8] = s1;
    }
    __syncthreads();
    {
        float mo0 = sred[((kh ^ 1) << 6) + q0 + gid];
        float mo1 = sred[((kh ^ 1) << 6) + q0 + gid + 8];
        float so0 = sred[128 + ((kh ^ 1) << 6) + q0 + gid];
        float so1 = sred[128 + ((kh ^ 1) << 6) + q0 + gid + 8];
        float M0 = fmaxf(m0, mo0), M1 = fmaxf(m1, mo1);
        float sc0 = fast_exp(m0 - M0), sc1 = fast_exp(m1 - M1);
        float den0 = s0 * sc0 + so0 * fast_exp(mo0 - M0);
        float den1 = s1 * sc1 + so1 * fast_exp(mo1 - M1);
        m0 = sc0 / den0;
        m1 = sc1 / den1;
    }

    // ---- O = P @ V with ldmatrix V fragments ----
    const int lrow16 = (lane & 7) + ((lane >> 3) & 1) * 8;
    const int ljcol = (lane >> 4) << 3;
    unsigned vaddr[2];
#pragma unroll
    for (int dh = 0; dh < 2; dh++)
        vaddr[dh] = smem_u32(&svt[((dh << 4) + lrow16) * SVH + kb + ljcol]);

    float O[4][4] = {};
#pragma unroll
    for (int kc = 0; kc < 8; kc++) {
        const int t0 = kc << 1;
        unsigned a0 = pack_half2(S[t0][0] * m0, S[t0][1] * m0);
        unsigned a1 = pack_half2(S[t0][2] * m1, S[t0][3] * m1);
        unsigned a2 = pack_half2(S[t0 + 1][0] * m0, S[t0 + 1][1] * m0);
        unsigned a3 = pack_half2(S[t0 + 1][2] * m1, S[t0 + 1][3] * m1);
#pragma unroll
        for (int dh = 0; dh < 2; dh++) {
            unsigned b0a, b0b, b1a, b1b;
            LDMATRIX_X4(b0a, b0b, b1a, b1b, vaddr[dh] + kc * 32);
            MMA_F16(O[2*dh][0], O[2*dh][1], O[2*dh][2], O[2*dh][3],
                    a0, a1, a2, a3, b0a, b1a);
            MMA_F16(O[2*dh+1][0], O[2*dh+1][1], O[2*dh+1][2], O[2*dh+1][3],
                    a0, a1, a2, a3, b0b, b1b);
        }
    }

    if (kh == 1) {
#pragma unroll
        for (int nt = 0; nt < 4; nt++) {
            const int col = (nt << 3) + (tig << 1);
            *(float2*)&sOp[(q0 + gid) * SOP_STRIDE + col]     = make_float2(O[nt][0], O[nt][1]);
            *(float2*)&sOp[(q0 + gid + 8) * SOP_STRIDE + col] = make_float2(O[nt][2], O[nt][3]);
        }
    }
    __syncthreads();
    if (kh == 0) {
        const int r0 = q0 + gid, r1 = r0 + 8;
#pragma unroll
        for (int nt = 0; nt < 4; nt++) {
            const int col = (nt << 3) + (tig << 1);
            float2 p0 = *(const float2*)&sOp[r0 * SOP_STRIDE + col];
            float2 p1 = *(const float2*)&sOp[r1 * SOP_STRIDE + col];
            const int dcol = hcol + col;
            if (r0 < WA)
                *(float2*)&g_attnout[(long)(w * WA + r0) * DIM + dcol] =
                    make_float2(O[nt][0] + p0.x, O[nt][1] + p0.y);
            if (r1 < WA)
                *(float2*)&g_attnout[(long)(w * WA + r1) * DIM + dcol] =
                    make_float2(O[nt][2] + p1.x, O[nt][3] + p1.y);
        }
    }
}

// ============================================================
// launch
// ============================================================
extern "C" void kernel_launch(void* const* d_in, const int* in_sizes, int n_in,
                              void* d_out, int out_size) {
    const float* x         = (const float*)d_in[0];
    const float* x_pooled  = (const float*)d_in[1];
    const float* qkv_w     = (const float*)d_in[2];
    const float* qkv_b     = (const float*)d_in[3];
    const float* proj_w    = (const float*)d_in[4];
    const float* proj_b    = (const float*)d_in[5];
    const float* rpb_table = (const float*)d_in[6];
    const float* rpb_nb    = (const float*)d_in[7];
    const float* rpb_win   = (const float*)d_in[8];
    float* out = (float*)d_out;

    float *p_qkv = nullptr, *p_qkvp = nullptr, *p_ao = nullptr;
    cudaGetSymbolAddress((void**)&p_qkv,  g_qkv);
    cudaGetSymbolAddress((void**)&p_qkvp, g_qkvp);
    cudaGetSymbolAddress((void**)&p_ao,   g_attnout);

    const int attn_smem = SMEM_HALVES * 2;  // 77312 B
    cudaFuncSetAttribute(attn_kernel, cudaFuncAttributeMaxDynamicSharedMemorySize, attn_smem);

    init_kernel<<<96, 256>>>(rpb_table, rpb_nb, rpb_win);

    gemm_fp16_kernel<<<dim3(100352 / 128, QKVC / 64), 256>>>(
        x, qkv_w, qkv_b, p_qkv, BATCH * HH * WWID, QKVC, DIM);

    gemm_fp16_kernel<<<dim3(2048 / 128, QKVC / 64), 256>>>(
        x_pooled, qkv_w, qkv_b, p_qkvp, BATCH * NWH * NWW, QKVC, DIM);

    attn_kernel<<<dim3(BNW, HEADS), 256, attn_smem>>>();

    gemm_fp16_kernel<<<dim3(100352 / 128, DIM / 64), 256>>>(
        p_ao, proj_w, proj_b, out, BNW * WA, DIM, DIM);
}

// round 14
// speedup vs baseline: 5.1271x; 1.3042x over previous
#include <cuda_runtime.h>
#include <cuda_fp16.h>
#include <limits.h>

// ---- problem constants ----
#define BATCH 8
#define HH    112
#define WWID  112
#define DIM   192
#define HEADS 6
#define HD    32
#define WS    7
#define WA    49
#define EXPAND 3
#define NWH   16
#define NWW   16
#define BNW   2048
#define NROLL 132
#define NK    230
#define NKP   256
#define QKVC  (3*DIM)
#define ATT_SCALE 0.17677669529663689f
#define FINE_STRIDE (HH*WWID*QKVC)
#define POOL_STRIDE (NWH*NWW*QKVC)

// attention smem layout (in halves)
#define SKH 40
#define SBS 264
#define SQ_OFF    0
#define SK_OFF    2560               // 64*SKH
#define SV_OFF    12800              // SK_OFF + 256*SKH
#define SBIAS_OFF 23040              // SV_OFF + 256*SKH
#define SRED_OFF  39936              // SBIAS_OFF + 64*SBS
#define SMEM_HALVES 40448            // SRED_OFF + 512 -> 80896 B
#define SOP_STRIDE 34

// GEMM fp16 tile strides (halves)
#define GAS 24
#define GBS 24

// ---- scratch ----
__device__ __half g_qkv [BATCH*HH*WWID*QKVC];   // fp16 now
__device__ __half g_qkvp[BATCH*NWH*NWW*QKVC];
__device__ float  g_attnout[BNW*WA*DIM];
__device__ __half g_bias_h[HEADS*64*NKP];
__device__ unsigned long long g_pmask[256];
__device__ int    g_gtab[256*NKP];
__device__ int    g_qtab[256*64];

__device__ __forceinline__ unsigned pack_half2(float lo, float hi) {
    __half2_raw hr = (__half2_raw)__floats2half2_rn(lo, hi);
    return ((unsigned)hr.y << 16) | (unsigned)hr.x;
}

__device__ __forceinline__ unsigned smem_u32(const void* p) {
    return (unsigned)__cvta_generic_to_shared(p);
}

// fast exp on fma/alu pipes. valid for x <= 0.
__device__ __forceinline__ float fast_exp(float v) {
    v = fmaxf(v, -80.f);
    float t  = v * 1.4426950408889634f;
    float tb = t + 12582912.0f;
    int   i  = __float_as_int(tb) - 0x4B400000;
    float f  = t - (tb - 12582912.0f);
    float p  = 0.0013333558f;
    p = fmaf(p, f, 0.0096181291f);
    p = fmaf(p, f, 0.0555041087f);
    p = fmaf(p, f, 0.2402265070f);
    p = fmaf(p, f, 0.6931471806f);
    p = fmaf(p, f, 1.0f);
    return __int_as_float(__float_as_int(p) + (i << 23));
}

#define MMA_F16(c0,c1,c2,c3,a0,a1,a2,a3,b0,b1)                               \
    asm volatile("mma.sync.aligned.m16n8k16.row.col.f32.f16.f16.f32 "        \
        "{%0,%1,%2,%3},{%4,%5,%6,%7},{%8,%9},{%0,%1,%2,%3};"                 \
        : "+f"(c0), "+f"(c1), "+f"(c2), "+f"(c3)                             \
        : "r"(a0), "r"(a1), "r"(a2), "r"(a3), "r"(b0), "r"(b1))

#define LDMATRIX_X4(r0,r1,r2,r3,addr)                                        \
    asm volatile("ldmatrix.sync.aligned.m8n8.x4.shared.b16 {%0,%1,%2,%3}, [%4];" \
        : "=r"(r0), "=r"(r1), "=r"(r2), "=r"(r3) : "r"(addr))

#define LDMATRIX_X4_TRANS(r0,r1,r2,r3,addr)                                  \
    asm volatile("ldmatrix.sync.aligned.m8n8.x4.trans.shared.b16 {%0,%1,%2,%3}, [%4];" \
        : "=r"(r0), "=r"(r1), "=r"(r2), "=r"(r3) : "r"(addr))

// ============================================================
// init: fp16 bias table + gather tables + pooled masks
// ============================================================
__global__ void init_kernel(const float* __restrict__ rpb_table,
                            const float* __restrict__ rpb_nb,
                            const float* __restrict__ rpb_win) {
    for (int i = blockIdx.x * blockDim.x + threadIdx.x;
         i < HEADS * 64 * NKP; i += gridDim.x * blockDim.x) {
        int j   = i % NKP;
        int row = (i / NKP) & 63;
        int h   = i / (NKP * 64);
        float v;
        if (j >= NK)        v = -60000.f;
        else if (row >= WA) v = 0.f;
        else {
            int rq = row / 7, cq = row - rq * 7;
            if (j < WA) {
                int rk = j / 7, ck = j - rk * 7;
                v = rpb_table[((rq - rk + 6) * 13 + (cq - ck + 6)) * HEADS + h];
            } else if (j < WA + NROLL) {
                v = rpb_nb[(h * WA + row) * NROLL + (j - WA)];
            } else {
                int jp = j - WA - NROLL;
                int rk = jp / 7, ck = jp - rk * 7;
                v = rpb_win[h * 169 + (rq - rk + 6) * 13 + (cq - ck + 6)];
            }
        }
        g_bias_h[i] = __float2half(v);
    }
    if (blockIdx.x == 0 && threadIdx.x < 256) {
        int wl = threadIdx.x;
        int wi = wl >> 4, wj = wl & 15;
        int y0 = wi * WS, x0 = wj * WS;
        for (int j = 0; j < WA; j++) {
            int r = j / 7, c = j - r * 7;
            g_gtab[wl * NKP + j] = ((y0 + r) * WWID + (x0 + c)) * QKVC;
        }
        int n = WA;
        for (int s = 0; s < 4; s++)
            for (int r = 0; r < 7; r++)
                for (int c = 0; c < 7; c++) {
                    bool inval;
                    if      (s == 0) inval = (r < 4 && c < 4);
                    else if (s == 1) inval = (r < 4 && c >= 3);
                    else if (s == 2) inval = (r >= 3 && c < 4);
                    else             inval = (r >= 3 && c >= 3);
                    if (inval) continue;
                    int dy = (s < 2) ? EXPAND : -EXPAND;
                    int dx = ((s & 1) == 0) ? EXPAND : -EXPAND;
                    int y = (y0 + r + dy + HH) % HH;
                    int x = (x0 + c + dx + WWID) % WWID;
                    g_gtab[wl * NKP + n++] = (y * WWID + x) * QKVC;
                }
        for (int jp = 0; jp < WA; jp++) {
            int r = jp / 7, c = jp - r * 7;
            int py = wi + r - EXPAND, px = wj + c - EXPAND;
            g_gtab[wl * NKP + 181 + jp] =
                (py >= 0 && py < NWH && px >= 0 && px < NWW)
                ? ~((py * NWW + px) * QKVC) : INT_MIN;
        }
        for (int j = NK; j < NKP; j++) g_gtab[wl * NKP + j] = INT_MIN;
        for (int r = 0; r < 64; r++) {
            if (r < WA) {
                int rr = r / 7, cc = r - rr * 7;
                g_qtab[wl * 64 + r] = ((y0 + rr) * WWID + (x0 + cc)) * QKVC;
            } else {
                g_qtab[wl * 64 + r] = INT_MIN;
            }
        }
        unsigned long long m = 0ull;
        for (int s = 0; s < WA; s++) {
            int rk = s / 7, ck = s - rk * 7;
            int py = wi + rk - EXPAND, px = wj + ck - EXPAND;
            if (py < 0 || py >= NWH || px < 0 || px >= NWW) m |= (1ull << s);
        }
        g_pmask[wl] = m;
    }
}

// ============================================================
// fp16 tensor-core GEMM, ldmatrix.x4, double-buffered.
// HALF_OUT selects fp16 vs fp32 output.
// ============================================================
template <bool HALF_OUT>
__global__ __launch_bounds__(256)
void gemm_fp16_kernel(const float* __restrict__ A, const float* __restrict__ Bw,
                      const float* __restrict__ bias, void* __restrict__ Cv,
                      int M, int N, int K) {
    __shared__ __half As[2][128 * GAS];
    __shared__ __half Bs[2][64 * GBS];
    const int tid = threadIdx.x;
    const int m0 = blockIdx.x << 7;
    const int n0 = blockIdx.y << 6;
    const int ar = tid >> 1, ac = (tid & 1) << 3;
    const int br = tid >> 2, bc = (tid & 3) << 2;
    const int wp = tid >> 5, lane = tid & 31;
    const int gid = lane >> 2, tig = lane & 3;
    const int wm = (wp >> 1) << 5;
    const int wn = (wp & 1) << 5;

    const float* Aptr = A + (long)(m0 + ar) * K + ac;
    const float* Bptr = Bw + (long)(n0 + br) * K + bc;

    const int lrow = (lane & 7) + ((lane >> 3) & 1) * 8;
    const int lcol = (lane >> 4) << 3;
    unsigned aaddr[2], baddr[2];
#pragma unroll
    for (int mt = 0; mt < 2; mt++)
        aaddr[mt] = smem_u32(&As[0][(wm + (mt << 4) + lrow) * GAS + lcol]);
#pragma unroll
    for (int ntp = 0; ntp < 2; ntp++)
        baddr[ntp] = smem_u32(&Bs[0][(wn + (ntp << 4) + lrow) * GBS + lcol]);
    const unsigned ABUF = 128 * GAS * 2;
    const unsigned BBUF = 64 * GBS * 2;

    float acc[2][4][4] = {};

    {
        float4 a0 = *(const float4*)(Aptr);
        float4 a1 = *(const float4*)(Aptr + 4);
        float4 bv = *(const float4*)(Bptr);
        uint4 ap; ap.x = pack_half2(a0.x, a0.y); ap.y = pack_half2(a0.z, a0.w);
        ap.z = pack_half2(a1.x, a1.y); ap.w = pack_half2(a1.z, a1.w);
        *(uint4*)&As[0][ar * GAS + ac] = ap;
        uint2 bp; bp.x = pack_half2(bv.x, bv.y); bp.y = pack_half2(bv.z, bv.w);
        *(uint2*)&Bs[0][br * GBS + bc] = bp;
    }
    __syncthreads();

    int cur = 0;
    for (int k0 = 0; k0 < K; k0 += 16) {
        const bool has_next = (k0 + 16) < K;
        float4 na0, na1, nbv;
        if (has_next) {
            na0 = *(const float4*)(Aptr + k0 + 16);
            na1 = *(const float4*)(Aptr + k0 + 20);
            nbv = *(const float4*)(Bptr + k0 + 16);
        }
        unsigned afr[2][4];
#pragma unroll
        for (int mt = 0; mt < 2; mt++)
            LDMATRIX_X4(afr[mt][0], afr[mt][1], afr[mt][2], afr[mt][3],
                        aaddr[mt] + cur * ABUF);
#pragma unroll
        for (int ntp = 0; ntp < 2; ntp++) {
            unsigned b0a, b0b, b1a, b1b;
            LDMATRIX_X4(b0a, b0b, b1a, b1b, baddr[ntp] + cur * BBUF);
#pragma unroll
            for (int mt = 0; mt < 2; mt++) {
                MMA_F16(acc[mt][2*ntp][0], acc[mt][2*ntp][1], acc[mt][2*ntp][2], acc[mt][2*ntp][3],
                        afr[mt][0], afr[mt][1], afr[mt][2], afr[mt][3], b0a, b1a);
                MMA_F16(acc[mt][2*ntp+1][0], acc[mt][2*ntp+1][1], acc[mt][2*ntp+1][2], acc[mt][2*ntp+1][3],
                        afr[mt][0], afr[mt][1], afr[mt][2], afr[mt][3], b0b, b1b);
            }
        }
        if (has_next) {
            const int nxt = cur ^ 1;
            uint4 ap; ap.x = pack_half2(na0.x, na0.y); ap.y = pack_half2(na0.z, na0.w);
            ap.z = pack_half2(na1.x, na1.y); ap.w = pack_half2(na1.z, na1.w);
            *(uint4*)&As[nxt][ar * GAS + ac] = ap;
            uint2 bp; bp.x = pack_half2(nbv.x, nbv.y); bp.y = pack_half2(nbv.z, nbv.w);
            *(uint2*)&Bs[nxt][br * GBS + bc] = bp;
            __syncthreads();
            cur = nxt;
        }
    }

#pragma unroll
    for (int mt = 0; mt < 2; mt++) {
        const int r0 = m0 + wm + (mt << 4) + gid;
#pragma unroll
        for (int nt = 0; nt < 4; nt++) {
            const int ccol = n0 + wn + (nt << 3) + (tig << 1);
            const float b0 = bias[ccol], b1 = bias[ccol + 1];
            if (HALF_OUT) {
                __half* C = (__half*)Cv;
                *(unsigned*)&C[(long)r0 * N + ccol] =
                    pack_half2(acc[mt][nt][0] + b0, acc[mt][nt][1] + b1);
                *(unsigned*)&C[(long)(r0 + 8) * N + ccol] =
                    pack_half2(acc[mt][nt][2] + b0, acc[mt][nt][3] + b1);
            } else {
                float* C = (float*)Cv;
                *(float2*)(C + (long)r0 * N + ccol) =
                    make_float2(acc[mt][nt][0] + b0, acc[mt][nt][1] + b1);
                *(float2*)(C + (long)(r0 + 8) * N + ccol) =
                    make_float2(acc[mt][nt][2] + b0, acc[mt][nt][3] + b1);
            }
        }
    }
}

// ============================================================
// fp16 MMA attention: fp16 uint4 gather, row-major V +
// ldmatrix.trans AV, single-exchange softmax.
// ============================================================
__global__ __launch_bounds__(256, 2)
void attn_kernel() {
    extern __shared__ __half sh[];
    __half* sq    = sh + SQ_OFF;    // [64][SKH]
    __half* sk    = sh + SK_OFF;    // [256][SKH]
    __half* sv    = sh + SV_OFF;    // [256][SKH] row-major (j, d)
    __half* sbias = sh + SBIAS_OFF;
    float*  sred  = (float*)(sh + SRED_OFF);
    float*  sOp   = (float*)(sh + SK_OFF);   // aliases sk (dead after QK)

    const int tid = threadIdx.x;
    const int wp = tid >> 5, lane = tid & 31;
    const int gid = lane >> 2, tig = lane & 3;
    const int kq = lane >> 2, q4 = lane & 3;   // gather map: 8 keys x 4 quads
    const int w = blockIdx.x;
    const int h = blockIdx.y;
    const int b  = w >> 8;
    const int wl = w & 255;
    const int bFine = b * FINE_STRIDE;
    const int bPool = b * POOL_STRIDE;
    const int hcol = h * HD;

    // ---- gather q (64 rows, one iter: 8 rows/warp, 4 lanes each) ----
    {
        const int r = (wp << 3) + kq;
        int off = g_qtab[(wl << 6) + r];
        uint4 qv = make_uint4(0, 0, 0, 0);
        if (off != INT_MIN)
            qv = *(const uint4*)(g_qkv + bFine + off + hcol + 8 * q4);
        const __half2 sc = __float2half2_rn(ATT_SCALE);
        __half2* qh = (__half2*)&qv;
        qh[0] = __hmul2(qh[0], sc); qh[1] = __hmul2(qh[1], sc);
        qh[2] = __hmul2(qh[2], sc); qh[3] = __hmul2(qh[3], sc);
        *(uint4*)&sq[r * SKH + 8 * q4] = qv;
    }
    // ---- gather k / v (256 keys, 4 iters: 8 keys/warp, 4 lanes each) ----
#pragma unroll
    for (int it = 0; it < 4; it++) {
        const int j = (it << 6) + (wp << 3) + kq;
        int off = g_gtab[(wl << 8) + j];
        uint4 kk = make_uint4(0, 0, 0, 0), vv = make_uint4(0, 0, 0, 0);
        if (off != INT_MIN) {
            const __half* base = (off >= 0) ? (g_qkv + bFine + off)
                                            : (g_qkvp + bPool + ~off);
            kk = *(const uint4*)(base + DIM + hcol + 8 * q4);
            vv = *(const uint4*)(base + 2 * DIM + hcol + 8 * q4);
        }
        *(uint4*)&sk[j * SKH + 8 * q4] = kk;
        *(uint4*)&sv[j * SKH + 8 * q4] = vv;
    }
    // ---- stage this head's bias slab into smem (fp16) ----
    {
        const __half* src = &g_bias_h[(h << 6) * NKP];
#pragma unroll
        for (int i = tid; i < 64 * 32; i += 256) {
            int row = i >> 5, ch = (i & 31) << 3;
            *(uint4*)&sbias[row * SBS + ch] = *(const uint4*)&src[(row << 8) + ch];
        }
    }
    __syncthreads();   // barrier 1

    // ---- QK^T: warp -> 16 q-rows x 128 keys ----
    const int q0 = (wp & 3) << 4;
    const int kh = wp >> 2;
    const int kb = kh << 7;
    unsigned qa[2][4];
#pragma unroll
    for (int ks = 0; ks < 2; ks++) {
        const int ra = (q0 + gid) * SKH + (ks << 4);
        const int rb = ra + (SKH << 3);
        qa[ks][0] = *(const unsigned*)&sq[ra + 2 * tig];
        qa[ks][1] = *(const unsigned*)&sq[rb + 2 * tig];
        qa[ks][2] = *(const unsigned*)&sq[ra + 2 * tig + 8];
        qa[ks][3] = *(const unsigned*)&sq[rb + 2 * tig + 8];
    }

    float S[16][4];
    const unsigned long long pm = g_pmask[wl];
    const __half* bq0 = &sbias[(q0 + gid) * SBS + kb + 2 * tig];
    const __half* bq1 = bq0 + (SBS << 3);
    const unsigned kaddr0 = smem_u32(&sk[(kb + (lane & 7)) * SKH + ((lane >> 3) << 3)]);

#pragma unroll
    for (int t = 0; t < 16; t++) {
        const int j0 = kb + (t << 3);
        float2 bL0 = __half22float2(*(const __half2*)(bq0 + (t << 3)));
        float2 bL1 = __half22float2(*(const __half2*)(bq1 + (t << 3)));
        float c0 = bL0.x, c1 = bL0.y, c2 = bL1.x, c3 = bL1.y;
        unsigned b00, b01, b10, b11;
        LDMATRIX_X4(b00, b01, b10, b11, kaddr0 + t * (8 * SKH * 2));
        MMA_F16(c0, c1, c2, c3, qa[0][0], qa[0][1], qa[0][2], qa[0][3], b00, b01);
        MMA_F16(c0, c1, c2, c3, qa[1][0], qa[1][1], qa[1][2], qa[1][3], b10, b11);
        if (kh) {
            const int jj = j0 + 2 * tig;
            if (jj >= 181 && jj < 230 && ((pm >> (jj - 181)) & 1ull)) { c0 -= 100.f; c2 -= 100.f; }
            if (jj + 1 >= 181 && jj + 1 < 230 && ((pm >> (jj - 180)) & 1ull)) { c1 -= 100.f; c3 -= 100.f; }
        }
        S[t][0] = c0; S[t][1] = c1; S[t][2] = c2; S[t][3] = c3;
    }

    // ---- online softmax, one exchange barrier ----
    float m0 = -1e30f, m1 = -1e30f;
#pragma unroll
    for (int t = 0; t < 16; t++) {
        m0 = fmaxf(m0, fmaxf(S[t][0], S[t][1]));
        m1 = fmaxf(m1, fmaxf(S[t][2], S[t][3]));
    }
    m0 = fmaxf(m0, __shfl_xor_sync(0xffffffffu, m0, 1));
    m0 = fmaxf(m0, __shfl_xor_sync(0xffffffffu, m0, 2));
    m1 = fmaxf(m1, __shfl_xor_sync(0xffffffffu, m1, 1));
    m1 = fmaxf(m1, __shfl_xor_sync(0xffffffffu, m1, 2));

    float s0 = 0.f, s1 = 0.f;
#pragma unroll
    for (int t = 0; t < 16; t++) {
        S[t][0] = fast_exp(S[t][0] - m0); s0 += S[t][0];
        S[t][1] = fast_exp(S[t][1] - m0); s0 += S[t][1];
        S[t][2] = fast_exp(S[t][2] - m1); s1 += S[t][2];
        S[t][3] = fast_exp(S[t][3] - m1); s1 += S[t][3];
    }
    s0 += __shfl_xor_sync(0xffffffffu, s0, 1);
    s0 += __shfl_xor_sync(0xffffffffu, s0, 2);
    s1 += __shfl_xor_sync(0xffffffffu, s1, 1);
    s1 += __shfl_xor_sync(0xffffffffu, s1, 2);

    if (tig == 0) {
        sred[(kh << 6) + q0 + gid]           = m0;
        sred[(kh << 6) + q0 + gid + 8]       = m1;
        sred[128 + (kh << 6) + q0 + gid]     = s0;
        sred[128 + (kh << 6) + q0 + gid + 8] = s1;
    }
    __syncthreads();   // barrier 2
    {
        float mo0 = sred[((kh ^ 1) << 6) + q0 + gid];
        float mo1 = sred[((kh ^ 1) << 6) + q0 + gid + 8];
        float so0 = sred[128 + ((kh ^ 1) << 6) + q0 + gid];
        float so1 = sred[128 + ((kh ^ 1) << 6) + q0 + gid + 8];
        float M0 = fmaxf(m0, mo0), M1 = fmaxf(m1, mo1);
        float sc0 = fast_exp(m0 - M0), sc1 = fast_exp(m1 - M1);
        float den0 = s0 * sc0 + so0 * fast_exp(mo0 - M0);
        float den1 = s1 * sc1 + so1 * fast_exp(mo1 - M1);
        m0 = sc0 / den0;
        m1 = sc1 / den1;
    }

    // ---- O = P @ V: ldmatrix.x4.trans on row-major V ----
    // lane -> matrix m=lane>>3; row = (m&1)*8 + lane&7; col-oct = (m>>1)*8
    const int vrow = ((lane >> 3) & 1) * 8 + (lane & 7);
    const int vcol = (lane >> 4) << 3;
    unsigned vaddr[2];
#pragma unroll
    for (int dh = 0; dh < 2; dh++)
        vaddr[dh] = smem_u32(&sv[(kb + vrow) * SKH + (dh << 4) + vcol]);

    float O[4][4] = {};
#pragma unroll
    for (int kc = 0; kc < 8; kc++) {
        const int t0 = kc << 1;
        unsigned a0 = pack_half2(S[t0][0] * m0, S[t0][1] * m0);
        unsigned a1 = pack_half2(S[t0][2] * m1, S[t0][3] * m1);
        unsigned a2 = pack_half2(S[t0 + 1][0] * m0, S[t0 + 1][1] * m0);
        unsigned a3 = pack_half2(S[t0 + 1][2] * m1, S[t0 + 1][3] * m1);
#pragma unroll
        for (int dh = 0; dh < 2; dh++) {
            unsigned b0a, b1a, b0b, b1b;
            // r0: (rows j0..+7, n-oct low) ; r1: (rows j0+8..15, low)
            // r2: (rows j0..+7, n-oct high); r3: (rows j0+8..15, high)
            LDMATRIX_X4_TRANS(b0a, b1a, b0b, b1b,
                              vaddr[dh] + kc * (16 * SKH * 2));
            MMA_F16(O[2*dh][0], O[2*dh][1], O[2*dh][2], O[2*dh][3],
                    a0, a1, a2, a3, b0a, b1a);
            MMA_F16(O[2*dh+1][0], O[2*dh+1][1], O[2*dh+1][2], O[2*dh+1][3],
                    a0, a1, a2, a3, b0b, b1b);
        }
    }

    // ---- combine key-halves (sOp aliases sk) ----
    if (kh == 1) {
#pragma unroll
        for (int nt = 0; nt < 4; nt++) {
            const int col = (nt << 3) + (tig << 1);
            *(float2*)&sOp[(q0 + gid) * SOP_STRIDE + col]     = make_float2(O[nt][0], O[nt][1]);
            *(float2*)&sOp[(q0 + gid + 8) * SOP_STRIDE + col] = make_float2(O[nt][2], O[nt][3]);
        }
    }
    __syncthreads();   // barrier 3
    if (kh == 0) {
        const int r0 = q0 + gid, r1 = r0 + 8;
#pragma unroll
        for (int nt = 0; nt < 4; nt++) {
            const int col = (nt << 3) + (tig << 1);
            float2 p0 = *(const float2*)&sOp[r0 * SOP_STRIDE + col];
            float2 p1 = *(const float2*)&sOp[r1 * SOP_STRIDE + col];
            const int dcol = hcol + col;
            if (r0 < WA)
                *(float2*)&g_attnout[(long)(w * WA + r0) * DIM + dcol] =
                    make_float2(O[nt][0] + p0.x, O[nt][1] + p0.y);
            if (r1 < WA)
                *(float2*)&g_attnout[(long)(w * WA + r1) * DIM + dcol] =
                    make_float2(O[nt][2] + p1.x, O[nt][3] + p1.y);
        }
    }
}

// ============================================================
// launch
// ============================================================
extern "C" void kernel_launch(void* const* d_in, const int* in_sizes, int n_in,
                              void* d_out, int out_size) {
    const float* x         = (const float*)d_in[0];
    const float* x_pooled  = (const float*)d_in[1];
    const float* qkv_w     = (const float*)d_in[2];
    const float* qkv_b     = (const float*)d_in[3];
    const float* proj_w    = (const float*)d_in[4];
    const float* proj_b    = (const float*)d_in[5];
    const float* rpb_table = (const float*)d_in[6];
    const float* rpb_nb    = (const float*)d_in[7];
    const float* rpb_win   = (const float*)d_in[8];
    float* out = (float*)d_out;

    void *p_qkv = nullptr, *p_qkvp = nullptr;
    float *p_ao = nullptr;
    cudaGetSymbolAddress(&p_qkv,  g_qkv);
    cudaGetSymbolAddress(&p_qkvp, g_qkvp);
    cudaGetSymbolAddress((void**)&p_ao, g_attnout);

    const int attn_smem = SMEM_HALVES * 2;  // 80896 B
    cudaFuncSetAttribute(attn_kernel, cudaFuncAttributeMaxDynamicSharedMemorySize, attn_smem);

    init_kernel<<<96, 256>>>(rpb_table, rpb_nb, rpb_win);

    gemm_fp16_kernel<true><<<dim3(100352 / 128, QKVC / 64), 256>>>(
        x, qkv_w, qkv_b, p_qkv, BATCH * HH * WWID, QKVC, DIM);

    gemm_fp16_kernel<true><<<dim3(2048 / 128, QKVC / 64), 256>>>(
        x_pooled, qkv_w, qkv_b, p_qkvp, BATCH * NWH * NWW, QKVC, DIM);

    attn_kernel<<<dim3(BNW, HEADS), 256, attn_smem>>>();

    gemm_fp16_kernel<false><<<dim3(100352 / 128, DIM / 64), 256>>>(
        p_ao, proj_w, proj_b, out, BNW * WA, DIM, DIM);
}

// round 15
// speedup vs baseline: 5.3972x; 1.0527x over previous
#include <cuda_runtime.h>
#include <cuda_fp16.h>
#include <limits.h>

// ---- problem constants ----
#define BATCH 8
#define HH    112
#define WWID  112
#define DIM   192
#define HEADS 6
#define HD    32
#define WS    7
#define WA    49
#define EXPAND 3
#define NWH   16
#define NWW   16
#define BNW   2048
#define NROLL 132
#define NK    230
#define NKP   256
#define QKVC  (3*DIM)
#define ATT_SCALE 0.17677669529663689f
#define FINE_STRIDE (HH*WWID*QKVC)
#define POOL_STRIDE (NWH*NWW*QKVC)

// attention smem layout (in halves)
#define SKH 40
#define SBS 264
#define SQ_OFF    0
#define SK_OFF    2560               // 64*SKH
#define SV_OFF    12800              // SK_OFF + 256*SKH
#define SBIAS_OFF 23040              // SV_OFF + 256*SKH
#define SRED_OFF  39936              // SBIAS_OFF + 64*SBS
#define SMEM_HALVES 40448            // SRED_OFF + 512 -> 80896 B
#define SOP_STRIDE 34

// GEMM: K=192 resident in smem, row stride 200 halves
#define AS2 200
#define GEMM_SMEM ((128 + 64) * AS2 * 2)   // 76800 B

// ---- scratch ----
__device__ __half g_qkv [BATCH*HH*WWID*QKVC];
__device__ __half g_qkvp[BATCH*NWH*NWW*QKVC];
__device__ float  g_attnout[BNW*WA*DIM];
__device__ __half g_bias_h[HEADS*64*NKP];
__device__ unsigned long long g_pmask[256];
__device__ int    g_gtab[256*NKP];
__device__ int    g_qtab[256*64];

__device__ __forceinline__ unsigned pack_half2(float lo, float hi) {
    __half2_raw hr = (__half2_raw)__floats2half2_rn(lo, hi);
    return ((unsigned)hr.y << 16) | (unsigned)hr.x;
}

__device__ __forceinline__ unsigned smem_u32(const void* p) {
    return (unsigned)__cvta_generic_to_shared(p);
}

// fast exp on fma/alu pipes. valid for x <= 0.
__device__ __forceinline__ float fast_exp(float v) {
    v = fmaxf(v, -80.f);
    float t  = v * 1.4426950408889634f;
    float tb = t + 12582912.0f;
    int   i  = __float_as_int(tb) - 0x4B400000;
    float f  = t - (tb - 12582912.0f);
    float p  = 0.0013333558f;
    p = fmaf(p, f, 0.0096181291f);
    p = fmaf(p, f, 0.0555041087f);
    p = fmaf(p, f, 0.2402265070f);
    p = fmaf(p, f, 0.6931471806f);
    p = fmaf(p, f, 1.0f);
    return __int_as_float(__float_as_int(p) + (i << 23));
}

#define MMA_F16(c0,c1,c2,c3,a0,a1,a2,a3,b0,b1)                               \
    asm volatile("mma.sync.aligned.m16n8k16.row.col.f32.f16.f16.f32 "        \
        "{%0,%1,%2,%3},{%4,%5,%6,%7},{%8,%9},{%0,%1,%2,%3};"                 \
        : "+f"(c0), "+f"(c1), "+f"(c2), "+f"(c3)                             \
        : "r"(a0), "r"(a1), "r"(a2), "r"(a3), "r"(b0), "r"(b1))

#define LDMATRIX_X4(r0,r1,r2,r3,addr)                                        \
    asm volatile("ldmatrix.sync.aligned.m8n8.x4.shared.b16 {%0,%1,%2,%3}, [%4];" \
        : "=r"(r0), "=r"(r1), "=r"(r2), "=r"(r3) : "r"(addr))

#define LDMATRIX_X4_TRANS(r0,r1,r2,r3,addr)                                  \
    asm volatile("ldmatrix.sync.aligned.m8n8.x4.trans.shared.b16 {%0,%1,%2,%3}, [%4];" \
        : "=r"(r0), "=r"(r1), "=r"(r2), "=r"(r3) : "r"(addr))

// ============================================================
// init: fp16 bias table + gather tables + pooled masks
// ============================================================
__global__ void init_kernel(const float* __restrict__ rpb_table,
                            const float* __restrict__ rpb_nb,
                            const float* __restrict__ rpb_win) {
    for (int i = blockIdx.x * blockDim.x + threadIdx.x;
         i < HEADS * 64 * NKP; i += gridDim.x * blockDim.x) {
        int j   = i % NKP;
        int row = (i / NKP) & 63;
        int h   = i / (NKP * 64);
        float v;
        if (j >= NK)        v = -60000.f;
        else if (row >= WA) v = 0.f;
        else {
            int rq = row / 7, cq = row - rq * 7;
            if (j < WA) {
                int rk = j / 7, ck = j - rk * 7;
                v = rpb_table[((rq - rk + 6) * 13 + (cq - ck + 6)) * HEADS + h];
            } else if (j < WA + NROLL) {
                v = rpb_nb[(h * WA + row) * NROLL + (j - WA)];
            } else {
                int jp = j - WA - NROLL;
                int rk = jp / 7, ck = jp - rk * 7;
                v = rpb_win[h * 169 + (rq - rk + 6) * 13 + (cq - ck + 6)];
            }
        }
        g_bias_h[i] = __float2half(v);
    }
    if (blockIdx.x == 0 && threadIdx.x < 256) {
        int wl = threadIdx.x;
        int wi = wl >> 4, wj = wl & 15;
        int y0 = wi * WS, x0 = wj * WS;
        for (int j = 0; j < WA; j++) {
            int r = j / 7, c = j - r * 7;
            g_gtab[wl * NKP + j] = ((y0 + r) * WWID + (x0 + c)) * QKVC;
        }
        int n = WA;
        for (int s = 0; s < 4; s++)
            for (int r = 0; r < 7; r++)
                for (int c = 0; c < 7; c++) {
                    bool inval;
                    if      (s == 0) inval = (r < 4 && c < 4);
                    else if (s == 1) inval = (r < 4 && c >= 3);
                    else if (s == 2) inval = (r >= 3 && c < 4);
                    else             inval = (r >= 3 && c >= 3);
                    if (inval) continue;
                    int dy = (s < 2) ? EXPAND : -EXPAND;
                    int dx = ((s & 1) == 0) ? EXPAND : -EXPAND;
                    int y = (y0 + r + dy + HH) % HH;
                    int x = (x0 + c + dx + WWID) % WWID;
                    g_gtab[wl * NKP + n++] = (y * WWID + x) * QKVC;
                }
        for (int jp = 0; jp < WA; jp++) {
            int r = jp / 7, c = jp - r * 7;
            int py = wi + r - EXPAND, px = wj + c - EXPAND;
            g_gtab[wl * NKP + 181 + jp] =
                (py >= 0 && py < NWH && px >= 0 && px < NWW)
                ? ~((py * NWW + px) * QKVC) : INT_MIN;
        }
        for (int j = NK; j < NKP; j++) g_gtab[wl * NKP + j] = INT_MIN;
        for (int r = 0; r < 64; r++) {
            if (r < WA) {
                int rr = r / 7, cc = r - rr * 7;
                g_qtab[wl * 64 + r] = ((y0 + rr) * WWID + (x0 + cc)) * QKVC;
            } else {
                g_qtab[wl * 64 + r] = INT_MIN;
            }
        }
        unsigned long long m = 0ull;
        for (int s = 0; s < WA; s++) {
            int rk = s / 7, ck = s - rk * 7;
            int py = wi + rk - EXPAND, px = wj + ck - EXPAND;
            if (py < 0 || py >= NWH || px < 0 || px >= NWW) m |= (1ull << s);
        }
        g_pmask[wl] = m;
    }
}

// ============================================================
// K-resident fp16 GEMM: block = 128 rows x 192 cols, K=192.
// A staged once; 3 n-sub-tiles of 64; no barriers in MMA loop.
// ============================================================
template <bool HALF_OUT>
__global__ __launch_bounds__(256, 2)
void gemm_fp16_kernel(const float* __restrict__ A, const float* __restrict__ Bw,
                      const float* __restrict__ bias, void* __restrict__ Cv,
                      int M, int N) {
    extern __shared__ __half gs[];
    __half* As = gs;                 // [128][AS2]
    __half* Bs = gs + 128 * AS2;     // [64][AS2]

    const int tid = threadIdx.x;
    const int m0 = blockIdx.x << 7;
    const int n0 = blockIdx.y * 192;
    const int wp = tid >> 5, lane = tid & 31;
    const int gid = lane >> 2, tig = lane & 3;
    const int wm = (wp >> 1) << 5;
    const int wn = (wp & 1) << 5;

    // ---- stage A (128 x 192) once ----
    {
        const int row = tid >> 1, colb = (tid & 1) * 96;
        const float* ap = A + (long)(m0 + row) * DIM + colb;
        __half* dst = &As[row * AS2 + colb];
#pragma unroll
        for (int c = 0; c < 96; c += 16) {
            float4 f0 = *(const float4*)(ap + c);
            float4 f1 = *(const float4*)(ap + c + 4);
            float4 f2 = *(const float4*)(ap + c + 8);
            float4 f3 = *(const float4*)(ap + c + 12);
            uint4 p0, p1;
            p0.x = pack_half2(f0.x, f0.y); p0.y = pack_half2(f0.z, f0.w);
            p0.z = pack_half2(f1.x, f1.y); p0.w = pack_half2(f1.z, f1.w);
            p1.x = pack_half2(f2.x, f2.y); p1.y = pack_half2(f2.z, f2.w);
            p1.z = pack_half2(f3.x, f3.y); p1.w = pack_half2(f3.z, f3.w);
            *(uint4*)(dst + c) = p0;
            *(uint4*)(dst + c + 8) = p1;
        }
    }
    // ---- stage B sub 0 ----
    {
        const int row = tid >> 2, colb = (tid & 3) * 48;
        const float* bp = Bw + (long)(n0 + row) * DIM + colb;
        __half* dst = &Bs[row * AS2 + colb];
#pragma unroll
        for (int c = 0; c < 48; c += 16) {
            float4 f0 = *(const float4*)(bp + c);
            float4 f1 = *(const float4*)(bp + c + 4);
            float4 f2 = *(const float4*)(bp + c + 8);
            float4 f3 = *(const float4*)(bp + c + 12);
            uint4 p0, p1;
            p0.x = pack_half2(f0.x, f0.y); p0.y = pack_half2(f0.z, f0.w);
            p0.z = pack_half2(f1.x, f1.y); p0.w = pack_half2(f1.z, f1.w);
            p1.x = pack_half2(f2.x, f2.y); p1.y = pack_half2(f2.z, f2.w);
            p1.z = pack_half2(f3.x, f3.y); p1.w = pack_half2(f3.z, f3.w);
            *(uint4*)(dst + c) = p0;
            *(uint4*)(dst + c + 8) = p1;
        }
    }
    __syncthreads();

    const int lrow = (lane & 7) + ((lane >> 3) & 1) * 8;
    const int lcol = (lane >> 4) << 3;
    unsigned aaddr[2], baddr[2];
#pragma unroll
    for (int mt = 0; mt < 2; mt++)
        aaddr[mt] = smem_u32(&As[(wm + (mt << 4) + lrow) * AS2 + lcol]);
#pragma unroll
    for (int ntp = 0; ntp < 2; ntp++)
        baddr[ntp] = smem_u32(&Bs[(wn + (ntp << 4) + lrow) * AS2 + lcol]);

#pragma unroll
    for (int sub = 0; sub < 3; sub++) {
        float acc[2][4][4] = {};
#pragma unroll
        for (int t = 0; t < 12; t++) {
            unsigned afr[2][4];
#pragma unroll
            for (int mt = 0; mt < 2; mt++)
                LDMATRIX_X4(afr[mt][0], afr[mt][1], afr[mt][2], afr[mt][3],
                            aaddr[mt] + t * 32);
#pragma unroll
            for (int ntp = 0; ntp < 2; ntp++) {
                unsigned b0a, b0b, b1a, b1b;
                LDMATRIX_X4(b0a, b0b, b1a, b1b, baddr[ntp] + t * 32);
#pragma unroll
                for (int mt = 0; mt < 2; mt++) {
                    MMA_F16(acc[mt][2*ntp][0], acc[mt][2*ntp][1], acc[mt][2*ntp][2], acc[mt][2*ntp][3],
                            afr[mt][0], afr[mt][1], afr[mt][2], afr[mt][3], b0a, b1a);
                    MMA_F16(acc[mt][2*ntp+1][0], acc[mt][2*ntp+1][1], acc[mt][2*ntp+1][2], acc[mt][2*ntp+1][3],
                            afr[mt][0], afr[mt][1], afr[mt][2], afr[mt][3], b0b, b1b);
                }
            }
        }
        // ---- write this sub-tile ----
#pragma unroll
        for (int mt = 0; mt < 2; mt++) {
            const int r0 = m0 + wm + (mt << 4) + gid;
#pragma unroll
            for (int nt = 0; nt < 4; nt++) {
                const int ccol = n0 + sub * 64 + wn + (nt << 3) + (tig << 1);
                const float b0 = bias[ccol], b1 = bias[ccol + 1];
                if (HALF_OUT) {
                    __half* C = (__half*)Cv;
                    *(unsigned*)&C[(long)r0 * N + ccol] =
                        pack_half2(acc[mt][nt][0] + b0, acc[mt][nt][1] + b1);
                    *(unsigned*)&C[(long)(r0 + 8) * N + ccol] =
                        pack_half2(acc[mt][nt][2] + b0, acc[mt][nt][3] + b1);
                } else {
                    float* C = (float*)Cv;
                    *(float2*)(C + (long)r0 * N + ccol) =
                        make_float2(acc[mt][nt][0] + b0, acc[mt][nt][1] + b1);
                    *(float2*)(C + (long)(r0 + 8) * N + ccol) =
                        make_float2(acc[mt][nt][2] + b0, acc[mt][nt][3] + b1);
                }
            }
        }
        // ---- restage B for next sub ----
        if (sub < 2) {
            __syncthreads();
            const int row = tid >> 2, colb = (tid & 3) * 48;
            const float* bp = Bw + (long)(n0 + (sub + 1) * 64 + row) * DIM + colb;
            __half* dst = &Bs[row * AS2 + colb];
#pragma unroll
            for (int c = 0; c < 48; c += 16) {
                float4 f0 = *(const float4*)(bp + c);
                float4 f1 = *(const float4*)(bp + c + 4);
                float4 f2 = *(const float4*)(bp + c + 8);
                float4 f3 = *(const float4*)(bp + c + 12);
                uint4 p0, p1;
                p0.x = pack_half2(f0.x, f0.y); p0.y = pack_half2(f0.z, f0.w);
                p0.z = pack_half2(f1.x, f1.y); p0.w = pack_half2(f1.z, f1.w);
                p1.x = pack_half2(f2.x, f2.y); p1.y = pack_half2(f2.z, f2.w);
                p1.z = pack_half2(f3.x, f3.y); p1.w = pack_half2(f3.z, f3.w);
                *(uint4*)(dst + c) = p0;
                *(uint4*)(dst + c + 8) = p1;
            }
            __syncthreads();
        }
    }
}

// ============================================================
// fp16 MMA attention (R14 structure; normalization deferred to epilogue)
// ============================================================
__global__ __launch_bounds__(256, 2)
void attn_kernel() {
    extern __shared__ __half sh[];
    __half* sq    = sh + SQ_OFF;
    __half* sk    = sh + SK_OFF;
    __half* sv    = sh + SV_OFF;
    __half* sbias = sh + SBIAS_OFF;
    float*  sred  = (float*)(sh + SRED_OFF);
    float*  sOp   = (float*)(sh + SK_OFF);

    const int tid = threadIdx.x;
    const int wp = tid >> 5, lane = tid & 31;
    const int gid = lane >> 2, tig = lane & 3;
    const int kq = lane >> 2, q4 = lane & 3;
    const int w = blockIdx.x;
    const int h = blockIdx.y;
    const int b  = w >> 8;
    const int wl = w & 255;
    const int bFine = b * FINE_STRIDE;
    const int bPool = b * POOL_STRIDE;
    const int hcol = h * HD;

    {
        const int r = (wp << 3) + kq;
        int off = g_qtab[(wl << 6) + r];
        uint4 qv = make_uint4(0, 0, 0, 0);
        if (off != INT_MIN)
            qv = *(const uint4*)(g_qkv + bFine + off + hcol + 8 * q4);
        const __half2 sc = __float2half2_rn(ATT_SCALE);
        __half2* qh = (__half2*)&qv;
        qh[0] = __hmul2(qh[0], sc); qh[1] = __hmul2(qh[1], sc);
        qh[2] = __hmul2(qh[2], sc); qh[3] = __hmul2(qh[3], sc);
        *(uint4*)&sq[r * SKH + 8 * q4] = qv;
    }
#pragma unroll
    for (int it = 0; it < 4; it++) {
        const int j = (it << 6) + (wp << 3) + kq;
        int off = g_gtab[(wl << 8) + j];
        uint4 kk = make_uint4(0, 0, 0, 0), vv = make_uint4(0, 0, 0, 0);
        if (off != INT_MIN) {
            const __half* base = (off >= 0) ? (g_qkv + bFine + off)
                                            : (g_qkvp + bPool + ~off);
            kk = *(const uint4*)(base + DIM + hcol + 8 * q4);
            vv = *(const uint4*)(base + 2 * DIM + hcol + 8 * q4);
        }
        *(uint4*)&sk[j * SKH + 8 * q4] = kk;
        *(uint4*)&sv[j * SKH + 8 * q4] = vv;
    }
    {
        const __half* src = &g_bias_h[(h << 6) * NKP];
#pragma unroll
        for (int i = tid; i < 64 * 32; i += 256) {
            int row = i >> 5, ch = (i & 31) << 3;
            *(uint4*)&sbias[row * SBS + ch] = *(const uint4*)&src[(row << 8) + ch];
        }
    }
    __syncthreads();

    const int q0 = (wp & 3) << 4;
    const int kh = wp >> 2;
    const int kb = kh << 7;
    unsigned qa[2][4];
#pragma unroll
    for (int ks = 0; ks < 2; ks++) {
        const int ra = (q0 + gid) * SKH + (ks << 4);
        const int rb = ra + (SKH << 3);
        qa[ks][0] = *(const unsigned*)&sq[ra + 2 * tig];
        qa[ks][1] = *(const unsigned*)&sq[rb + 2 * tig];
        qa[ks][2] = *(const unsigned*)&sq[ra + 2 * tig + 8];
        qa[ks][3] = *(const unsigned*)&sq[rb + 2 * tig + 8];
    }

    float S[16][4];
    const unsigned long long pm = g_pmask[wl];
    const __half* bq0 = &sbias[(q0 + gid) * SBS + kb + 2 * tig];
    const __half* bq1 = bq0 + (SBS << 3);
    const unsigned kaddr0 = smem_u32(&sk[(kb + (lane & 7)) * SKH + ((lane >> 3) << 3)]);

#pragma unroll
    for (int t = 0; t < 16; t++) {
        const int j0 = kb + (t << 3);
        float2 bL0 = __half22float2(*(const __half2*)(bq0 + (t << 3)));
        float2 bL1 = __half22float2(*(const __half2*)(bq1 + (t << 3)));
        float c0 = bL0.x, c1 = bL0.y, c2 = bL1.x, c3 = bL1.y;
        unsigned b00, b01, b10, b11;
        LDMATRIX_X4(b00, b01, b10, b11, kaddr0 + t * (8 * SKH * 2));
        MMA_F16(c0, c1, c2, c3, qa[0][0], qa[0][1], qa[0][2], qa[0][3], b00, b01);
        MMA_F16(c0, c1, c2, c3, qa[1][0], qa[1][1], qa[1][2], qa[1][3], b10, b11);
        if (kh) {
            const int jj = j0 + 2 * tig;
            if (jj >= 181 && jj < 230 && ((pm >> (jj - 181)) & 1ull)) { c0 -= 100.f; c2 -= 100.f; }
            if (jj + 1 >= 181 && jj + 1 < 230 && ((pm >> (jj - 180)) & 1ull)) { c1 -= 100.f; c3 -= 100.f; }
        }
        S[t][0] = c0; S[t][1] = c1; S[t][2] = c2; S[t][3] = c3;
    }

    float m0 = -1e30f, m1 = -1e30f;
#pragma unroll
    for (int t = 0; t < 16; t++) {
        m0 = fmaxf(m0, fmaxf(S[t][0], S[t][1]));
        m1 = fmaxf(m1, fmaxf(S[t][2], S[t][3]));
    }
    m0 = fmaxf(m0, __shfl_xor_sync(0xffffffffu, m0, 1));
    m0 = fmaxf(m0, __shfl_xor_sync(0xffffffffu, m0, 2));
    m1 = fmaxf(m1, __shfl_xor_sync(0xffffffffu, m1, 1));
    m1 = fmaxf(m1, __shfl_xor_sync(0xffffffffu, m1, 2));

    float s0 = 0.f, s1 = 0.f;
#pragma unroll
    for (int t = 0; t < 16; t++) {
        S[t][0] = fast_exp(S[t][0] - m0); s0 += S[t][0];
        S[t][1] = fast_exp(S[t][1] - m0); s0 += S[t][1];
        S[t][2] = fast_exp(S[t][2] - m1); s1 += S[t][2];
        S[t][3] = fast_exp(S[t][3] - m1); s1 += S[t][3];
    }
    s0 += __shfl_xor_sync(0xffffffffu, s0, 1);
    s0 += __shfl_xor_sync(0xffffffffu, s0, 2);
    s1 += __shfl_xor_sync(0xffffffffu, s1, 1);
    s1 += __shfl_xor_sync(0xffffffffu, s1, 2);

    if (tig == 0) {
        sred[(kh << 6) + q0 + gid]           = m0;
        sred[(kh << 6) + q0 + gid + 8]       = m1;
        sred[128 + (kh << 6) + q0 + gid]     = s0;
        sred[128 + (kh << 6) + q0 + gid + 8] = s1;
    }
    __syncthreads();
    {
        float mo0 = sred[((kh ^ 1) << 6) + q0 + gid];
        float mo1 = sred[((kh ^ 1) << 6) + q0 + gid + 8];
        float so0 = sred[128 + ((kh ^ 1) << 6) + q0 + gid];
        float so1 = sred[128 + ((kh ^ 1) << 6) + q0 + gid + 8];
        float M0 = fmaxf(m0, mo0), M1 = fmaxf(m1, mo1);
        float sc0 = fast_exp(m0 - M0), sc1 = fast_exp(m1 - M1);
        float den0 = s0 * sc0 + so0 * fast_exp(mo0 - M0);
        float den1 = s1 * sc1 + so1 * fast_exp(mo1 - M1);
        m0 = sc0 / den0;
        m1 = sc1 / den1;
    }

    // ---- O = P_unnorm @ V (normalization deferred to epilogue) ----
    const int vrow = ((lane >> 3) & 1) * 8 + (lane & 7);
    const int vcol = (lane >> 4) << 3;
    unsigned vaddr[2];
#pragma unroll
    for (int dh = 0; dh < 2; dh++)
        vaddr[dh] = smem_u32(&sv[(kb + vrow) * SKH + (dh << 4) + vcol]);

    float O[4][4] = {};
#pragma unroll
    for (int kc = 0; kc < 8; kc++) {
        const int t0 = kc << 1;
        unsigned a0 = pack_half2(S[t0][0], S[t0][1]);
        unsigned a1 = pack_half2(S[t0][2], S[t0][3]);
        unsigned a2 = pack_half2(S[t0 + 1][0], S[t0 + 1][1]);
        unsigned a3 = pack_half2(S[t0 + 1][2], S[t0 + 1][3]);
#pragma unroll
        for (int dh = 0; dh < 2; dh++) {
            unsigned b0a, b1a, b0b, b1b;
            LDMATRIX_X4_TRANS(b0a, b1a, b0b, b1b,
                              vaddr[dh] + kc * (16 * SKH * 2));
            MMA_F16(O[2*dh][0], O[2*dh][1], O[2*dh][2], O[2*dh][3],
                    a0, a1, a2, a3, b0a, b1a);
            MMA_F16(O[2*dh+1][0], O[2*dh+1][1], O[2*dh+1][2], O[2*dh+1][3],
                    a0, a1, a2, a3, b0b, b1b);
        }
    }
    // apply per-row normalization once
#pragma unroll
    for (int nt = 0; nt < 4; nt++) {
        O[nt][0] *= m0; O[nt][1] *= m0;
        O[nt][2] *= m1; O[nt][3] *= m1;
    }

    if (kh == 1) {
#pragma unroll
        for (int nt = 0; nt < 4; nt++) {
            const int col = (nt << 3) + (tig << 1);
            *(float2*)&sOp[(q0 + gid) * SOP_STRIDE + col]     = make_float2(O[nt][0], O[nt][1]);
            *(float2*)&sOp[(q0 + gid + 8) * SOP_STRIDE + col] = make_float2(O[nt][2], O[nt][3]);
        }
    }
    __syncthreads();
    if (kh == 0) {
        const int r0 = q0 + gid, r1 = r0 + 8;
#pragma unroll
        for (int nt = 0; nt < 4; nt++) {
            const int col = (nt << 3) + (tig << 1);
            float2 p0 = *(const float2*)&sOp[r0 * SOP_STRIDE + col];
            float2 p1 = *(const float2*)&sOp[r1 * SOP_STRIDE + col];
            const int dcol = hcol + col;
            if (r0 < WA)
                *(float2*)&g_attnout[(long)(w * WA + r0) * DIM + dcol] =
                    make_float2(O[nt][0] + p0.x, O[nt][1] + p0.y);
            if (r1 < WA)
                *(float2*)&g_attnout[(long)(w * WA + r1) * DIM + dcol] =
                    make_float2(O[nt][2] + p1.x, O[nt][3] + p1.y);
        }
    }
}

// ============================================================
// launch
// ============================================================
extern "C" void kernel_launch(void* const* d_in, const int* in_sizes, int n_in,
                              void* d_out, int out_size) {
    const float* x         = (const float*)d_in[0];
    const float* x_pooled  = (const float*)d_in[1];
    const float* qkv_w     = (const float*)d_in[2];
    const float* qkv_b     = (const float*)d_in[3];
    const float* proj_w    = (const float*)d_in[4];
    const float* proj_b    = (const float*)d_in[5];
    const float* rpb_table = (const float*)d_in[6];
    const float* rpb_nb    = (const float*)d_in[7];
    const float* rpb_win   = (const float*)d_in[8];
    float* out = (float*)d_out;

    void *p_qkv = nullptr, *p_qkvp = nullptr;
    float *p_ao = nullptr;
    cudaGetSymbolAddress(&p_qkv,  g_qkv);
    cudaGetSymbolAddress(&p_qkvp, g_qkvp);
    cudaGetSymbolAddress((void**)&p_ao, g_attnout);

    const int attn_smem = SMEM_HALVES * 2;  // 80896 B
    cudaFuncSetAttribute(attn_kernel, cudaFuncAttributeMaxDynamicSharedMemorySize, attn_smem);
    cudaFuncSetAttribute(gemm_fp16_kernel<true>,
                         cudaFuncAttributeMaxDynamicSharedMemorySize, GEMM_SMEM);
    cudaFuncSetAttribute(gemm_fp16_kernel<false>,
                         cudaFuncAttributeMaxDynamicSharedMemorySize, GEMM_SMEM);

    init_kernel<<<96, 256>>>(rpb_table, rpb_nb, rpb_win);

    gemm_fp16_kernel<true><<<dim3(100352 / 128, 3), 256, GEMM_SMEM>>>(
        x, qkv_w, qkv_b, p_qkv, BATCH * HH * WWID, QKVC);

    gemm_fp16_kernel<true><<<dim3(2048 / 128, 3), 256, GEMM_SMEM>>>(
        x_pooled, qkv_w, qkv_b, p_qkvp, BATCH * NWH * NWW, QKVC);

    attn_kernel<<<dim3(BNW, HEADS), 256, attn_smem>>>();

    gemm_fp16_kernel<false><<<dim3(100352 / 128, 1), 256, GEMM_SMEM>>>(
        p_ao, proj_w, proj_b, out, BNW * WA, DIM);
}

// round 16
// speedup vs baseline: 6.4168x; 1.1889x over previous
#include <cuda_runtime.h>
#include <cuda_fp16.h>
#include <limits.h>

// ---- problem constants ----
#define BATCH 8
#define HH    112
#define WWID  112
#define DIM   192
#define HEADS 6
#define HD    32
#define WS    7
#define WA    49
#define EXPAND 3
#define NWH   16
#define NWW   16
#define BNW   2048
#define NROLL 132
#define NK    230
#define NKP   256
#define QKVC  (3*DIM)
#define ATT_SCALE 0.17677669529663689f
#define FINE_STRIDE (HH*WWID*QKVC)
#define POOL_STRIDE (NWH*NWW*QKVC)

// attention smem layout (in halves)
#define SKH 40
#define SBS 264
#define SQ_OFF    0
#define SK_OFF    2560
#define SV_OFF    12800
#define SBIAS_OFF 23040
#define SRED_OFF  39936
#define SMEM_HALVES 40448            // 80896 B
#define SOP_STRIDE 34

// GEMM: K=192 resident, row stride 200 halves
#define AS2 200
#define GEMM_SMEM ((128 + 64) * AS2 * 2)   // 76800 B

// ---- scratch ----
__device__ __half g_qkv [BATCH*HH*WWID*QKVC];
__device__ __half g_qkvp[BATCH*NWH*NWW*QKVC];
__device__ float  g_attnout[BNW*WA*DIM];
__device__ __half g_bias_h[HEADS*64*NKP];
__device__ __half g_wqkv_h[QKVC*DIM];
__device__ __half g_wproj_h[DIM*DIM];
__device__ unsigned long long g_pmask[256];
__device__ int    g_gtab[256*NKP];
__device__ int    g_qtab[256*64];

__device__ __forceinline__ unsigned pack_half2(float lo, float hi) {
    __half2_raw hr = (__half2_raw)__floats2half2_rn(lo, hi);
    return ((unsigned)hr.y << 16) | (unsigned)hr.x;
}

__device__ __forceinline__ unsigned smem_u32(const void* p) {
    return (unsigned)__cvta_generic_to_shared(p);
}

// fast exp, degree-3 minimax for 2^f (rel err ~1.4e-4). valid for x <= 0.
__device__ __forceinline__ float fast_exp(float v) {
    v = fmaxf(v, -80.f);
    float t  = v * 1.4426950408889634f;
    float tb = t + 12582912.0f;
    int   i  = __float_as_int(tb) - 0x4B400000;
    float f  = t - (tb - 12582912.0f);
    float p  = 0.0558263f;
    p = fmaf(p, f, 0.2401397f);
    p = fmaf(p, f, 0.6931471f);
    p = fmaf(p, f, 1.0f);
    return __int_as_float(__float_as_int(p) + (i << 23));
}

#define MMA_F16(c0,c1,c2,c3,a0,a1,a2,a3,b0,b1)                               \
    asm volatile("mma.sync.aligned.m16n8k16.row.col.f32.f16.f16.f32 "        \
        "{%0,%1,%2,%3},{%4,%5,%6,%7},{%8,%9},{%0,%1,%2,%3};"                 \
        : "+f"(c0), "+f"(c1), "+f"(c2), "+f"(c3)                             \
        : "r"(a0), "r"(a1), "r"(a2), "r"(a3), "r"(b0), "r"(b1))

#define LDMATRIX_X4(r0,r1,r2,r3,addr)                                        \
    asm volatile("ldmatrix.sync.aligned.m8n8.x4.shared.b16 {%0,%1,%2,%3}, [%4];" \
        : "=r"(r0), "=r"(r1), "=r"(r2), "=r"(r3) : "r"(addr))

#define LDMATRIX_X4_TRANS(r0,r1,r2,r3,addr)                                  \
    asm volatile("ldmatrix.sync.aligned.m8n8.x4.trans.shared.b16 {%0,%1,%2,%3}, [%4];" \
        : "=r"(r0), "=r"(r1), "=r"(r2), "=r"(r3) : "r"(addr))

// ============================================================
// init: bias table + weights->fp16 + per-window tables (parallel)
// grid = 256 blocks x 256 threads; block wl owns window wl's tables.
// ============================================================
__global__ void init_kernel(const float* __restrict__ rpb_table,
                            const float* __restrict__ rpb_nb,
                            const float* __restrict__ rpb_win,
                            const float* __restrict__ qkv_w,
                            const float* __restrict__ proj_w) {
    const int gtid = blockIdx.x * blockDim.x + threadIdx.x;
    const int gsz = gridDim.x * blockDim.x;
    // bias table
    for (int i = gtid; i < HEADS * 64 * NKP; i += gsz) {
        int j   = i % NKP;
        int row = (i / NKP) & 63;
        int h   = i / (NKP * 64);
        float v;
        if (j >= NK)        v = -60000.f;
        else if (row >= WA) v = 0.f;
        else {
            int rq = row / 7, cq = row - rq * 7;
            if (j < WA) {
                int rk = j / 7, ck = j - rk * 7;
                v = rpb_table[((rq - rk + 6) * 13 + (cq - ck + 6)) * HEADS + h];
            } else if (j < WA + NROLL) {
                v = rpb_nb[(h * WA + row) * NROLL + (j - WA)];
            } else {
                int jp = j - WA - NROLL;
                int rk = jp / 7, ck = jp - rk * 7;
                v = rpb_win[h * 169 + (rq - rk + 6) * 13 + (cq - ck + 6)];
            }
        }
        g_bias_h[i] = __float2half(v);
    }
    // weights -> fp16
    for (int i = gtid; i < QKVC * DIM; i += gsz) g_wqkv_h[i] = __float2half(qkv_w[i]);
    for (int i = gtid; i < DIM * DIM; i += gsz)  g_wproj_h[i] = __float2half(proj_w[i]);

    // per-window tables: block wl handles window wl
    const int wl = blockIdx.x;
    const int t = threadIdx.x;
    const int wi = wl >> 4, wj = wl & 15;
    const int y0 = wi * WS, x0 = wj * WS;
    if (t < WA) {            // own window
        int r = t / 7, c = t - r * 7;
        g_gtab[wl * NKP + t] = ((y0 + r) * WWID + (x0 + c)) * QKVC;
    }
    if (t >= 64 && t - 64 < WA) {   // pooled unfold (threads 64..112)
        int jp = t - 64;
        int r = jp / 7, c = jp - r * 7;
        int py = wi + r - EXPAND, px = wj + c - EXPAND;
        g_gtab[wl * NKP + 181 + jp] =
            (py >= 0 && py < NWH && px >= 0 && px < NWW)
            ? ~((py * NWW + px) * QKVC) : INT_MIN;
    }
    if (t >= 128 && t < 128 + (NKP - NK))   // padding keys
        g_gtab[wl * NKP + NK + (t - 128)] = INT_MIN;
    if (t >= 192 && t < 256) {              // q offsets (64 rows)
        int r = t - 192;
        if (r < WA) {
            int rr = r / 7, cc = r - rr * 7;
            g_qtab[wl * 64 + r] = ((y0 + rr) * WWID + (x0 + cc)) * QKVC;
        } else {
            g_qtab[wl * 64 + r] = INT_MIN;
        }
    }
    if (t == 1) {            // rolled ring (order-sensitive) + pmask
        int n = WA;
        for (int s = 0; s < 4; s++)
            for (int r = 0; r < 7; r++)
                for (int c = 0; c < 7; c++) {
                    bool inval;
                    if      (s == 0) inval = (r < 4 && c < 4);
                    else if (s == 1) inval = (r < 4 && c >= 3);
                    else if (s == 2) inval = (r >= 3 && c < 4);
                    else             inval = (r >= 3 && c >= 3);
                    if (inval) continue;
                    int dy = (s < 2) ? EXPAND : -EXPAND;
                    int dx = ((s & 1) == 0) ? EXPAND : -EXPAND;
                    int y = (y0 + r + dy + HH) % HH;
                    int x = (x0 + c + dx + WWID) % WWID;
                    g_gtab[wl * NKP + n++] = (y * WWID + x) * QKVC;
                }
        unsigned long long m = 0ull;
        for (int s = 0; s < WA; s++) {
            int rk = s / 7, ck = s - rk * 7;
            int py = wi + rk - EXPAND, px = wj + ck - EXPAND;
            if (py < 0 || py >= NWH || px < 0 || px >= NWW) m |= (1ull << s);
        }
        g_pmask[wl] = m;
    }
}

// ============================================================
// K-resident fp16 GEMM: A fp32 (converted), B fp16 preconverted.
// block = 128 rows x 192 cols; 3 n-sub-tiles of 64.
// ============================================================
template <bool HALF_OUT>
__global__ __launch_bounds__(256, 2)
void gemm_fp16_kernel(const float* __restrict__ A, const __half* __restrict__ Bw,
                      const float* __restrict__ bias, void* __restrict__ Cv,
                      int M, int N) {
    extern __shared__ __half gs[];
    __half* As = gs;
    __half* Bs = gs + 128 * AS2;

    const int tid = threadIdx.x;
    const int m0 = blockIdx.x << 7;
    const int n0 = blockIdx.y * 192;
    const int wp = tid >> 5, lane = tid & 31;
    const int gid = lane >> 2, tig = lane & 3;
    const int wm = (wp >> 1) << 5;
    const int wn = (wp & 1) << 5;

    // ---- stage A (128 x 192) once, fp32 -> fp16 ----
    {
        const int row = tid >> 1, colb = (tid & 1) * 96;
        const float* ap = A + (long)(m0 + row) * DIM + colb;
        __half* dst = &As[row * AS2 + colb];
#pragma unroll
        for (int c = 0; c < 96; c += 16) {
            float4 f0 = *(const float4*)(ap + c);
            float4 f1 = *(const float4*)(ap + c + 4);
            float4 f2 = *(const float4*)(ap + c + 8);
            float4 f3 = *(const float4*)(ap + c + 12);
            uint4 p0, p1;
            p0.x = pack_half2(f0.x, f0.y); p0.y = pack_half2(f0.z, f0.w);
            p0.z = pack_half2(f1.x, f1.y); p0.w = pack_half2(f1.z, f1.w);
            p1.x = pack_half2(f2.x, f2.y); p1.y = pack_half2(f2.z, f2.w);
            p1.z = pack_half2(f3.x, f3.y); p1.w = pack_half2(f3.z, f3.w);
            *(uint4*)(dst + c) = p0;
            *(uint4*)(dst + c + 8) = p1;
        }
    }
    // ---- stage B sub 0 (fp16 memcpy) ----
    {
        const int row = tid >> 2, colb = (tid & 3) * 48;
        const __half* bp = Bw + (long)(n0 + row) * DIM + colb;
        __half* dst = &Bs[row * AS2 + colb];
#pragma unroll
        for (int c = 0; c < 48; c += 8)
            *(uint4*)(dst + c) = *(const uint4*)(bp + c);
    }
    __syncthreads();

    const int lrow = (lane & 7) + ((lane >> 3) & 1) * 8;
    const int lcol = (lane >> 4) << 3;
    unsigned aaddr[2], baddr[2];
#pragma unroll
    for (int mt = 0; mt < 2; mt++)
        aaddr[mt] = smem_u32(&As[(wm + (mt << 4) + lrow) * AS2 + lcol]);
#pragma unroll
    for (int ntp = 0; ntp < 2; ntp++)
        baddr[ntp] = smem_u32(&Bs[(wn + (ntp << 4) + lrow) * AS2 + lcol]);

#pragma unroll
    for (int sub = 0; sub < 3; sub++) {
        float acc[2][4][4] = {};
#pragma unroll
        for (int t = 0; t < 12; t++) {
            unsigned afr[2][4];
#pragma unroll
            for (int mt = 0; mt < 2; mt++)
                LDMATRIX_X4(afr[mt][0], afr[mt][1], afr[mt][2], afr[mt][3],
                            aaddr[mt] + t * 32);
#pragma unroll
            for (int ntp = 0; ntp < 2; ntp++) {
                unsigned b0a, b0b, b1a, b1b;
                LDMATRIX_X4(b0a, b0b, b1a, b1b, baddr[ntp] + t * 32);
#pragma unroll
                for (int mt = 0; mt < 2; mt++) {
                    MMA_F16(acc[mt][2*ntp][0], acc[mt][2*ntp][1], acc[mt][2*ntp][2], acc[mt][2*ntp][3],
                            afr[mt][0], afr[mt][1], afr[mt][2], afr[mt][3], b0a, b1a);
                    MMA_F16(acc[mt][2*ntp+1][0], acc[mt][2*ntp+1][1], acc[mt][2*ntp+1][2], acc[mt][2*ntp+1][3],
                            afr[mt][0], afr[mt][1], afr[mt][2], afr[mt][3], b0b, b1b);
                }
            }
        }
#pragma unroll
        for (int mt = 0; mt < 2; mt++) {
            const int r0 = m0 + wm + (mt << 4) + gid;
#pragma unroll
            for (int nt = 0; nt < 4; nt++) {
                const int ccol = n0 + sub * 64 + wn + (nt << 3) + (tig << 1);
                const float b0 = bias[ccol], b1 = bias[ccol + 1];
                if (HALF_OUT) {
                    __half* C = (__half*)Cv;
                    *(unsigned*)&C[(long)r0 * N + ccol] =
                        pack_half2(acc[mt][nt][0] + b0, acc[mt][nt][1] + b1);
                    *(unsigned*)&C[(long)(r0 + 8) * N + ccol] =
                        pack_half2(acc[mt][nt][2] + b0, acc[mt][nt][3] + b1);
                } else {
                    float* C = (float*)Cv;
                    *(float2*)(C + (long)r0 * N + ccol) =
                        make_float2(acc[mt][nt][0] + b0, acc[mt][nt][1] + b1);
                    *(float2*)(C + (long)(r0 + 8) * N + ccol) =
                        make_float2(acc[mt][nt][2] + b0, acc[mt][nt][3] + b1);
                }
            }
        }
        if (sub < 2) {
            __syncthreads();
            const int row = tid >> 2, colb = (tid & 3) * 48;
            const __half* bp = Bw + (long)(n0 + (sub + 1) * 64 + row) * DIM + colb;
            __half* dst = &Bs[row * AS2 + colb];
#pragma unroll
            for (int c = 0; c < 48; c += 8)
                *(uint4*)(dst + c) = *(const uint4*)(bp + c);
            __syncthreads();
        }
    }
}

// ============================================================
// fp16 MMA attention (R15 structure, degree-3 exp)
// ============================================================
__global__ __launch_bounds__(256, 2)
void attn_kernel() {
    extern __shared__ __half sh[];
    __half* sq    = sh + SQ_OFF;
    __half* sk    = sh + SK_OFF;
    __half* sv    = sh + SV_OFF;
    __half* sbias = sh + SBIAS_OFF;
    float*  sred  = (float*)(sh + SRED_OFF);
    float*  sOp   = (float*)(sh + SK_OFF);

    const int tid = threadIdx.x;
    const int wp = tid >> 5, lane = tid & 31;
    const int gid = lane >> 2, tig = lane & 3;
    const int kq = lane >> 2, q4 = lane & 3;
    const int w = blockIdx.x;
    const int h = blockIdx.y;
    const int b  = w >> 8;
    const int wl = w & 255;
    const int bFine = b * FINE_STRIDE;
    const int bPool = b * POOL_STRIDE;
    const int hcol = h * HD;

    {
        const int r = (wp << 3) + kq;
        int off = g_qtab[(wl << 6) + r];
        uint4 qv = make_uint4(0, 0, 0, 0);
        if (off != INT_MIN)
            qv = *(const uint4*)(g_qkv + bFine + off + hcol + 8 * q4);
        const __half2 sc = __float2half2_rn(ATT_SCALE);
        __half2* qh = (__half2*)&qv;
        qh[0] = __hmul2(qh[0], sc); qh[1] = __hmul2(qh[1], sc);
        qh[2] = __hmul2(qh[2], sc); qh[3] = __hmul2(qh[3], sc);
        *(uint4*)&sq[r * SKH + 8 * q4] = qv;
    }
#pragma unroll
    for (int it = 0; it < 4; it++) {
        const int j = (it << 6) + (wp << 3) + kq;
        int off = g_gtab[(wl << 8) + j];
        uint4 kk = make_uint4(0, 0, 0, 0), vv = make_uint4(0, 0, 0, 0);
        if (off != INT_MIN) {
            const __half* base = (off >= 0) ? (g_qkv + bFine + off)
                                            : (g_qkvp + bPool + ~off);
            kk = *(const uint4*)(base + DIM + hcol + 8 * q4);
            vv = *(const uint4*)(base + 2 * DIM + hcol + 8 * q4);
        }
        *(uint4*)&sk[j * SKH + 8 * q4] = kk;
        *(uint4*)&sv[j * SKH + 8 * q4] = vv;
    }
    {
        const __half* src = &g_bias_h[(h << 6) * NKP];
#pragma unroll
        for (int i = tid; i < 64 * 32; i += 256) {
            int row = i >> 5, ch = (i & 31) << 3;
            *(uint4*)&sbias[row * SBS + ch] = *(const uint4*)&src[(row << 8) + ch];
        }
    }
    __syncthreads();

    const int q0 = (wp & 3) << 4;
    const int kh = wp >> 2;
    const int kb = kh << 7;
    unsigned qa[2][4];
#pragma unroll
    for (int ks = 0; ks < 2; ks++) {
        const int ra = (q0 + gid) * SKH + (ks << 4);
        const int rb = ra + (SKH << 3);
        qa[ks][0] = *(const unsigned*)&sq[ra + 2 * tig];
        qa[ks][1] = *(const unsigned*)&sq[rb + 2 * tig];
        qa[ks][2] = *(const unsigned*)&sq[ra + 2 * tig + 8];
        qa[ks][3] = *(const unsigned*)&sq[rb + 2 * tig + 8];
    }

    float S[16][4];
    const unsigned long long pm = g_pmask[wl];
    const __half* bq0 = &sbias[(q0 + gid) * SBS + kb + 2 * tig];
    const __half* bq1 = bq0 + (SBS << 3);
    const unsigned kaddr0 = smem_u32(&sk[(kb + (lane & 7)) * SKH + ((lane >> 3) << 3)]);

#pragma unroll
    for (int t = 0; t < 16; t++) {
        const int j0 = kb + (t << 3);
        float2 bL0 = __half22float2(*(const __half2*)(bq0 + (t << 3)));
        float2 bL1 = __half22float2(*(const __half2*)(bq1 + (t << 3)));
        float c0 = bL0.x, c1 = bL0.y, c2 = bL1.x, c3 = bL1.y;
        unsigned b00, b01, b10, b11;
        LDMATRIX_X4(b00, b01, b10, b11, kaddr0 + t * (8 * SKH * 2));
        MMA_F16(c0, c1, c2, c3, qa[0][0], qa[0][1], qa[0][2], qa[0][3], b00, b01);
        MMA_F16(c0, c1, c2, c3, qa[1][0], qa[1][1], qa[1][2], qa[1][3], b10, b11);
        if (kh) {
            const int jj = j0 + 2 * tig;
            if (jj >= 181 && jj < 230 && ((pm >> (jj - 181)) & 1ull)) { c0 -= 100.f; c2 -= 100.f; }
            if (jj + 1 >= 181 && jj + 1 < 230 && ((pm >> (jj - 180)) & 1ull)) { c1 -= 100.f; c3 -= 100.f; }
        }
        S[t][0] = c0; S[t][1] = c1; S[t][2] = c2; S[t][3] = c3;
    }

    float m0 = -1e30f, m1 = -1e30f;
#pragma unroll
    for (int t = 0; t < 16; t++) {
        m0 = fmaxf(m0, fmaxf(S[t][0], S[t][1]));
        m1 = fmaxf(m1, fmaxf(S[t][2], S[t][3]));
    }
    m0 = fmaxf(m0, __shfl_xor_sync(0xffffffffu, m0, 1));
    m0 = fmaxf(m0, __shfl_xor_sync(0xffffffffu, m0, 2));
    m1 = fmaxf(m1, __shfl_xor_sync(0xffffffffu, m1, 1));
    m1 = fmaxf(m1, __shfl_xor_sync(0xffffffffu, m1, 2));

    float s0 = 0.f, s1 = 0.f;
#pragma unroll
    for (int t = 0; t < 16; t++) {
        S[t][0] = fast_exp(S[t][0] - m0); s0 += S[t][0];
        S[t][1] = fast_exp(S[t][1] - m0); s0 += S[t][1];
        S[t][2] = fast_exp(S[t][2] - m1); s1 += S[t][2];
        S[t][3] = fast_exp(S[t][3] - m1); s1 += S[t][3];
    }
    s0 += __shfl_xor_sync(0xffffffffu, s0, 1);
    s0 += __shfl_xor_sync(0xffffffffu, s0, 2);
    s1 += __shfl_xor_sync(0xffffffffu, s1, 1);
    s1 += __shfl_xor_sync(0xffffffffu, s1, 2);

    if (tig == 0) {
        sred[(kh << 6) + q0 + gid]           = m0;
        sred[(kh << 6) + q0 + gid + 8]       = m1;
        sred[128 + (kh << 6) + q0 + gid]     = s0;
        sred[128 + (kh << 6) + q0 + gid + 8] = s1;
    }
    __syncthreads();
    {
        float mo0 = sred[((kh ^ 1) << 6) + q0 + gid];
        float mo1 = sred[((kh ^ 1) << 6) + q0 + gid + 8];
        float so0 = sred[128 + ((kh ^ 1) << 6) + q0 + gid];
        float so1 = sred[128 + ((kh ^ 1) << 6) + q0 + gid + 8];
        float M0 = fmaxf(m0, mo0), M1 = fmaxf(m1, mo1);
        float sc0 = fast_exp(m0 - M0), sc1 = fast_exp(m1 - M1);
        float den0 = s0 * sc0 + so0 * fast_exp(mo0 - M0);
        float den1 = s1 * sc1 + so1 * fast_exp(mo1 - M1);
        m0 = sc0 / den0;
        m1 = sc1 / den1;
    }

    const int vrow = ((lane >> 3) & 1) * 8 + (lane & 7);
    const int vcol = (lane >> 4) << 3;
    unsigned vaddr[2];
#pragma unroll
    for (int dh = 0; dh < 2; dh++)
        vaddr[dh] = smem_u32(&sv[(kb + vrow) * SKH + (dh << 4) + vcol]);

    float O[4][4] = {};
#pragma unroll
    for (int kc = 0; kc < 8; kc++) {
        const int t0 = kc << 1;
        unsigned a0 = pack_half2(S[t0][0], S[t0][1]);
        unsigned a1 = pack_half2(S[t0][2], S[t0][3]);
        unsigned a2 = pack_half2(S[t0 + 1][0], S[t0 + 1][1]);
        unsigned a3 = pack_half2(S[t0 + 1][2], S[t0 + 1][3]);
#pragma unroll
        for (int dh = 0; dh < 2; dh++) {
            unsigned b0a, b1a, b0b, b1b;
            LDMATRIX_X4_TRANS(b0a, b1a, b0b, b1b,
                              vaddr[dh] + kc * (16 * SKH * 2));
            MMA_F16(O[2*dh][0], O[2*dh][1], O[2*dh][2], O[2*dh][3],
                    a0, a1, a2, a3, b0a, b1a);
            MMA_F16(O[2*dh+1][0], O[2*dh+1][1], O[2*dh+1][2], O[2*dh+1][3],
                    a0, a1, a2, a3, b0b, b1b);
        }
    }
#pragma unroll
    for (int nt = 0; nt < 4; nt++) {
        O[nt][0] *= m0; O[nt][1] *= m0;
        O[nt][2] *= m1; O[nt][3] *= m1;
    }

    if (kh == 1) {
#pragma unroll
        for (int nt = 0; nt < 4; nt++) {
            const int col = (nt << 3) + (tig << 1);
            *(float2*)&sOp[(q0 + gid) * SOP_STRIDE + col]     = make_float2(O[nt][0], O[nt][1]);
            *(float2*)&sOp[(q0 + gid + 8) * SOP_STRIDE + col] = make_float2(O[nt][2], O[nt][3]);
        }
    }
    __syncthreads();
    if (kh == 0) {
        const int r0 = q0 + gid, r1 = r0 + 8;
#pragma unroll
        for (int nt = 0; nt < 4; nt++) {
            const int col = (nt << 3) + (tig << 1);
            float2 p0 = *(const float2*)&sOp[r0 * SOP_STRIDE + col];
            float2 p1 = *(const float2*)&sOp[r1 * SOP_STRIDE + col];
            const int dcol = hcol + col;
            if (r0 < WA)
                *(float2*)&g_attnout[(long)(w * WA + r0) * DIM + dcol] =
                    make_float2(O[nt][0] + p0.x, O[nt][1] + p0.y);
            if (r1 < WA)
                *(float2*)&g_attnout[(long)(w * WA + r1) * DIM + dcol] =
                    make_float2(O[nt][2] + p1.x, O[nt][3] + p1.y);
        }
    }
}

// ============================================================
// launch
// ============================================================
extern "C" void kernel_launch(void* const* d_in, const int* in_sizes, int n_in,
                              void* d_out, int out_size) {
    const float* x         = (const float*)d_in[0];
    const float* x_pooled  = (const float*)d_in[1];
    const float* qkv_w     = (const float*)d_in[2];
    const float* qkv_b     = (const float*)d_in[3];
    const float* proj_w    = (const float*)d_in[4];
    const float* proj_b    = (const float*)d_in[5];
    const float* rpb_table = (const float*)d_in[6];
    const float* rpb_nb    = (const float*)d_in[7];
    const float* rpb_win   = (const float*)d_in[8];
    float* out = (float*)d_out;

    void *p_qkv = nullptr, *p_qkvp = nullptr;
    float *p_ao = nullptr;
    __half *p_wqkv = nullptr, *p_wproj = nullptr;
    cudaGetSymbolAddress(&p_qkv,  g_qkv);
    cudaGetSymbolAddress(&p_qkvp, g_qkvp);
    cudaGetSymbolAddress((void**)&p_ao, g_attnout);
    cudaGetSymbolAddress((void**)&p_wqkv, g_wqkv_h);
    cudaGetSymbolAddress((void**)&p_wproj, g_wproj_h);

    const int attn_smem = SMEM_HALVES * 2;  // 80896 B
    cudaFuncSetAttribute(attn_kernel, cudaFuncAttributeMaxDynamicSharedMemorySize, attn_smem);
    cudaFuncSetAttribute(gemm_fp16_kernel<true>,
                         cudaFuncAttributeMaxDynamicSharedMemorySize, GEMM_SMEM);
    cudaFuncSetAttribute(gemm_fp16_kernel<false>,
                         cudaFuncAttributeMaxDynamicSharedMemorySize, GEMM_SMEM);

    init_kernel<<<256, 256>>>(rpb_table, rpb_nb, rpb_win, qkv_w, proj_w);

    gemm_fp16_kernel<true><<<dim3(100352 / 128, 3), 256, GEMM_SMEM>>>(
        x, p_wqkv, qkv_b, p_qkv, BATCH * HH * WWID, QKVC);

    gemm_fp16_kernel<true><<<dim3(2048 / 128, 3), 256, GEMM_SMEM>>>(
        x_pooled, p_wqkv, qkv_b, p_qkvp, BATCH * NWH * NWW, QKVC);

    attn_kernel<<<dim3(BNW, HEADS), 256, attn_smem>>>();

    gemm_fp16_kernel<false><<<dim3(100352 / 128, 1), 256, GEMM_SMEM>>>(
        p_ao, p_wproj, proj_b, out, BNW * WA, DIM);
}

// round 17
// speedup vs baseline: 6.8972x; 1.0749x over previous
#include <cuda_runtime.h>
#include <cuda_fp16.h>
#include <limits.h>

// ---- problem constants ----
#define BATCH 8
#define HH    112
#define WWID  112
#define DIM   192
#define HEADS 6
#define HD    32
#define WS    7
#define WA    49
#define EXPAND 3
#define NWH   16
#define NWW   16
#define BNW   2048
#define NROLL 132
#define NK    230
#define NKP   256
#define QKVC  (3*DIM)
#define ATT_SCALE 0.17677669529663689f
#define FINE_STRIDE (HH*WWID*QKVC)
#define POOL_STRIDE (NWH*NWW*QKVC)
#define NFINE (BATCH*HH*WWID)
#define NPOOL (BATCH*NWH*NWW)

// attention smem layout (in halves)
#define SKH 40
#define SBS 264
#define SQ_OFF    0
#define SK_OFF    2560
#define SV_OFF    12800
#define SBIAS_OFF 23040
#define SRED_OFF  39936
#define SMEM_HALVES 40448            // 80896 B
#define SOP_STRIDE 34

// GEMM: K=192 resident, row stride 200 halves
#define AS2 200
#define GEMM_SMEM ((128 + 64) * AS2 * 2)   // 76800 B

// ---- scratch ----
__device__ __half g_x_h [NFINE*DIM];
__device__ __half g_xp_h[NPOOL*DIM];
__device__ __half g_qkv [NFINE*QKVC];
__device__ __half g_qkvp[NPOOL*QKVC];
__device__ __half g_attnout[BNW*WA*DIM];
__device__ __half g_bias_h[HEADS*64*NKP];
__device__ __half g_wqkv_h[QKVC*DIM];
__device__ __half g_wproj_h[DIM*DIM];
__device__ unsigned long long g_pmask[256];
__device__ int    g_gtab[256*NKP];
__device__ int    g_qtab[256*64];

__device__ __forceinline__ unsigned pack_half2(float lo, float hi) {
    __half2_raw hr = (__half2_raw)__floats2half2_rn(lo, hi);
    return ((unsigned)hr.y << 16) | (unsigned)hr.x;
}

__device__ __forceinline__ unsigned smem_u32(const void* p) {
    return (unsigned)__cvta_generic_to_shared(p);
}

#define CP_ASYNC16(dst, src) \
    asm volatile("cp.async.ca.shared.global [%0], [%1], 16;" :: "r"(dst), "l"(src))
#define CP_COMMIT() asm volatile("cp.async.commit_group;")
#define CP_WAIT0()  asm volatile("cp.async.wait_group 0;")

// fast exp, degree-3 minimax for 2^f. valid for x <= 0.
__device__ __forceinline__ float fast_exp(float v) {
    v = fmaxf(v, -80.f);
    float t  = v * 1.4426950408889634f;
    float tb = t + 12582912.0f;
    int   i  = __float_as_int(tb) - 0x4B400000;
    float f  = t - (tb - 12582912.0f);
    float p  = 0.0558263f;
    p = fmaf(p, f, 0.2401397f);
    p = fmaf(p, f, 0.6931471f);
    p = fmaf(p, f, 1.0f);
    return __int_as_float(__float_as_int(p) + (i << 23));
}

#define MMA_F16(c0,c1,c2,c3,a0,a1,a2,a3,b0,b1)                               \
    asm volatile("mma.sync.aligned.m16n8k16.row.col.f32.f16.f16.f32 "        \
        "{%0,%1,%2,%3},{%4,%5,%6,%7},{%8,%9},{%0,%1,%2,%3};"                 \
        : "+f"(c0), "+f"(c1), "+f"(c2), "+f"(c3)                             \
        : "r"(a0), "r"(a1), "r"(a2), "r"(a3), "r"(b0), "r"(b1))

#define LDMATRIX_X4(r0,r1,r2,r3,addr)                                        \
    asm volatile("ldmatrix.sync.aligned.m8n8.x4.shared.b16 {%0,%1,%2,%3}, [%4];" \
        : "=r"(r0), "=r"(r1), "=r"(r2), "=r"(r3) : "r"(addr))

#define LDMATRIX_X4_TRANS(r0,r1,r2,r3,addr)                                  \
    asm volatile("ldmatrix.sync.aligned.m8n8.x4.trans.shared.b16 {%0,%1,%2,%3}, [%4];" \
        : "=r"(r0), "=r"(r1), "=r"(r2), "=r"(r3) : "r"(addr))

// ============================================================
// init: bias + weights/x -> fp16 + per-window tables
// ============================================================
__global__ void init_kernel(const float* __restrict__ rpb_table,
                            const float* __restrict__ rpb_nb,
                            const float* __restrict__ rpb_win,
                            const float* __restrict__ qkv_w,
                            const float* __restrict__ proj_w,
                            const float* __restrict__ x,
                            const float* __restrict__ x_pooled) {
    const int gtid = blockIdx.x * blockDim.x + threadIdx.x;
    const int gsz = gridDim.x * blockDim.x;
    for (int i = gtid; i < HEADS * 64 * NKP; i += gsz) {
        int j   = i % NKP;
        int row = (i / NKP) & 63;
        int h   = i / (NKP * 64);
        float v;
        if (j >= NK)        v = -60000.f;
        else if (row >= WA) v = 0.f;
        else {
            int rq = row / 7, cq = row - rq * 7;
            if (j < WA) {
                int rk = j / 7, ck = j - rk * 7;
                v = rpb_table[((rq - rk + 6) * 13 + (cq - ck + 6)) * HEADS + h];
            } else if (j < WA + NROLL) {
                v = rpb_nb[(h * WA + row) * NROLL + (j - WA)];
            } else {
                int jp = j - WA - NROLL;
                int rk = jp / 7, ck = jp - rk * 7;
                v = rpb_win[h * 169 + (rq - rk + 6) * 13 + (cq - ck + 6)];
            }
        }
        g_bias_h[i] = __float2half(v);
    }
    for (int i = gtid; i < QKVC * DIM; i += gsz) g_wqkv_h[i] = __float2half(qkv_w[i]);
    for (int i = gtid; i < DIM * DIM; i += gsz)  g_wproj_h[i] = __float2half(proj_w[i]);
    for (int i = gtid; i < NPOOL * DIM; i += gsz) g_xp_h[i] = __float2half(x_pooled[i]);
    // x: vectorized convert (float4 -> 4 halves)
    for (int i = gtid; i < (NFINE * DIM) / 4; i += gsz) {
        float4 f = *(const float4*)(x + 4 * i);
        uint2 p; p.x = pack_half2(f.x, f.y); p.y = pack_half2(f.z, f.w);
        *(uint2*)&g_x_h[4 * i] = p;
    }

    const int wl = blockIdx.x;
    const int t = threadIdx.x;
    if (wl < 256) {
        const int wi = wl >> 4, wj = wl & 15;
        const int y0 = wi * WS, x0 = wj * WS;
        if (t < WA) {
            int r = t / 7, c = t - r * 7;
            g_gtab[wl * NKP + t] = ((y0 + r) * WWID + (x0 + c)) * QKVC;
        }
        if (t >= 64 && t - 64 < WA) {
            int jp = t - 64;
            int r = jp / 7, c = jp - r * 7;
            int py = wi + r - EXPAND, px = wj + c - EXPAND;
            g_gtab[wl * NKP + 181 + jp] =
                (py >= 0 && py < NWH && px >= 0 && px < NWW)
                ? ~((py * NWW + px) * QKVC) : INT_MIN;
        }
        if (t >= 128 && t < 128 + (NKP - NK))
            g_gtab[wl * NKP + NK + (t - 128)] = INT_MIN;
        if (t >= 192 && t < 256) {
            int r = t - 192;
            if (r < WA) {
                int rr = r / 7, cc = r - rr * 7;
                g_qtab[wl * 64 + r] = ((y0 + rr) * WWID + (x0 + cc)) * QKVC;
            } else {
                g_qtab[wl * 64 + r] = INT_MIN;
            }
        }
        if (t == 1) {
            int n = WA;
            for (int s = 0; s < 4; s++)
                for (int r = 0; r < 7; r++)
                    for (int c = 0; c < 7; c++) {
                        bool inval;
                        if      (s == 0) inval = (r < 4 && c < 4);
                        else if (s == 1) inval = (r < 4 && c >= 3);
                        else if (s == 2) inval = (r >= 3 && c < 4);
                        else             inval = (r >= 3 && c >= 3);
                        if (inval) continue;
                        int dy = (s < 2) ? EXPAND : -EXPAND;
                        int dx = ((s & 1) == 0) ? EXPAND : -EXPAND;
                        int y = (y0 + r + dy + HH) % HH;
                        int x2 = (x0 + c + dx + WWID) % WWID;
                        g_gtab[wl * NKP + n++] = (y * WWID + x2) * QKVC;
                    }
            unsigned long long m = 0ull;
            for (int s = 0; s < WA; s++) {
                int rk = s / 7, ck = s - rk * 7;
                int py = wi + rk - EXPAND, px = wj + ck - EXPAND;
                if (py < 0 || py >= NWH || px < 0 || px >= NWW) m |= (1ull << s);
            }
            g_pmask[wl] = m;
        }
    }
}

// ============================================================
// K-resident fp16 GEMM, cp.async staging, all-fp16 operands.
// ============================================================
template <bool HALF_OUT>
__global__ __launch_bounds__(256, 2)
void gemm_fp16_kernel(const __half* __restrict__ A, const __half* __restrict__ Bw,
                      const float* __restrict__ bias, void* __restrict__ Cv,
                      int M, int N) {
    extern __shared__ __half gs[];
    __half* As = gs;
    __half* Bs = gs + 128 * AS2;

    const int tid = threadIdx.x;
    const int m0 = blockIdx.x << 7;
    const int n0 = blockIdx.y * 192;
    const int wp = tid >> 5, lane = tid & 31;
    const int gid = lane >> 2, tig = lane & 3;
    const int wm = (wp >> 1) << 5;
    const int wn = (wp & 1) << 5;

    // ---- stage A (128 x 192 fp16) + B sub0 via cp.async ----
    {
        const int row = tid >> 1, colb = (tid & 1) * 96;
        const __half* ap = A + (long)(m0 + row) * DIM + colb;
        unsigned dst = smem_u32(&As[row * AS2 + colb]);
#pragma unroll
        for (int c = 0; c < 96; c += 8)
            CP_ASYNC16(dst + c * 2, ap + c);
    }
    {
        const int row = tid >> 2, colb = (tid & 3) * 48;
        const __half* bp = Bw + (long)(n0 + row) * DIM + colb;
        unsigned dst = smem_u32(&Bs[row * AS2 + colb]);
#pragma unroll
        for (int c = 0; c < 48; c += 8)
            CP_ASYNC16(dst + c * 2, bp + c);
    }
    CP_COMMIT();
    CP_WAIT0();
    __syncthreads();

    const int lrow = (lane & 7) + ((lane >> 3) & 1) * 8;
    const int lcol = (lane >> 4) << 3;
    unsigned aaddr[2], baddr[2];
#pragma unroll
    for (int mt = 0; mt < 2; mt++)
        aaddr[mt] = smem_u32(&As[(wm + (mt << 4) + lrow) * AS2 + lcol]);
#pragma unroll
    for (int ntp = 0; ntp < 2; ntp++)
        baddr[ntp] = smem_u32(&Bs[(wn + (ntp << 4) + lrow) * AS2 + lcol]);

#pragma unroll
    for (int sub = 0; sub < 3; sub++) {
        float acc[2][4][4] = {};
#pragma unroll
        for (int t = 0; t < 12; t++) {
            unsigned afr[2][4];
#pragma unroll
            for (int mt = 0; mt < 2; mt++)
                LDMATRIX_X4(afr[mt][0], afr[mt][1], afr[mt][2], afr[mt][3],
                            aaddr[mt] + t * 32);
#pragma unroll
            for (int ntp = 0; ntp < 2; ntp++) {
                unsigned b0a, b0b, b1a, b1b;
                LDMATRIX_X4(b0a, b0b, b1a, b1b, baddr[ntp] + t * 32);
#pragma unroll
                for (int mt = 0; mt < 2; mt++) {
                    MMA_F16(acc[mt][2*ntp][0], acc[mt][2*ntp][1], acc[mt][2*ntp][2], acc[mt][2*ntp][3],
                            afr[mt][0], afr[mt][1], afr[mt][2], afr[mt][3], b0a, b1a);
                    MMA_F16(acc[mt][2*ntp+1][0], acc[mt][2*ntp+1][1], acc[mt][2*ntp+1][2], acc[mt][2*ntp+1][3],
                            afr[mt][0], afr[mt][1], afr[mt][2], afr[mt][3], b0b, b1b);
                }
            }
        }
#pragma unroll
        for (int mt = 0; mt < 2; mt++) {
            const int r0 = m0 + wm + (mt << 4) + gid;
#pragma unroll
            for (int nt = 0; nt < 4; nt++) {
                const int ccol = n0 + sub * 64 + wn + (nt << 3) + (tig << 1);
                const float b0 = bias[ccol], b1 = bias[ccol + 1];
                if (HALF_OUT) {
                    __half* C = (__half*)Cv;
                    *(unsigned*)&C[(long)r0 * N + ccol] =
                        pack_half2(acc[mt][nt][0] + b0, acc[mt][nt][1] + b1);
                    *(unsigned*)&C[(long)(r0 + 8) * N + ccol] =
                        pack_half2(acc[mt][nt][2] + b0, acc[mt][nt][3] + b1);
                } else {
                    float* C = (float*)Cv;
                    *(float2*)(C + (long)r0 * N + ccol) =
                        make_float2(acc[mt][nt][0] + b0, acc[mt][nt][1] + b1);
                    *(float2*)(C + (long)(r0 + 8) * N + ccol) =
                        make_float2(acc[mt][nt][2] + b0, acc[mt][nt][3] + b1);
                }
            }
        }
        if (sub < 2) {
            __syncthreads();
            const int row = tid >> 2, colb = (tid & 3) * 48;
            const __half* bp = Bw + (long)(n0 + (sub + 1) * 64 + row) * DIM + colb;
            unsigned dst = smem_u32(&Bs[row * AS2 + colb]);
#pragma unroll
            for (int c = 0; c < 48; c += 8)
                CP_ASYNC16(dst + c * 2, bp + c);
            CP_COMMIT();
            CP_WAIT0();
            __syncthreads();
        }
    }
}

// ============================================================
// fp16 MMA attention (R16 structure; fp16 attnout store)
// ============================================================
__global__ __launch_bounds__(256, 2)
void attn_kernel() {
    extern __shared__ __half sh[];
    __half* sq    = sh + SQ_OFF;
    __half* sk    = sh + SK_OFF;
    __half* sv    = sh + SV_OFF;
    __half* sbias = sh + SBIAS_OFF;
    float*  sred  = (float*)(sh + SRED_OFF);
    float*  sOp   = (float*)(sh + SK_OFF);

    const int tid = threadIdx.x;
    const int wp = tid >> 5, lane = tid & 31;
    const int gid = lane >> 2, tig = lane & 3;
    const int kq = lane >> 2, q4 = lane & 3;
    const int w = blockIdx.x;
    const int h = blockIdx.y;
    const int b  = w >> 8;
    const int wl = w & 255;
    const int bFine = b * FINE_STRIDE;
    const int bPool = b * POOL_STRIDE;
    const int hcol = h * HD;

    {
        const int r = (wp << 3) + kq;
        int off = g_qtab[(wl << 6) + r];
        uint4 qv = make_uint4(0, 0, 0, 0);
        if (off != INT_MIN)
            qv = *(const uint4*)(g_qkv + bFine + off + hcol + 8 * q4);
        const __half2 sc = __float2half2_rn(ATT_SCALE);
        __half2* qh = (__half2*)&qv;
        qh[0] = __hmul2(qh[0], sc); qh[1] = __hmul2(qh[1], sc);
        qh[2] = __hmul2(qh[2], sc); qh[3] = __hmul2(qh[3], sc);
        *(uint4*)&sq[r * SKH + 8 * q4] = qv;
    }
#pragma unroll
    for (int it = 0; it < 4; it++) {
        const int j = (it << 6) + (wp << 3) + kq;
        int off = g_gtab[(wl << 8) + j];
        uint4 kk = make_uint4(0, 0, 0, 0), vv = make_uint4(0, 0, 0, 0);
        if (off != INT_MIN) {
            const __half* base = (off >= 0) ? (g_qkv + bFine + off)
                                            : (g_qkvp + bPool + ~off);
            kk = *(const uint4*)(base + DIM + hcol + 8 * q4);
            vv = *(const uint4*)(base + 2 * DIM + hcol + 8 * q4);
        }
        *(uint4*)&sk[j * SKH + 8 * q4] = kk;
        *(uint4*)&sv[j * SKH + 8 * q4] = vv;
    }
    {
        const __half* src = &g_bias_h[(h << 6) * NKP];
#pragma unroll
        for (int i = tid; i < 64 * 32; i += 256) {
            int row = i >> 5, ch = (i & 31) << 3;
            *(uint4*)&sbias[row * SBS + ch] = *(const uint4*)&src[(row << 8) + ch];
        }
    }
    __syncthreads();

    const int q0 = (wp & 3) << 4;
    const int kh = wp >> 2;
    const int kb = kh << 7;
    unsigned qa[2][4];
#pragma unroll
    for (int ks = 0; ks < 2; ks++) {
        const int ra = (q0 + gid) * SKH + (ks << 4);
        const int rb = ra + (SKH << 3);
        qa[ks][0] = *(const unsigned*)&sq[ra + 2 * tig];
        qa[ks][1] = *(const unsigned*)&sq[rb + 2 * tig];
        qa[ks][2] = *(const unsigned*)&sq[ra + 2 * tig + 8];
        qa[ks][3] = *(const unsigned*)&sq[rb + 2 * tig + 8];
    }

    float S[16][4];
    const unsigned long long pm = g_pmask[wl];
    const __half* bq0 = &sbias[(q0 + gid) * SBS + kb + 2 * tig];
    const __half* bq1 = bq0 + (SBS << 3);
    const unsigned kaddr0 = smem_u32(&sk[(kb + (lane & 7)) * SKH + ((lane >> 3) << 3)]);

#pragma unroll
    for (int t = 0; t < 16; t++) {
        const int j0 = kb + (t << 3);
        float2 bL0 = __half22float2(*(const __half2*)(bq0 + (t << 3)));
        float2 bL1 = __half22float2(*(const __half2*)(bq1 + (t << 3)));
        float c0 = bL0.x, c1 = bL0.y, c2 = bL1.x, c3 = bL1.y;
        unsigned b00, b01, b10, b11;
        LDMATRIX_X4(b00, b01, b10, b11, kaddr0 + t * (8 * SKH * 2));
        MMA_F16(c0, c1, c2, c3, qa[0][0], qa[0][1], qa[0][2], qa[0][3], b00, b01);
        MMA_F16(c0, c1, c2, c3, qa[1][0], qa[1][1], qa[1][2], qa[1][3], b10, b11);
        if (kh) {
            const int jj = j0 + 2 * tig;
            if (jj >= 181 && jj < 230 && ((pm >> (jj - 181)) & 1ull)) { c0 -= 100.f; c2 -= 100.f; }
            if (jj + 1 >= 181 && jj + 1 < 230 && ((pm >> (jj - 180)) & 1ull)) { c1 -= 100.f; c3 -= 100.f; }
        }
        S[t][0] = c0; S[t][1] = c1; S[t][2] = c2; S[t][3] = c3;
    }

    float m0 = -1e30f, m1 = -1e30f;
#pragma unroll
    for (int t = 0; t < 16; t++) {
        m0 = fmaxf(m0, fmaxf(S[t][0], S[t][1]));
        m1 = fmaxf(m1, fmaxf(S[t][2], S[t][3]));
    }
    m0 = fmaxf(m0, __shfl_xor_sync(0xffffffffu, m0, 1));
    m0 = fmaxf(m0, __shfl_xor_sync(0xffffffffu, m0, 2));
    m1 = fmaxf(m1, __shfl_xor_sync(0xffffffffu, m1, 1));
    m1 = fmaxf(m1, __shfl_xor_sync(0xffffffffu, m1, 2));

    float s0 = 0.f, s1 = 0.f;
#pragma unroll
    for (int t = 0; t < 16; t++) {
        S[t][0] = fast_exp(S[t][0] - m0); s0 += S[t][0];
        S[t][1] = fast_exp(S[t][1] - m0); s0 += S[t][1];
        S[t][2] = fast_exp(S[t][2] - m1); s1 += S[t][2];
        S[t][3] = fast_exp(S[t][3] - m1); s1 += S[t][3];
    }
    s0 += __shfl_xor_sync(0xffffffffu, s0, 1);
    s0 += __shfl_xor_sync(0xffffffffu, s0, 2);
    s1 += __shfl_xor_sync(0xffffffffu, s1, 1);
    s1 += __shfl_xor_sync(0xffffffffu, s1, 2);

    if (tig == 0) {
        sred[(kh << 6) + q0 + gid]           = m0;
        sred[(kh << 6) + q0 + gid + 8]       = m1;
        sred[128 + (kh << 6) + q0 + gid]     = s0;
        sred[128 + (kh << 6) + q0 + gid + 8] = s1;
    }
    __syncthreads();
    {
        float mo0 = sred[((kh ^ 1) << 6) + q0 + gid];
        float mo1 = sred[((kh ^ 1) << 6) + q0 + gid + 8];
        float so0 = sred[128 + ((kh ^ 1) << 6) + q0 + gid];
        float so1 = sred[128 + ((kh ^ 1) << 6) + q0 + gid + 8];
        float M0 = fmaxf(m0, mo0), M1 = fmaxf(m1, mo1);
        float sc0 = fast_exp(m0 - M0), sc1 = fast_exp(m1 - M1);
        float den0 = s0 * sc0 + so0 * fast_exp(mo0 - M0);
        float den1 = s1 * sc1 + so1 * fast_exp(mo1 - M1);
        m0 = sc0 / den0;
        m1 = sc1 / den1;
    }

    const int vrow = ((lane >> 3) & 1) * 8 + (lane & 7);
    const int vcol = (lane >> 4) << 3;
    unsigned vaddr[2];
#pragma unroll
    for (int dh = 0; dh < 2; dh++)
        vaddr[dh] = smem_u32(&sv[(kb + vrow) * SKH + (dh << 4) + vcol]);

    float O[4][4] = {};
#pragma unroll
    for (int kc = 0; kc < 8; kc++) {
        const int t0 = kc << 1;
        unsigned a0 = pack_half2(S[t0][0], S[t0][1]);
        unsigned a1 = pack_half2(S[t0][2], S[t0][3]);
        unsigned a2 = pack_half2(S[t0 + 1][0], S[t0 + 1][1]);
        unsigned a3 = pack_half2(S[t0 + 1][2], S[t0 + 1][3]);
#pragma unroll
        for (int dh = 0; dh < 2; dh++) {
            unsigned b0a, b1a, b0b, b1b;
            LDMATRIX_X4_TRANS(b0a, b1a, b0b, b1b,
                              vaddr[dh] + kc * (16 * SKH * 2));
            MMA_F16(O[2*dh][0], O[2*dh][1], O[2*dh][2], O[2*dh][3],
                    a0, a1, a2, a3, b0a, b1a);
            MMA_F16(O[2*dh+1][0], O[2*dh+1][1], O[2*dh+1][2], O[2*dh+1][3],
                    a0, a1, a2, a3, b0b, b1b);
        }
    }
#pragma unroll
    for (int nt = 0; nt < 4; nt++) {
        O[nt][0] *= m0; O[nt][1] *= m0;
        O[nt][2] *= m1; O[nt][3] *= m1;
    }

    if (kh == 1) {
#pragma unroll
        for (int nt = 0; nt < 4; nt++) {
            const int col = (nt << 3) + (tig << 1);
            *(float2*)&sOp[(q0 + gid) * SOP_STRIDE + col]     = make_float2(O[nt][0], O[nt][1]);
            *(float2*)&sOp[(q0 + gid + 8) * SOP_STRIDE + col] = make_float2(O[nt][2], O[nt][3]);
        }
    }
    __syncthreads();
    if (kh == 0) {
        const int r0 = q0 + gid, r1 = r0 + 8;
#pragma unroll
        for (int nt = 0; nt < 4; nt++) {
            const int col = (nt << 3) + (tig << 1);
            float2 p0 = *(const float2*)&sOp[r0 * SOP_STRIDE + col];
            float2 p1 = *(const float2*)&sOp[r1 * SOP_STRIDE + col];
            const int dcol = hcol + col;
            if (r0 < WA)
                *(unsigned*)&g_attnout[(long)(w * WA + r0) * DIM + dcol] =
                    pack_half2(O[nt][0] + p0.x, O[nt][1] + p0.y);
            if (r1 < WA)
                *(unsigned*)&g_attnout[(long)(w * WA + r1) * DIM + dcol] =
                    pack_half2(O[nt][2] + p1.x, O[nt][3] + p1.y);
        }
    }
}

// ============================================================
// launch
// ============================================================
extern "C" void kernel_launch(void* const* d_in, const int* in_sizes, int n_in,
                              void* d_out, int out_size) {
    const float* x         = (const float*)d_in[0];
    const float* x_pooled  = (const float*)d_in[1];
    const float* qkv_w     = (const float*)d_in[2];
    const float* qkv_b     = (const float*)d_in[3];
    const float* proj_w    = (const float*)d_in[4];
    const float* proj_b    = (const float*)d_in[5];
    const float* rpb_table = (const float*)d_in[6];
    const float* rpb_nb    = (const float*)d_in[7];
    const float* rpb_win   = (const float*)d_in[8];
    float* out = (float*)d_out;

    void *p_qkv = nullptr, *p_qkvp = nullptr;
    __half *p_xh = nullptr, *p_xph = nullptr, *p_ao = nullptr;
    __half *p_wqkv = nullptr, *p_wproj = nullptr;
    cudaGetSymbolAddress(&p_qkv,  g_qkv);
    cudaGetSymbolAddress(&p_qkvp, g_qkvp);
    cudaGetSymbolAddress((void**)&p_xh, g_x_h);
    cudaGetSymbolAddress((void**)&p_xph, g_xp_h);
    cudaGetSymbolAddress((void**)&p_ao, g_attnout);
    cudaGetSymbolAddress((void**)&p_wqkv, g_wqkv_h);
    cudaGetSymbolAddress((void**)&p_wproj, g_wproj_h);

    const int attn_smem = SMEM_HALVES * 2;  // 80896 B
    cudaFuncSetAttribute(attn_kernel, cudaFuncAttributeMaxDynamicSharedMemorySize, attn_smem);
    cudaFuncSetAttribute(gemm_fp16_kernel<true>,
                         cudaFuncAttributeMaxDynamicSharedMemorySize, GEMM_SMEM);
    cudaFuncSetAttribute(gemm_fp16_kernel<false>,
                         cudaFuncAttributeMaxDynamicSharedMemorySize, GEMM_SMEM);

    init_kernel<<<512, 256>>>(rpb_table, rpb_nb, rpb_win, qkv_w, proj_w, x, x_pooled);

    gemm_fp16_kernel<true><<<dim3(NFINE / 128, 3), 256, GEMM_SMEM>>>(
        p_xh, p_wqkv, qkv_b, p_qkv, NFINE, QKVC);

    gemm_fp16_kernel<true><<<dim3(NPOOL / 128, 3), 256, GEMM_SMEM>>>(
        p_xph, p_wqkv, qkv_b, p_qkvp, NPOOL, QKVC);

    attn_kernel<<<dim3(BNW, HEADS), 256, attn_smem>>>();

    gemm_fp16_kernel<false><<<dim3((BNW * WA) / 128, 1), 256, GEMM_SMEM>>>(
        p_ao, p_wproj, proj_b, out, BNW * WA, DIM);
}